// round 7
// baseline (speedup 1.0000x reference)
#include <cuda_runtime.h>
#include <cuda_bf16.h>
#include <math.h>
#include <cstdint>

// ---------------- problem constants ----------------------------------------
constexpr int B   = 8;
constexpr int F   = 8;
constexpr int NS  = 196;
constexpr int NT  = 1 + F*NS;   // 1569
constexpr int D   = 768;
constexpr int H   = 12;
constexpr int HD  = 64;
constexpr int D3  = 3*D;        // 2304
constexpr int D4  = 4*D;        // 3072
constexpr int M   = B*NT;       // 12552
constexpr int MP  = 12672;      // M padded
constexpr float LN_EPS = 1e-5f;
constexpr float QSCALE = 0.125f;

// ---------------- scratch (device globals; no allocation) ------------------
__device__ int8_t g_lnq1 [(size_t)M * D],  g_lnq2 [(size_t)M * D];
__device__ float  g_lns  [6 * MP];
__device__ float  g_qkv  [(size_t)M * D3];
__device__ float  g_att  [(size_t)M * D];
__device__ int8_t g_attq1[(size_t)M * D],  g_attq2[(size_t)M * D];
__device__ float  g_atts [6 * MP];
__device__ float  g_tres [(size_t)M * D];
__device__ float  g_sres [(size_t)M * D];
__device__ float  g_hid  [(size_t)M * D4];
__device__ int8_t g_hidq1[(size_t)M * D4], g_hidq2[(size_t)M * D4];
__device__ float  g_hids [24 * MP];
__device__ float  g_wtmp [(size_t)3072 * 768];
// quantized transposed weights: Wt[n][k]
__device__ int8_t g_q1_tqkv [(size_t)D3*D], g_q2_tqkv [(size_t)D3*D];  __device__ float g_s_tqkv [6*D3];
__device__ int8_t g_q1_aqkv [(size_t)D3*D], g_q2_aqkv [(size_t)D3*D];  __device__ float g_s_aqkv [6*D3];
__device__ int8_t g_q1_tproj[(size_t)D*D],  g_q2_tproj[(size_t)D*D];   __device__ float g_s_tproj[6*D];
__device__ int8_t g_q1_aproj[(size_t)D*D],  g_q2_aproj[(size_t)D*D];   __device__ float g_s_aproj[6*D];
__device__ int8_t g_q1_fc1  [(size_t)D4*D], g_q2_fc1  [(size_t)D4*D];  __device__ float g_s_fc1  [6*D4];
__device__ int8_t g_q1_fc2  [(size_t)D*D4], g_q2_fc2  [(size_t)D*D4];  __device__ float g_s_fc2  [24*D];

// ---------------- helpers ----------------------------------------------------
__device__ __forceinline__ uint32_t smem_to_u32(const void* p) {
    uint32_t a;
    asm("{ .reg .u64 t; cvta.to.shared.u64 t, %1; cvt.u32.u64 %0, t; }"
        : "=r"(a) : "l"(p));
    return a;
}
__device__ __forceinline__ void cp_async16(uint32_t dst, const void* src, bool valid) {
    int sz = valid ? 16 : 0;
    asm volatile("cp.async.cg.shared.global [%0], [%1], 16, %2;"
                 :: "r"(dst), "l"(src), "r"(sz) : "memory");
}
#define CP_COMMIT()  asm volatile("cp.async.commit_group;" ::: "memory")
#define CP_WAIT(n)   asm volatile("cp.async.wait_group %0;" :: "n"(n) : "memory")

__device__ __forceinline__ void ldsm_x4(uint32_t& r0, uint32_t& r1, uint32_t& r2, uint32_t& r3, uint32_t addr) {
    asm volatile("ldmatrix.sync.aligned.m8n8.x4.shared.b16 {%0,%1,%2,%3}, [%4];"
                 : "=r"(r0), "=r"(r1), "=r"(r2), "=r"(r3) : "r"(addr));
}
__device__ __forceinline__ void mma_s8(int* c, const uint32_t* a, const uint32_t* b) {
    asm volatile(
        "mma.sync.aligned.m16n8k32.row.col.s32.s8.s8.s32 "
        "{%0,%1,%2,%3}, {%4,%5,%6,%7}, {%8,%9}, {%0,%1,%2,%3};"
        : "+r"(c[0]), "+r"(c[1]), "+r"(c[2]), "+r"(c[3])
        : "r"(a[0]), "r"(a[1]), "r"(a[2]), "r"(a[3]), "r"(b[0]), "r"(b[1]));
}
__device__ __forceinline__ float gelu_exact(float v) {
    return 0.5f * v * (1.f + erff(v * 0.70710678118654752f));
}

// ---------------- int8x2 GEMM (register-lean) --------------------------------
// C[M][N] = A[M][K] @ Wt[N][K]^T; x ~= s(x1 + x2/128)
// CTA 64x128, BK=128, 8 warps each owning 64x16 (mt=4, nt=2).
constexpr int BM = 64, BN = 128, BK = 128;
constexpr int RSB = 144;
constexpr int MAT_A  = 64  * RSB;   // 9216
constexpr int MAT_B2 = 128 * RSB;   // 18432
constexpr int OFF_A1 = 0;
constexpr int OFF_A2 = MAT_A;               // 9216
constexpr int OFF_B1 = 2*MAT_A;             // 18432
constexpr int OFF_B2 = 2*MAT_A + MAT_B2;    // 36864
constexpr int OFF_SA = 2*MAT_A + 2*MAT_B2;  // 55296 (64 floats)
constexpr int OFF_SB = OFF_SA + 256;        // 55552 (128 floats)
constexpr int STAGE_B = OFF_SB + 512;       // 56064 -> pad
constexpr int STAGE_PAD = 56320;
constexpr int SMEM_GEMM = 2 * STAGE_PAD;    // 112640

// EPI: 0 = bias, 1 = bias+residual, 2 = bias+GELU
template<int EPI>
__global__ void __launch_bounds__(256, 1)
gemm_s8(const int8_t* __restrict__ Aq1, const int8_t* __restrict__ Aq2,
        const float* __restrict__ As, int AsStride,
        const int8_t* __restrict__ Bq1, const int8_t* __restrict__ Bq2,
        const float* __restrict__ Bs,
        const float* __restrict__ bias, const float* __restrict__ R,
        float* __restrict__ C, int Mr, int K, int Nc)
{
    extern __shared__ char smem[];
    const uint32_t sb = smem_to_u32(smem);
    const int tid = threadIdx.x;
    const int wid = tid >> 5, lane = tid & 31;
    const int bm = blockIdx.y * BM, bn = blockIdx.x * BN;
    const int wn0 = wid * 16;             // warp's n offset within tile

    float acc[4][2][4];
    #pragma unroll
    for (int i = 0; i < 4; i++)
        #pragma unroll
        for (int j = 0; j < 2; j++)
            #pragma unroll
            for (int q = 0; q < 4; q++) acc[i][j][q] = 0.f;

    auto load_stage = [&](int stage, int c) {
        uint32_t base = sb + stage * STAGE_PAD;
        int k0 = c * BK;
        #pragma unroll
        for (int i = 0; i < 2; i++) {                 // A1, A2: 64 rows
            int idx = tid + i*256;
            int r = idx >> 3, cb = (idx & 7) << 4;
            int gr = bm + r;
            bool v = gr < Mr;
            cp_async16(base + OFF_A1 + r*RSB + cb, Aq1 + (size_t)(v?gr:0)*K + k0 + cb, v);
            cp_async16(base + OFF_A2 + r*RSB + cb, Aq2 + (size_t)(v?gr:0)*K + k0 + cb, v);
        }
        #pragma unroll
        for (int i = 0; i < 4; i++) {                 // B1, B2: 128 rows
            int idx = tid + i*256;
            int r = idx >> 3, cb = (idx & 7) << 4;
            cp_async16(base + OFF_B1 + r*RSB + cb, Bq1 + (size_t)(bn + r)*K + k0 + cb, true);
            cp_async16(base + OFF_B2 + r*RSB + cb, Bq2 + (size_t)(bn + r)*K + k0 + cb, true);
        }
        if (tid < 16)
            cp_async16(base + OFF_SA + tid*16, As + (size_t)c*AsStride + bm + tid*4, true);
        else if (tid >= 32 && tid < 64)
            cp_async16(base + OFF_SB + (tid-32)*16, Bs + (size_t)c*Nc + bn + (tid-32)*4, true);
        CP_COMMIT();
    };

    const int NC = K / BK;
    load_stage(0, 0);

    const int aRow = (lane & 15);
    const int aColB = (lane >> 4) * 16;
    const int bMtx = lane >> 3, bRit = lane & 7;
    const int bNrow = (bMtx & 2) ? (8 + bRit) : bRit;
    const int bKoff = (bMtx & 1) * 16;
    const int er = lane >> 2, ec = (lane & 3) * 2;

    for (int c = 0; c < NC; c++) {
        if (c + 1 < NC) { load_stage((c + 1) & 1, c + 1); CP_WAIT(1); }
        else            { CP_WAIT(0); }
        __syncthreads();

        uint32_t st = sb + (c & 1) * STAGE_PAD;
        const float* sAp = (const float*)(smem + (c & 1)*STAGE_PAD + OFF_SA);
        const float* sBp = (const float*)(smem + (c & 1)*STAGE_PAD + OFF_SB);

        int accM[4][2][4], accC[4][2][4];
        #pragma unroll
        for (int i = 0; i < 4; i++)
            #pragma unroll
            for (int j = 0; j < 2; j++)
                #pragma unroll
                for (int q = 0; q < 4; q++) { accM[i][j][q] = 0; accC[i][j][q] = 0; }

        #pragma unroll
        for (int kk = 0; kk < 4; kk++) {
            uint32_t a1[4][4], a2[4][4], b1[2][2], b2[2][2];
            #pragma unroll
            for (int mt = 0; mt < 4; mt++) {
                uint32_t off = (uint32_t)((mt*16 + aRow) * RSB + kk*32 + aColB);
                ldsm_x4(a1[mt][0], a1[mt][1], a1[mt][2], a1[mt][3], st + OFF_A1 + off);
                ldsm_x4(a2[mt][0], a2[mt][1], a2[mt][2], a2[mt][3], st + OFF_A2 + off);
            }
            {
                uint32_t off = (uint32_t)((wn0 + bNrow) * RSB + kk*32 + bKoff);
                ldsm_x4(b1[0][0], b1[0][1], b1[1][0], b1[1][1], st + OFF_B1 + off);
                ldsm_x4(b2[0][0], b2[0][1], b2[1][0], b2[1][1], st + OFF_B2 + off);
            }
            #pragma unroll
            for (int mt = 0; mt < 4; mt++)
                #pragma unroll
                for (int nt = 0; nt < 2; nt++)
                    mma_s8(accM[mt][nt], a1[mt], b1[nt]);
            #pragma unroll
            for (int mt = 0; mt < 4; mt++)
                #pragma unroll
                for (int nt = 0; nt < 2; nt++)
                    mma_s8(accC[mt][nt], a1[mt], b2[nt]);
            #pragma unroll
            for (int mt = 0; mt < 4; mt++)
                #pragma unroll
                for (int nt = 0; nt < 2; nt++)
                    mma_s8(accC[mt][nt], a2[mt], b1[nt]);
        }

        // dequant into fp32 accumulators
        #pragma unroll
        for (int mt = 0; mt < 4; mt++) {
            float sa0 = sAp[mt*16 + er];
            float sa1 = sAp[mt*16 + er + 8];
            #pragma unroll
            for (int nt = 0; nt < 2; nt++) {
                float sb0 = sBp[wn0 + nt*8 + ec];
                float sb1 = sBp[wn0 + nt*8 + ec + 1];
                acc[mt][nt][0] += (float)(accM[mt][nt][0]*128 + accC[mt][nt][0]) * (sa0*sb0);
                acc[mt][nt][1] += (float)(accM[mt][nt][1]*128 + accC[mt][nt][1]) * (sa0*sb1);
                acc[mt][nt][2] += (float)(accM[mt][nt][2]*128 + accC[mt][nt][2]) * (sa1*sb0);
                acc[mt][nt][3] += (float)(accM[mt][nt][3]*128 + accC[mt][nt][3]) * (sa1*sb1);
            }
        }
        __syncthreads();
    }

    #pragma unroll
    for (int mt = 0; mt < 4; mt++) {
        int r0 = bm + mt*16 + er;
        int r1 = r0 + 8;
        #pragma unroll
        for (int nt = 0; nt < 2; nt++) {
            int cc = bn + wn0 + nt*8 + ec;
            float b0 = bias[cc], b1 = bias[cc + 1];
            if (r0 < Mr) {
                float v0 = acc[mt][nt][0] + b0;
                float v1 = acc[mt][nt][1] + b1;
                size_t off = (size_t)r0 * Nc + cc;
                if (EPI == 1) { v0 += R[off]; v1 += R[off + 1]; }
                if (EPI == 2) { v0 = gelu_exact(v0); v1 = gelu_exact(v1); }
                C[off] = v0; C[off + 1] = v1;
            }
            if (r1 < Mr) {
                float v2 = acc[mt][nt][2] + b0;
                float v3 = acc[mt][nt][3] + b1;
                size_t off = (size_t)r1 * Nc + cc;
                if (EPI == 1) { v2 += R[off]; v3 += R[off + 1]; }
                if (EPI == 2) { v2 = gelu_exact(v2); v3 = gelu_exact(v3); }
                C[off] = v2; C[off + 1] = v3;
            }
        }
    }
}

// ---------------- quantization helpers ----------------------------------------
__device__ __forceinline__ void quant_block_lane(const float* v4, float inv,
                                                 char4& c1, char4& c2)
{
    int a1[4], a2[4];
    #pragma unroll
    for (int j = 0; j < 4; j++) {
        float s = v4[j] * inv;
        a1[j] = (int)rintf(s);
        a2[j] = (int)rintf((s - (float)a1[j]) * 128.f);
    }
    c1 = make_char4((char)a1[0], (char)a1[1], (char)a1[2], (char)a1[3]);
    c2 = make_char4((char)a2[0], (char)a2[1], (char)a2[2], (char)a2[3]);
}

__global__ void rowquant_kernel(const float* __restrict__ X,
                                int8_t* __restrict__ Q1, int8_t* __restrict__ Q2,
                                float* __restrict__ St,
                                int Kd, int srows, float postscale)
{
    int r = blockIdx.x;
    int w = threadIdx.x >> 5, lane = threadIdx.x & 31;
    const float* x = X + (size_t)r * Kd;
    for (int kb = w; kb < Kd/128; kb += 8) {
        float v[4]; float mx = 0.f;
        #pragma unroll
        for (int j = 0; j < 4; j++) {
            v[j] = x[kb*128 + lane*4 + j];
            mx = fmaxf(mx, fabsf(v[j]));
        }
        #pragma unroll
        for (int o = 16; o > 0; o >>= 1) mx = fmaxf(mx, __shfl_xor_sync(0xffffffffu, mx, o));
        float inv = mx > 0.f ? 127.f/mx : 0.f;
        char4 c1, c2;
        quant_block_lane(v, inv, c1, c2);
        size_t o = (size_t)r*Kd + kb*128 + lane*4;
        *(char4*)&Q1[o] = c1;
        *(char4*)&Q2[o] = c2;
        if (lane == 0) St[(size_t)kb*srows + r] = mx * postscale;
    }
}

__global__ void ln_quant_kernel(const float* __restrict__ X,
                                const float* __restrict__ gam,
                                const float* __restrict__ bet,
                                int8_t* __restrict__ Q1, int8_t* __restrict__ Q2,
                                float* __restrict__ St)
{
    int row = blockIdx.x;
    const float* x = X + (size_t)row * D;
    int tid = threadIdx.x;
    __shared__ float vrow[D];

    float s = 0.f, ss = 0.f;
    for (int i = tid; i < D; i += 256) { float v = x[i]; s += v; ss += v*v; }
    __shared__ float rs[8], rss[8];
    #pragma unroll
    for (int o = 16; o > 0; o >>= 1) {
        s  += __shfl_xor_sync(0xffffffffu, s,  o);
        ss += __shfl_xor_sync(0xffffffffu, ss, o);
    }
    int w = tid >> 5, lane = tid & 31;
    if (lane == 0) { rs[w] = s; rss[w] = ss; }
    __syncthreads();
    __shared__ float s_mean, s_inv;
    if (tid == 0) {
        float ts = 0.f, tss = 0.f;
        for (int k = 0; k < 8; k++) { ts += rs[k]; tss += rss[k]; }
        float mean = ts * (1.f/D);
        float var  = tss * (1.f/D) - mean*mean;
        s_mean = mean; s_inv = rsqrtf(var + LN_EPS);
    }
    __syncthreads();
    float mean = s_mean, inv = s_inv;
    for (int i = tid; i < D; i += 256)
        vrow[i] = (x[i] - mean) * inv * gam[i] + bet[i];
    __syncthreads();

    if (w < 6) {
        float v[4]; float mx = 0.f;
        #pragma unroll
        for (int j = 0; j < 4; j++) {
            v[j] = vrow[w*128 + lane*4 + j];
            mx = fmaxf(mx, fabsf(v[j]));
        }
        #pragma unroll
        for (int o = 16; o > 0; o >>= 1) mx = fmaxf(mx, __shfl_xor_sync(0xffffffffu, mx, o));
        float qi = mx > 0.f ? 127.f/mx : 0.f;
        char4 c1, c2;
        quant_block_lane(v, qi, c1, c2);
        size_t o = (size_t)row*D + w*128 + lane*4;
        *(char4*)&Q1[o] = c1;
        *(char4*)&Q2[o] = c2;
        if (lane == 0) St[(size_t)w*MP + row] = mx * (1.f/127.f);
    }
}

// ---------------- weight transpose -------------------------------------------
__global__ void wtrans_kernel(const float* __restrict__ W, float* __restrict__ Wt,
                              int K, int N)
{
    __shared__ float t[32][33];
    int n0 = blockIdx.x * 32, k0 = blockIdx.y * 32;
    int tx = threadIdx.x, ty = threadIdx.y;
    for (int i = ty; i < 32; i += 8)
        t[i][tx] = W[(size_t)(k0 + i) * N + n0 + tx];
    __syncthreads();
    for (int r = ty; r < 32; r += 8)
        Wt[(size_t)(n0 + r) * K + k0 + tx] = t[tx][r];
}

// ---------------- attention kernels (fp32) -----------------------------------
__global__ void attn_cls_kernel(const float* __restrict__ qkv,
                                float* __restrict__ att)
{
    int bh = blockIdx.x;
    int b = bh / H, hh = bh % H;
    int tid = threadIdx.x;

    __shared__ float qs[HD];
    __shared__ float sim[NT];
    __shared__ float red[256];
    __shared__ float red2[4][HD];

    if (tid < HD)
        qs[tid] = qkv[(size_t)(b*NT) * D3 + hh*HD + tid] * QSCALE;
    __syncthreads();

    float lmx = -1e30f;
    for (int j = tid; j < NT; j += 256) {
        const float* kp = qkv + (size_t)(b*NT + j) * D3 + D + hh*HD;
        float s = 0.f;
        #pragma unroll
        for (int d = 0; d < HD; d++) s += qs[d] * kp[d];
        sim[j] = s;
        lmx = fmaxf(lmx, s);
    }
    red[tid] = lmx; __syncthreads();
    for (int st = 128; st > 0; st >>= 1) {
        if (tid < st) red[tid] = fmaxf(red[tid], red[tid+st]);
        __syncthreads();
    }
    float mx = red[0];
    __syncthreads();

    float ls = 0.f;
    for (int j = tid; j < NT; j += 256) {
        float e = __expf(sim[j] - mx);
        sim[j] = e;
        ls += e;
    }
    red[tid] = ls; __syncthreads();
    for (int st = 128; st > 0; st >>= 1) {
        if (tid < st) red[tid] += red[tid+st];
        __syncthreads();
    }
    float linv = 1.f / red[0];
    __syncthreads();

    int d = tid & 63, p = tid >> 6;
    float acc = 0.f;
    for (int j = p; j < NT; j += 4)
        acc += sim[j] * qkv[(size_t)(b*NT + j) * D3 + 2*D + hh*HD + d];
    red2[p][d] = acc;
    __syncthreads();
    if (p == 0) {
        float o = (red2[0][d] + red2[1][d] + red2[2][d] + red2[3][d]) * linv;
        att[(size_t)(b*NT) * D + hh*HD + d] = o;
    }
}

__global__ void attn_time_kernel(const float* __restrict__ qkv,
                                 float* __restrict__ att)
{
    int qid = blockIdx.x * blockDim.x + threadIdx.x;
    int fr = qid % F;
    int sp = (qid / F) % NS;
    int bh = qid / (F * NS);
    int b = bh / H, hh = bh % H;
    int t = 1 + fr*NS + sp;

    const float4* qp = (const float4*)(qkv + (size_t)(b*NT + t) * D3 + hh*HD);
    float4 q4[16];
    #pragma unroll
    for (int i = 0; i < 16; i++) {
        float4 v = qp[i];
        v.x *= QSCALE; v.y *= QSCALE; v.z *= QSCALE; v.w *= QSCALE;
        q4[i] = v;
    }

    float sim[F+1];
    #pragma unroll
    for (int j = 0; j < F+1; j++) {
        int tk = (j == 0) ? 0 : (1 + (j-1)*NS + sp);
        const float4* kp = (const float4*)(qkv + (size_t)(b*NT + tk) * D3 + D + hh*HD);
        float s = 0.f;
        #pragma unroll
        for (int i = 0; i < 16; i++) {
            float4 kk = kp[i];
            s += q4[i].x*kk.x + q4[i].y*kk.y + q4[i].z*kk.z + q4[i].w*kk.w;
        }
        sim[j] = s;
    }
    float mx = sim[0];
    #pragma unroll
    for (int j = 1; j < F+1; j++) mx = fmaxf(mx, sim[j]);
    float l = 0.f;
    #pragma unroll
    for (int j = 0; j < F+1; j++) { sim[j] = __expf(sim[j] - mx); l += sim[j]; }
    float inv = 1.f / l;

    float4 o4[16];
    #pragma unroll
    for (int i = 0; i < 16; i++) o4[i] = make_float4(0.f,0.f,0.f,0.f);
    #pragma unroll
    for (int j = 0; j < F+1; j++) {
        int tk = (j == 0) ? 0 : (1 + (j-1)*NS + sp);
        const float4* vp = (const float4*)(qkv + (size_t)(b*NT + tk) * D3 + 2*D + hh*HD);
        float p = sim[j] * inv;
        #pragma unroll
        for (int i = 0; i < 16; i++) {
            float4 vv = vp[i];
            o4[i].x += p*vv.x; o4[i].y += p*vv.y; o4[i].z += p*vv.z; o4[i].w += p*vv.w;
        }
    }
    float4* op = (float4*)(att + (size_t)(b*NT + t) * D + hh*HD);
    #pragma unroll
    for (int i = 0; i < 16; i++) op[i] = o4[i];
}

__global__ void attn_space_kernel(const float* __restrict__ qkv,
                                  float* __restrict__ att)
{
    int bx = blockIdx.x;
    int bh = bx / F, fr = bx % F;
    int b = bh / H, hh = bh % H;
    int tid = threadIdx.x;
    int sp = tid;
    const int NK = NS + 1;

    __shared__ float Ks[64 * HD];
    __shared__ float Vs[64 * HD];

    float4 q4[16], o4[16];
    float m = -1e30f, l = 0.f;
    if (sp < NS) {
        const float4* qp = (const float4*)(qkv + (size_t)(b*NT + 1 + fr*NS + sp) * D3 + hh*HD);
        #pragma unroll
        for (int i = 0; i < 16; i++) {
            float4 v = qp[i];
            v.x *= QSCALE; v.y *= QSCALE; v.z *= QSCALE; v.w *= QSCALE;
            q4[i] = v;
            o4[i] = make_float4(0.f,0.f,0.f,0.f);
        }
    }

    for (int t0 = 0; t0 < NK; t0 += 64) {
        __syncthreads();
        for (int e = tid; e < 64*HD; e += 256) {
            int jj = e >> 6, d = e & 63;
            int j = t0 + jj;
            float kv = 0.f, vv = 0.f;
            if (j < NK) {
                int tk = (j == 0) ? 0 : (1 + fr*NS + (j-1));
                size_t base = (size_t)(b*NT + tk) * D3 + hh*HD + d;
                kv = qkv[base + D];
                vv = qkv[base + 2*D];
            }
            Ks[e] = kv; Vs[e] = vv;
        }
        __syncthreads();

        if (sp < NS) {
            int lim = min(64, NK - t0);
            for (int jj = 0; jj < lim; jj++) {
                const float4* kr = (const float4*)&Ks[jj * HD];
                float s = 0.f;
                #pragma unroll
                for (int i = 0; i < 16; i++) {
                    float4 kk = kr[i];
                    s += q4[i].x*kk.x + q4[i].y*kk.y + q4[i].z*kk.z + q4[i].w*kk.w;
                }
                float mn  = fmaxf(m, s);
                float fac = __expf(m - mn);
                float p   = __expf(s - mn);
                l = l * fac + p;
                const float4* vr = (const float4*)&Vs[jj * HD];
                #pragma unroll
                for (int i = 0; i < 16; i++) {
                    float4 vv = vr[i];
                    o4[i].x = o4[i].x*fac + p*vv.x;
                    o4[i].y = o4[i].y*fac + p*vv.y;
                    o4[i].z = o4[i].z*fac + p*vv.z;
                    o4[i].w = o4[i].w*fac + p*vv.w;
                }
                m = mn;
            }
        }
    }

    if (sp < NS) {
        float inv = 1.f / l;
        float4* op = (float4*)(att + (size_t)(b*NT + 1 + fr*NS + sp) * D + hh*HD);
        #pragma unroll
        for (int i = 0; i < 16; i++)
            op[i] = make_float4(o4[i].x*inv, o4[i].y*inv, o4[i].z*inv, o4[i].w*inv);
    }
}

// ---------------- host launch ------------------------------------------------
extern "C" void kernel_launch(void* const* d_in, const int* in_sizes, int n_in,
                              void* d_out, int out_size)
{
    const float* x      = (const float*)d_in[0];
    const float* n1g    = (const float*)d_in[1];
    const float* n1b    = (const float*)d_in[2];
    const float* n2g    = (const float*)d_in[3];
    const float* n2b    = (const float*)d_in[4];
    const float* n3g    = (const float*)d_in[5];
    const float* n3b    = (const float*)d_in[6];
    const float* aqkvw  = (const float*)d_in[7];
    const float* aqkvb  = (const float*)d_in[8];
    const float* aprojw = (const float*)d_in[9];
    const float* aprojb = (const float*)d_in[10];
    const float* tqkvw  = (const float*)d_in[11];
    const float* tqkvb  = (const float*)d_in[12];
    const float* tprojw = (const float*)d_in[13];
    const float* tprojb = (const float*)d_in[14];
    const float* fc1w   = (const float*)d_in[15];
    const float* fc1b   = (const float*)d_in[16];
    const float* fc2w   = (const float*)d_in[17];
    const float* fc2b   = (const float*)d_in[18];
    float* out = (float*)d_out;

    int8_t *lnq1,*lnq2,*attq1,*attq2,*hidq1,*hidq2;
    float *lns,*atts,*hids,*bqkv,*batt,*btres,*bsres,*bhid,*wtmp;
    cudaGetSymbolAddress((void**)&lnq1, g_lnq1);   cudaGetSymbolAddress((void**)&lnq2, g_lnq2);
    cudaGetSymbolAddress((void**)&lns,  g_lns);
    cudaGetSymbolAddress((void**)&attq1,g_attq1);  cudaGetSymbolAddress((void**)&attq2,g_attq2);
    cudaGetSymbolAddress((void**)&atts, g_atts);
    cudaGetSymbolAddress((void**)&hidq1,g_hidq1);  cudaGetSymbolAddress((void**)&hidq2,g_hidq2);
    cudaGetSymbolAddress((void**)&hids, g_hids);
    cudaGetSymbolAddress((void**)&bqkv, g_qkv);    cudaGetSymbolAddress((void**)&batt, g_att);
    cudaGetSymbolAddress((void**)&btres,g_tres);   cudaGetSymbolAddress((void**)&bsres,g_sres);
    cudaGetSymbolAddress((void**)&bhid, g_hid);    cudaGetSymbolAddress((void**)&wtmp, g_wtmp);

    int8_t *q1_tqkv,*q2_tqkv,*q1_aqkv,*q2_aqkv,*q1_tproj,*q2_tproj,*q1_aproj,*q2_aproj,*q1_fc1,*q2_fc1,*q1_fc2,*q2_fc2;
    float *s_tqkv,*s_aqkv,*s_tproj,*s_aproj,*s_fc1,*s_fc2;
    cudaGetSymbolAddress((void**)&q1_tqkv, g_q1_tqkv); cudaGetSymbolAddress((void**)&q2_tqkv, g_q2_tqkv);
    cudaGetSymbolAddress((void**)&s_tqkv, g_s_tqkv);
    cudaGetSymbolAddress((void**)&q1_aqkv, g_q1_aqkv); cudaGetSymbolAddress((void**)&q2_aqkv, g_q2_aqkv);
    cudaGetSymbolAddress((void**)&s_aqkv, g_s_aqkv);
    cudaGetSymbolAddress((void**)&q1_tproj,g_q1_tproj);cudaGetSymbolAddress((void**)&q2_tproj,g_q2_tproj);
    cudaGetSymbolAddress((void**)&s_tproj,g_s_tproj);
    cudaGetSymbolAddress((void**)&q1_aproj,g_q1_aproj);cudaGetSymbolAddress((void**)&q2_aproj,g_q2_aproj);
    cudaGetSymbolAddress((void**)&s_aproj,g_s_aproj);
    cudaGetSymbolAddress((void**)&q1_fc1, g_q1_fc1);   cudaGetSymbolAddress((void**)&q2_fc1, g_q2_fc1);
    cudaGetSymbolAddress((void**)&s_fc1, g_s_fc1);
    cudaGetSymbolAddress((void**)&q1_fc2, g_q1_fc2);   cudaGetSymbolAddress((void**)&q2_fc2, g_q2_fc2);
    cudaGetSymbolAddress((void**)&s_fc2, g_s_fc2);

    cudaFuncSetAttribute(gemm_s8<0>, cudaFuncAttributeMaxDynamicSharedMemorySize, SMEM_GEMM);
    cudaFuncSetAttribute(gemm_s8<1>, cudaFuncAttributeMaxDynamicSharedMemorySize, SMEM_GEMM);
    cudaFuncSetAttribute(gemm_s8<2>, cudaFuncAttributeMaxDynamicSharedMemorySize, SMEM_GEMM);

    const int MT = (M + BM - 1) / BM;    // 197
    dim3 tb(32, 8);
    const float wps = 1.f / (127.f * 128.f);

    // ---- weight transpose + quantize ----
    wtrans_kernel<<<dim3(D3/32, D/32), tb>>>(tqkvw, wtmp, D, D3);
    rowquant_kernel<<<D3, 256>>>(wtmp, q1_tqkv, q2_tqkv, s_tqkv, D, D3, wps);
    wtrans_kernel<<<dim3(D3/32, D/32), tb>>>(aqkvw, wtmp, D, D3);
    rowquant_kernel<<<D3, 256>>>(wtmp, q1_aqkv, q2_aqkv, s_aqkv, D, D3, wps);
    wtrans_kernel<<<dim3(D/32, D/32), tb>>>(tprojw, wtmp, D, D);
    rowquant_kernel<<<D, 256>>>(wtmp, q1_tproj, q2_tproj, s_tproj, D, D, wps);
    wtrans_kernel<<<dim3(D/32, D/32), tb>>>(aprojw, wtmp, D, D);
    rowquant_kernel<<<D, 256>>>(wtmp, q1_aproj, q2_aproj, s_aproj, D, D, wps);
    wtrans_kernel<<<dim3(D4/32, D/32), tb>>>(fc1w, wtmp, D, D4);
    rowquant_kernel<<<D4, 256>>>(wtmp, q1_fc1, q2_fc1, s_fc1, D, D4, wps);
    wtrans_kernel<<<dim3(D/32, D4/32), tb>>>(fc2w, wtmp, D4, D);
    rowquant_kernel<<<D, 256>>>(wtmp, q1_fc2, q2_fc2, s_fc2, D4, D, wps);

    const int nTimeBlocks = (B*H*NS*F) / 256;   // 588

    // ---- time attention branch ----
    ln_quant_kernel<<<M, 256>>>(x, n3g, n3b, lnq1, lnq2, lns);
    gemm_s8<0><<<dim3(D3/BN, MT), 256, SMEM_GEMM>>>(lnq1, lnq2, lns, MP, q1_tqkv, q2_tqkv, s_tqkv, tqkvb, nullptr, bqkv, M, D, D3);
    attn_cls_kernel <<<B*H, 256>>>(bqkv, batt);
    attn_time_kernel<<<nTimeBlocks, 256>>>(bqkv, batt);
    rowquant_kernel<<<M, 256>>>(batt, attq1, attq2, atts, D, MP, 1.f/127.f);
    gemm_s8<1><<<dim3(D/BN, MT), 256, SMEM_GEMM>>>(attq1, attq2, atts, MP, q1_tproj, q2_tproj, s_tproj, tprojb, x, btres, M, D, D);

    // ---- space attention branch ----
    ln_quant_kernel<<<M, 256>>>(btres, n1g, n1b, lnq1, lnq2, lns);
    gemm_s8<0><<<dim3(D3/BN, MT), 256, SMEM_GEMM>>>(lnq1, lnq2, lns, MP, q1_aqkv, q2_aqkv, s_aqkv, aqkvb, nullptr, bqkv, M, D, D3);
    attn_cls_kernel  <<<B*H, 256>>>(bqkv, batt);
    attn_space_kernel<<<B*H*F, 256>>>(bqkv, batt);
    rowquant_kernel<<<M, 256>>>(batt, attq1, attq2, atts, D, MP, 1.f/127.f);
    gemm_s8<1><<<dim3(D/BN, MT), 256, SMEM_GEMM>>>(attq1, attq2, atts, MP, q1_aproj, q2_aproj, s_aproj, aprojb, x, bsres, M, D, D);

    // ---- MLP ----
    ln_quant_kernel<<<M, 256>>>(bsres, n2g, n2b, lnq1, lnq2, lns);
    gemm_s8<2><<<dim3(D4/BN, MT), 256, SMEM_GEMM>>>(lnq1, lnq2, lns, MP, q1_fc1, q2_fc1, s_fc1, fc1b, nullptr, bhid, M, D, D4);
    rowquant_kernel<<<M, 256>>>(bhid, hidq1, hidq2, hids, D4, MP, 1.f/127.f);
    gemm_s8<1><<<dim3(D/BN, MT), 256, SMEM_GEMM>>>(hidq1, hidq2, hids, MP, q1_fc2, q2_fc2, s_fc2, fc2b, bsres, out, M, D4, D);
}

// round 8
// speedup vs baseline: 2.5224x; 2.5224x over previous
#include <cuda_runtime.h>
#include <cuda_bf16.h>
#include <cuda_fp16.h>
#include <math.h>
#include <cstdint>

// ---------------- problem constants ----------------------------------------
constexpr int B   = 8;
constexpr int F   = 8;
constexpr int NS  = 196;
constexpr int NT  = 1 + F*NS;   // 1569
constexpr int D   = 768;
constexpr int H   = 12;
constexpr int HD  = 64;
constexpr int D3  = 3*D;        // 2304
constexpr int D4  = 4*D;        // 3072
constexpr int M   = B*NT;       // 12552
constexpr float LN_EPS = 1e-5f;
constexpr float QSCALE = 0.125f;

// ---------------- scratch (device globals; no allocation) ------------------
__device__ __nv_bfloat16 g_lnh [(size_t)M * D];   // also reused as __half for MLP path
__device__ __nv_bfloat16 g_lnl [(size_t)M * D];
__device__ float         g_qkv [(size_t)M * D3];
__device__ __nv_bfloat16 g_atth[(size_t)M * D];
__device__ __nv_bfloat16 g_attl[(size_t)M * D];
__device__ float         g_tres[(size_t)M * D];
__device__ float         g_sres[(size_t)M * D];
__device__ __half        g_hidf[(size_t)M * D4];
// transposed weights: bf16 hi/lo for attention path, fp16 for MLP path
__device__ __nv_bfloat16 g_wth_tqkv [(size_t)D3*D], g_wtl_tqkv [(size_t)D3*D];
__device__ __nv_bfloat16 g_wth_aqkv [(size_t)D3*D], g_wtl_aqkv [(size_t)D3*D];
__device__ __nv_bfloat16 g_wth_tproj[(size_t)D*D],  g_wtl_tproj[(size_t)D*D];
__device__ __nv_bfloat16 g_wth_aproj[(size_t)D*D],  g_wtl_aproj[(size_t)D*D];
__device__ __half        g_wf_fc1   [(size_t)D4*D];
__device__ __half        g_wf_fc2   [(size_t)D*D4];

// ---------------- helpers ----------------------------------------------------
__device__ __forceinline__ uint32_t smem_to_u32(const void* p) {
    uint32_t a;
    asm("{ .reg .u64 t; cvta.to.shared.u64 t, %1; cvt.u32.u64 %0, t; }"
        : "=r"(a) : "l"(p));
    return a;
}
__device__ __forceinline__ void cp_async16(uint32_t dst, const void* src, bool valid) {
    int sz = valid ? 16 : 0;
    asm volatile("cp.async.cg.shared.global [%0], [%1], 16, %2;"
                 :: "r"(dst), "l"(src), "r"(sz) : "memory");
}
#define CP_COMMIT()  asm volatile("cp.async.commit_group;" ::: "memory")
#define CP_WAIT(n)   asm volatile("cp.async.wait_group %0;" :: "n"(n) : "memory")

__device__ __forceinline__ void ldsm_x4(uint32_t& r0, uint32_t& r1, uint32_t& r2, uint32_t& r3, uint32_t addr) {
    asm volatile("ldmatrix.sync.aligned.m8n8.x4.shared.b16 {%0,%1,%2,%3}, [%4];"
                 : "=r"(r0), "=r"(r1), "=r"(r2), "=r"(r3) : "r"(addr));
}
__device__ __forceinline__ void mma_bf16(float* c, const uint32_t* a, const uint32_t* b) {
    asm volatile(
        "mma.sync.aligned.m16n8k16.row.col.f32.bf16.bf16.f32 "
        "{%0,%1,%2,%3}, {%4,%5,%6,%7}, {%8,%9}, {%0,%1,%2,%3};"
        : "+f"(c[0]), "+f"(c[1]), "+f"(c[2]), "+f"(c[3])
        : "r"(a[0]), "r"(a[1]), "r"(a[2]), "r"(a[3]), "r"(b[0]), "r"(b[1]));
}
__device__ __forceinline__ void mma_f16(float* c, const uint32_t* a, const uint32_t* b) {
    asm volatile(
        "mma.sync.aligned.m16n8k16.row.col.f32.f16.f16.f32 "
        "{%0,%1,%2,%3}, {%4,%5,%6,%7}, {%8,%9}, {%0,%1,%2,%3};"
        : "+f"(c[0]), "+f"(c[1]), "+f"(c[2]), "+f"(c[3])
        : "r"(a[0]), "r"(a[1]), "r"(a[2]), "r"(a[3]), "r"(b[0]), "r"(b[1]));
}
__device__ __forceinline__ float gelu_exact(float v) {
    return 0.5f * v * (1.f + erff(v * 0.70710678118654752f));
}
__device__ __forceinline__ __nv_bfloat162 split2(float v0, float v1, __nv_bfloat162& lo) {
    __nv_bfloat16 h0 = __float2bfloat16(v0), h1 = __float2bfloat16(v1);
    lo = __halves2bfloat162(__float2bfloat16(v0 - __bfloat162float(h0)),
                            __float2bfloat16(v1 - __bfloat162float(h1)));
    return __halves2bfloat162(h0, h1);
}

// ================= bf16x3 GEMM (R5, 4-stage, term-major) ======================
constexpr int BM = 128, BN = 128, BK = 32;
constexpr int RSB = 80;
constexpr int MAT_B = 128 * RSB;       // 10240
constexpr int STAGE_B = 4 * MAT_B;     // 40960
constexpr int SMEM_GEMM = 4 * STAGE_B; // 163840

// EPI: 0 = bias (fp32 out), 1 = bias+residual (fp32 out)
template<int EPI>
__global__ void __launch_bounds__(256, 1)
gemm_bf16x3(const __nv_bfloat16* __restrict__ Ah, const __nv_bfloat16* __restrict__ Al,
            const __nv_bfloat16* __restrict__ Bh, const __nv_bfloat16* __restrict__ Bl,
            const float* __restrict__ bias, const float* __restrict__ R,
            float* __restrict__ C, int Mr, int K, int Nc)
{
    extern __shared__ char smem[];
    const uint32_t sb = smem_to_u32(smem);
    const int tid = threadIdx.x;
    const int wid = tid >> 5, lane = tid & 31;
    const int wm = wid & 1, wn = wid >> 1;
    const int bm = blockIdx.y * BM, bn = blockIdx.x * BN;

    float acc[4][4][4];
    #pragma unroll
    for (int i = 0; i < 4; i++)
        #pragma unroll
        for (int j = 0; j < 4; j++)
            #pragma unroll
            for (int q = 0; q < 4; q++) acc[i][j][q] = 0.f;

    auto load_stage = [&](int stage, int k0) {
        uint32_t base = sb + stage * STAGE_B;
        #pragma unroll
        for (int i = 0; i < 2; i++) {
            int idx = tid + i*256;
            int r = idx >> 2, cb = (idx & 3) << 4;
            int gr = bm + r;
            bool v = gr < Mr;
            cp_async16(base + 0*MAT_B + r*RSB + cb, (const char*)(Ah + (size_t)(v?gr:0)*K + k0) + cb, v);
            cp_async16(base + 1*MAT_B + r*RSB + cb, (const char*)(Al + (size_t)(v?gr:0)*K + k0) + cb, v);
        }
        #pragma unroll
        for (int i = 0; i < 2; i++) {
            int idx = tid + i*256;
            int r = idx >> 2, cb = (idx & 3) << 4;
            cp_async16(base + 2*MAT_B + r*RSB + cb, (const char*)(Bh + (size_t)(bn + r)*K + k0) + cb, true);
            cp_async16(base + 3*MAT_B + r*RSB + cb, (const char*)(Bl + (size_t)(bn + r)*K + k0) + cb, true);
        }
        CP_COMMIT();
    };

    const int NC = K / BK;
    load_stage(0, 0);
    load_stage(1, BK);
    load_stage(2, 2*BK);

    const int aRow = (lane & 15);
    const int aColB = (lane >> 4) * 16;
    const int bMtx = lane >> 3, bRit = lane & 7;
    const int bNrow = (bMtx & 2) ? (8 + bRit) : bRit;
    const int bKoff = (bMtx & 1) * 16;

    for (int c = 0; c < NC; c++) {
        CP_WAIT(2);
        __syncthreads();
        if (c + 3 < NC) load_stage((c + 3) & 3, (c + 3) * BK);

        uint32_t st = sb + (c & 3) * STAGE_B;
        uint32_t aHb = st + 0*MAT_B, aLb = st + 1*MAT_B;
        uint32_t bHb = st + 2*MAT_B, bLb = st + 3*MAT_B;

        #pragma unroll
        for (int kk = 0; kk < 2; kk++) {
            uint32_t ah[4][4], al[4][4], bh[4][2], bl[4][2];
            #pragma unroll
            for (int mt = 0; mt < 4; mt++) {
                uint32_t off = (uint32_t)((wm*64 + mt*16 + aRow) * RSB + kk*32 + aColB);
                ldsm_x4(ah[mt][0], ah[mt][1], ah[mt][2], ah[mt][3], aHb + off);
                ldsm_x4(al[mt][0], al[mt][1], al[mt][2], al[mt][3], aLb + off);
            }
            #pragma unroll
            for (int np = 0; np < 2; np++) {
                uint32_t off = (uint32_t)((wn*32 + np*16 + bNrow) * RSB + kk*32 + bKoff);
                ldsm_x4(bh[2*np][0], bh[2*np][1], bh[2*np+1][0], bh[2*np+1][1], bHb + off);
                ldsm_x4(bl[2*np][0], bl[2*np][1], bl[2*np+1][0], bl[2*np+1][1], bLb + off);
            }
            #pragma unroll
            for (int mt = 0; mt < 4; mt++)
                #pragma unroll
                for (int nt = 0; nt < 4; nt++)
                    mma_bf16(acc[mt][nt], ah[mt], bh[nt]);
            #pragma unroll
            for (int mt = 0; mt < 4; mt++)
                #pragma unroll
                for (int nt = 0; nt < 4; nt++)
                    mma_bf16(acc[mt][nt], ah[mt], bl[nt]);
            #pragma unroll
            for (int mt = 0; mt < 4; mt++)
                #pragma unroll
                for (int nt = 0; nt < 4; nt++)
                    mma_bf16(acc[mt][nt], al[mt], bh[nt]);
        }
    }

    const int er = lane >> 2, ec = (lane & 3) * 2;
    #pragma unroll
    for (int mt = 0; mt < 4; mt++) {
        int r0 = bm + wm*64 + mt*16 + er;
        int r1 = r0 + 8;
        #pragma unroll
        for (int nt = 0; nt < 4; nt++) {
            int cc = bn + wn*32 + nt*8 + ec;
            float b0 = bias[cc], b1 = bias[cc + 1];
            if (r0 < Mr) {
                float v0 = acc[mt][nt][0] + b0;
                float v1 = acc[mt][nt][1] + b1;
                size_t off = (size_t)r0 * Nc + cc;
                if (EPI == 1) { v0 += R[off]; v1 += R[off + 1]; }
                C[off] = v0; C[off + 1] = v1;
            }
            if (r1 < Mr) {
                float v2 = acc[mt][nt][2] + b0;
                float v3 = acc[mt][nt][3] + b1;
                size_t off = (size_t)r1 * Nc + cc;
                if (EPI == 1) { v2 += R[off]; v3 += R[off + 1]; }
                C[off] = v2; C[off + 1] = v3;
            }
        }
    }
}

// ================= fp16 single-pass GEMM (MLP path) ===========================
// EPI: 1 = bias+residual -> fp32 C ; 4 = bias+GELU -> fp16 Ch
constexpr int FBK = 64;
constexpr int FRSB = 144;               // 128B data + 16B pad
constexpr int FMAT = 128 * FRSB;        // 18432
constexpr int FSTAGE = 2 * FMAT;        // 36864
constexpr int SMEM_F16 = 4 * FSTAGE;    // 147456

template<int EPI>
__global__ void __launch_bounds__(256, 1)
gemm_f16(const __half* __restrict__ A, const __half* __restrict__ Bw,
         const float* __restrict__ bias, const float* __restrict__ R,
         float* __restrict__ C, __half* __restrict__ Ch,
         int Mr, int K, int Nc)
{
    extern __shared__ char smem[];
    const uint32_t sb = smem_to_u32(smem);
    const int tid = threadIdx.x;
    const int wid = tid >> 5, lane = tid & 31;
    const int wm = wid & 1, wn = wid >> 1;
    const int bm = blockIdx.y * BM, bn = blockIdx.x * BN;

    float acc[4][4][4];
    #pragma unroll
    for (int i = 0; i < 4; i++)
        #pragma unroll
        for (int j = 0; j < 4; j++)
            #pragma unroll
            for (int q = 0; q < 4; q++) acc[i][j][q] = 0.f;

    auto load_stage = [&](int stage, int k0) {
        uint32_t base = sb + stage * FSTAGE;
        #pragma unroll
        for (int i = 0; i < 4; i++) {
            int idx = tid + i*256;
            int r = idx >> 3, cb = (idx & 7) << 4;
            int gr = bm + r;
            bool v = gr < Mr;
            cp_async16(base + r*FRSB + cb, (const char*)(A + (size_t)(v?gr:0)*K + k0) + cb, v);
        }
        #pragma unroll
        for (int i = 0; i < 4; i++) {
            int idx = tid + i*256;
            int r = idx >> 3, cb = (idx & 7) << 4;
            cp_async16(base + FMAT + r*FRSB + cb, (const char*)(Bw + (size_t)(bn + r)*K + k0) + cb, true);
        }
        CP_COMMIT();
    };

    const int NC = K / FBK;
    load_stage(0, 0);
    load_stage(1, FBK);
    load_stage(2, 2*FBK);

    const int aRow = (lane & 15);
    const int aColB = (lane >> 4) * 16;
    const int bMtx = lane >> 3, bRit = lane & 7;
    const int bNrow = (bMtx & 2) ? (8 + bRit) : bRit;
    const int bKoff = (bMtx & 1) * 16;

    for (int c = 0; c < NC; c++) {
        CP_WAIT(2);
        __syncthreads();
        if (c + 3 < NC) load_stage((c + 3) & 3, (c + 3) * FBK);

        uint32_t aB = sb + (c & 3) * FSTAGE;
        uint32_t bB = aB + FMAT;

        #pragma unroll
        for (int kk = 0; kk < 4; kk++) {
            uint32_t af[4][4], bf[4][2];
            #pragma unroll
            for (int mt = 0; mt < 4; mt++) {
                uint32_t off = (uint32_t)((wm*64 + mt*16 + aRow) * FRSB + kk*32 + aColB);
                ldsm_x4(af[mt][0], af[mt][1], af[mt][2], af[mt][3], aB + off);
            }
            #pragma unroll
            for (int np = 0; np < 2; np++) {
                uint32_t off = (uint32_t)((wn*32 + np*16 + bNrow) * FRSB + kk*32 + bKoff);
                ldsm_x4(bf[2*np][0], bf[2*np][1], bf[2*np+1][0], bf[2*np+1][1], bB + off);
            }
            #pragma unroll
            for (int mt = 0; mt < 4; mt++)
                #pragma unroll
                for (int nt = 0; nt < 4; nt++)
                    mma_f16(acc[mt][nt], af[mt], bf[nt]);
        }
    }

    const int er = lane >> 2, ec = (lane & 3) * 2;
    #pragma unroll
    for (int mt = 0; mt < 4; mt++) {
        int r0 = bm + wm*64 + mt*16 + er;
        int r1 = r0 + 8;
        #pragma unroll
        for (int nt = 0; nt < 4; nt++) {
            int cc = bn + wn*32 + nt*8 + ec;
            float b0 = bias[cc], b1 = bias[cc + 1];
            if (r0 < Mr) {
                float v0 = acc[mt][nt][0] + b0;
                float v1 = acc[mt][nt][1] + b1;
                size_t off = (size_t)r0 * Nc + cc;
                if (EPI == 1) {
                    v0 += R[off]; v1 += R[off + 1];
                    C[off] = v0; C[off + 1] = v1;
                } else {
                    v0 = gelu_exact(v0); v1 = gelu_exact(v1);
                    *(__half2*)&Ch[off] = __floats2half2_rn(v0, v1);
                }
            }
            if (r1 < Mr) {
                float v2 = acc[mt][nt][2] + b0;
                float v3 = acc[mt][nt][3] + b1;
                size_t off = (size_t)r1 * Nc + cc;
                if (EPI == 1) {
                    v2 += R[off]; v3 += R[off + 1];
                    C[off] = v2; C[off + 1] = v3;
                } else {
                    v2 = gelu_exact(v2); v3 = gelu_exact(v3);
                    *(__half2*)&Ch[off] = __floats2half2_rn(v2, v3);
                }
            }
        }
    }
}

// ---------------- LayerNorm variants ------------------------------------------
__global__ void ln_split_kernel(const float* __restrict__ X,
                                const float* __restrict__ gam,
                                const float* __restrict__ bet,
                                __nv_bfloat16* __restrict__ Hi,
                                __nv_bfloat16* __restrict__ Lo)
{
    int row = blockIdx.x;
    const float* x = X + (size_t)row * D;
    int tid = threadIdx.x;

    float s = 0.f, ss = 0.f;
    for (int i = tid; i < D; i += 256) { float v = x[i]; s += v; ss += v*v; }
    __shared__ float rs[32], rss[32];
    for (int o = 16; o > 0; o >>= 1) {
        s  += __shfl_xor_sync(0xffffffffu, s,  o);
        ss += __shfl_xor_sync(0xffffffffu, ss, o);
    }
    int wid = tid >> 5, lid = tid & 31;
    if (lid == 0) { rs[wid] = s; rss[wid] = ss; }
    __syncthreads();
    __shared__ float s_mean, s_inv;
    if (tid == 0) {
        float ts = 0.f, tss = 0.f;
        for (int w = 0; w < 8; w++) { ts += rs[w]; tss += rss[w]; }
        float mean = ts * (1.f/D);
        float var  = tss * (1.f/D) - mean*mean;
        s_mean = mean; s_inv = rsqrtf(var + LN_EPS);
    }
    __syncthreads();
    float mean = s_mean, inv = s_inv;
    for (int i = tid; i < D; i += 256) {
        float v = (x[i] - mean) * inv * gam[i] + bet[i];
        __nv_bfloat16 h = __float2bfloat16(v);
        Hi[(size_t)row*D + i] = h;
        Lo[(size_t)row*D + i] = __float2bfloat16(v - __bfloat162float(h));
    }
}

__global__ void ln_f16_kernel(const float* __restrict__ X,
                              const float* __restrict__ gam,
                              const float* __restrict__ bet,
                              __half* __restrict__ Y)
{
    int row = blockIdx.x;
    const float* x = X + (size_t)row * D;
    int tid = threadIdx.x;

    float s = 0.f, ss = 0.f;
    for (int i = tid; i < D; i += 256) { float v = x[i]; s += v; ss += v*v; }
    __shared__ float rs[32], rss[32];
    for (int o = 16; o > 0; o >>= 1) {
        s  += __shfl_xor_sync(0xffffffffu, s,  o);
        ss += __shfl_xor_sync(0xffffffffu, ss, o);
    }
    int wid = tid >> 5, lid = tid & 31;
    if (lid == 0) { rs[wid] = s; rss[wid] = ss; }
    __syncthreads();
    __shared__ float s_mean, s_inv;
    if (tid == 0) {
        float ts = 0.f, tss = 0.f;
        for (int w = 0; w < 8; w++) { ts += rs[w]; tss += rss[w]; }
        float mean = ts * (1.f/D);
        float var  = tss * (1.f/D) - mean*mean;
        s_mean = mean; s_inv = rsqrtf(var + LN_EPS);
    }
    __syncthreads();
    float mean = s_mean, inv = s_inv;
    for (int i = tid; i < D; i += 256)
        Y[(size_t)row*D + i] = __float2half((x[i] - mean) * inv * gam[i] + bet[i]);
}

// ---------------- weight transpose variants -----------------------------------
__global__ void tsplit_kernel(const float* __restrict__ W,
                              __nv_bfloat16* __restrict__ Th,
                              __nv_bfloat16* __restrict__ Tl, int K, int N)
{
    __shared__ float t[32][33];
    int n0 = blockIdx.x * 32, k0 = blockIdx.y * 32;
    int tx = threadIdx.x, ty = threadIdx.y;
    for (int i = ty; i < 32; i += 8)
        t[i][tx] = W[(size_t)(k0 + i) * N + n0 + tx];
    __syncthreads();
    for (int r = ty; r < 32; r += 8) {
        float v = t[tx][r];
        __nv_bfloat16 h = __float2bfloat16(v);
        size_t o = (size_t)(n0 + r) * K + k0 + tx;
        Th[o] = h;
        Tl[o] = __float2bfloat16(v - __bfloat162float(h));
    }
}

__global__ void tf16_kernel(const float* __restrict__ W,
                            __half* __restrict__ T, int K, int N)
{
    __shared__ float t[32][33];
    int n0 = blockIdx.x * 32, k0 = blockIdx.y * 32;
    int tx = threadIdx.x, ty = threadIdx.y;
    for (int i = ty; i < 32; i += 8)
        t[i][tx] = W[(size_t)(k0 + i) * N + n0 + tx];
    __syncthreads();
    for (int r = ty; r < 32; r += 8)
        T[(size_t)(n0 + r) * K + k0 + tx] = __float2half(t[tx][r]);
}

// ---------------- attention kernels (fp32 math, bf16 hi/lo out) ---------------
__global__ void attn_cls_kernel(const float* __restrict__ qkv,
                                __nv_bfloat16* __restrict__ Oh,
                                __nv_bfloat16* __restrict__ Ol)
{
    int bh = blockIdx.x;
    int b = bh / H, hh = bh % H;
    int tid = threadIdx.x;

    __shared__ float qs[HD];
    __shared__ float sim[NT];
    __shared__ float red[256];
    __shared__ float red2[4][HD];

    if (tid < HD)
        qs[tid] = qkv[(size_t)(b*NT) * D3 + hh*HD + tid] * QSCALE;
    __syncthreads();

    float lmx = -1e30f;
    for (int j = tid; j < NT; j += 256) {
        const float* kp = qkv + (size_t)(b*NT + j) * D3 + D + hh*HD;
        float s = 0.f;
        #pragma unroll
        for (int d = 0; d < HD; d++) s += qs[d] * kp[d];
        sim[j] = s;
        lmx = fmaxf(lmx, s);
    }
    red[tid] = lmx; __syncthreads();
    for (int st = 128; st > 0; st >>= 1) {
        if (tid < st) red[tid] = fmaxf(red[tid], red[tid+st]);
        __syncthreads();
    }
    float mx = red[0];
    __syncthreads();

    float ls = 0.f;
    for (int j = tid; j < NT; j += 256) {
        float e = __expf(sim[j] - mx);
        sim[j] = e;
        ls += e;
    }
    red[tid] = ls; __syncthreads();
    for (int st = 128; st > 0; st >>= 1) {
        if (tid < st) red[tid] += red[tid+st];
        __syncthreads();
    }
    float linv = 1.f / red[0];
    __syncthreads();

    int d = tid & 63, p = tid >> 6;
    float acc = 0.f;
    for (int j = p; j < NT; j += 4)
        acc += sim[j] * qkv[(size_t)(b*NT + j) * D3 + 2*D + hh*HD + d];
    red2[p][d] = acc;
    __syncthreads();
    if (p == 0) {
        float o = (red2[0][d] + red2[1][d] + red2[2][d] + red2[3][d]) * linv;
        size_t idx = (size_t)(b*NT) * D + hh*HD + d;
        __nv_bfloat16 h = __float2bfloat16(o);
        Oh[idx] = h;
        Ol[idx] = __float2bfloat16(o - __bfloat162float(h));
    }
}

__global__ void attn_time_kernel(const float* __restrict__ qkv,
                                 __nv_bfloat16* __restrict__ Oh,
                                 __nv_bfloat16* __restrict__ Ol)
{
    int qid = blockIdx.x * blockDim.x + threadIdx.x;
    int fr = qid % F;
    int sp = (qid / F) % NS;
    int bh = qid / (F * NS);
    int b = bh / H, hh = bh % H;
    int t = 1 + fr*NS + sp;

    const float4* qp = (const float4*)(qkv + (size_t)(b*NT + t) * D3 + hh*HD);
    float4 q4[16];
    #pragma unroll
    for (int i = 0; i < 16; i++) {
        float4 v = qp[i];
        v.x *= QSCALE; v.y *= QSCALE; v.z *= QSCALE; v.w *= QSCALE;
        q4[i] = v;
    }

    float sim[F+1];
    #pragma unroll
    for (int j = 0; j < F+1; j++) {
        int tk = (j == 0) ? 0 : (1 + (j-1)*NS + sp);
        const float4* kp = (const float4*)(qkv + (size_t)(b*NT + tk) * D3 + D + hh*HD);
        float s = 0.f;
        #pragma unroll
        for (int i = 0; i < 16; i++) {
            float4 kk = kp[i];
            s += q4[i].x*kk.x + q4[i].y*kk.y + q4[i].z*kk.z + q4[i].w*kk.w;
        }
        sim[j] = s;
    }
    float mx = sim[0];
    #pragma unroll
    for (int j = 1; j < F+1; j++) mx = fmaxf(mx, sim[j]);
    float l = 0.f;
    #pragma unroll
    for (int j = 0; j < F+1; j++) { sim[j] = __expf(sim[j] - mx); l += sim[j]; }
    float inv = 1.f / l;

    float4 o4[16];
    #pragma unroll
    for (int i = 0; i < 16; i++) o4[i] = make_float4(0.f,0.f,0.f,0.f);
    #pragma unroll
    for (int j = 0; j < F+1; j++) {
        int tk = (j == 0) ? 0 : (1 + (j-1)*NS + sp);
        const float4* vp = (const float4*)(qkv + (size_t)(b*NT + tk) * D3 + 2*D + hh*HD);
        float p = sim[j] * inv;
        #pragma unroll
        for (int i = 0; i < 16; i++) {
            float4 vv = vp[i];
            o4[i].x += p*vv.x; o4[i].y += p*vv.y; o4[i].z += p*vv.z; o4[i].w += p*vv.w;
        }
    }
    size_t base = (size_t)(b*NT + t) * D + hh*HD;
    __nv_bfloat162* oh = (__nv_bfloat162*)&Oh[base];
    __nv_bfloat162* ol = (__nv_bfloat162*)&Ol[base];
    #pragma unroll
    for (int i = 0; i < 16; i++) {
        __nv_bfloat162 lo0, hi0 = split2(o4[i].x, o4[i].y, lo0);
        __nv_bfloat162 lo1, hi1 = split2(o4[i].z, o4[i].w, lo1);
        oh[2*i] = hi0; oh[2*i+1] = hi1;
        ol[2*i] = lo0; ol[2*i+1] = lo1;
    }
}

__global__ void attn_space_kernel(const float* __restrict__ qkv,
                                  __nv_bfloat16* __restrict__ Oh,
                                  __nv_bfloat16* __restrict__ Ol)
{
    int bx = blockIdx.x;
    int bh = bx / F, fr = bx % F;
    int b = bh / H, hh = bh % H;
    int tid = threadIdx.x;
    int sp = tid;
    const int NK = NS + 1;

    __shared__ float Ks[64 * HD];
    __shared__ float Vs[64 * HD];

    float4 q4[16], o4[16];
    float m = -1e30f, l = 0.f;
    if (sp < NS) {
        const float4* qp = (const float4*)(qkv + (size_t)(b*NT + 1 + fr*NS + sp) * D3 + hh*HD);
        #pragma unroll
        for (int i = 0; i < 16; i++) {
            float4 v = qp[i];
            v.x *= QSCALE; v.y *= QSCALE; v.z *= QSCALE; v.w *= QSCALE;
            q4[i] = v;
            o4[i] = make_float4(0.f,0.f,0.f,0.f);
        }
    }

    for (int t0 = 0; t0 < NK; t0 += 64) {
        __syncthreads();
        for (int e = tid; e < 64*HD; e += 256) {
            int jj = e >> 6, d = e & 63;
            int j = t0 + jj;
            float kv = 0.f, vv = 0.f;
            if (j < NK) {
                int tk = (j == 0) ? 0 : (1 + fr*NS + (j-1));
                size_t base = (size_t)(b*NT + tk) * D3 + hh*HD + d;
                kv = qkv[base + D];
                vv = qkv[base + 2*D];
            }
            Ks[e] = kv; Vs[e] = vv;
        }
        __syncthreads();

        if (sp < NS) {
            int lim = min(64, NK - t0);
            for (int jj = 0; jj < lim; jj++) {
                const float4* kr = (const float4*)&Ks[jj * HD];
                float s = 0.f;
                #pragma unroll
                for (int i = 0; i < 16; i++) {
                    float4 kk = kr[i];
                    s += q4[i].x*kk.x + q4[i].y*kk.y + q4[i].z*kk.z + q4[i].w*kk.w;
                }
                float mn  = fmaxf(m, s);
                float fac = __expf(m - mn);
                float p   = __expf(s - mn);
                l = l * fac + p;
                const float4* vr = (const float4*)&Vs[jj * HD];
                #pragma unroll
                for (int i = 0; i < 16; i++) {
                    float4 vv = vr[i];
                    o4[i].x = o4[i].x*fac + p*vv.x;
                    o4[i].y = o4[i].y*fac + p*vv.y;
                    o4[i].z = o4[i].z*fac + p*vv.z;
                    o4[i].w = o4[i].w*fac + p*vv.w;
                }
                m = mn;
            }
        }
    }

    if (sp < NS) {
        float inv = 1.f / l;
        size_t base = (size_t)(b*NT + 1 + fr*NS + sp) * D + hh*HD;
        __nv_bfloat162* oh = (__nv_bfloat162*)&Oh[base];
        __nv_bfloat162* ol = (__nv_bfloat162*)&Ol[base];
        #pragma unroll
        for (int i = 0; i < 16; i++) {
            __nv_bfloat162 lo0, hi0 = split2(o4[i].x*inv, o4[i].y*inv, lo0);
            __nv_bfloat162 lo1, hi1 = split2(o4[i].z*inv, o4[i].w*inv, lo1);
            oh[2*i] = hi0; oh[2*i+1] = hi1;
            ol[2*i] = lo0; ol[2*i+1] = lo1;
        }
    }
}

// ---------------- host launch ------------------------------------------------
extern "C" void kernel_launch(void* const* d_in, const int* in_sizes, int n_in,
                              void* d_out, int out_size)
{
    const float* x      = (const float*)d_in[0];
    const float* n1g    = (const float*)d_in[1];
    const float* n1b    = (const float*)d_in[2];
    const float* n2g    = (const float*)d_in[3];
    const float* n2b    = (const float*)d_in[4];
    const float* n3g    = (const float*)d_in[5];
    const float* n3b    = (const float*)d_in[6];
    const float* aqkvw  = (const float*)d_in[7];
    const float* aqkvb  = (const float*)d_in[8];
    const float* aprojw = (const float*)d_in[9];
    const float* aprojb = (const float*)d_in[10];
    const float* tqkvw  = (const float*)d_in[11];
    const float* tqkvb  = (const float*)d_in[12];
    const float* tprojw = (const float*)d_in[13];
    const float* tprojb = (const float*)d_in[14];
    const float* fc1w   = (const float*)d_in[15];
    const float* fc1b   = (const float*)d_in[16];
    const float* fc2w   = (const float*)d_in[17];
    const float* fc2b   = (const float*)d_in[18];
    float* out = (float*)d_out;

    __nv_bfloat16 *lnh, *lnl, *atth, *attl;
    __nv_bfloat16 *wth_tqkv, *wtl_tqkv, *wth_aqkv, *wtl_aqkv;
    __nv_bfloat16 *wth_tproj, *wtl_tproj, *wth_aproj, *wtl_aproj;
    __half *wf_fc1, *wf_fc2, *hidf;
    float *bqkv, *btres, *bsres;
    cudaGetSymbolAddress((void**)&lnh,  g_lnh);  cudaGetSymbolAddress((void**)&lnl,  g_lnl);
    cudaGetSymbolAddress((void**)&atth, g_atth); cudaGetSymbolAddress((void**)&attl, g_attl);
    cudaGetSymbolAddress((void**)&hidf, g_hidf);
    cudaGetSymbolAddress((void**)&bqkv, g_qkv);
    cudaGetSymbolAddress((void**)&btres,g_tres); cudaGetSymbolAddress((void**)&bsres,g_sres);
    cudaGetSymbolAddress((void**)&wth_tqkv, g_wth_tqkv); cudaGetSymbolAddress((void**)&wtl_tqkv, g_wtl_tqkv);
    cudaGetSymbolAddress((void**)&wth_aqkv, g_wth_aqkv); cudaGetSymbolAddress((void**)&wtl_aqkv, g_wtl_aqkv);
    cudaGetSymbolAddress((void**)&wth_tproj,g_wth_tproj);cudaGetSymbolAddress((void**)&wtl_tproj,g_wtl_tproj);
    cudaGetSymbolAddress((void**)&wth_aproj,g_wth_aproj);cudaGetSymbolAddress((void**)&wtl_aproj,g_wtl_aproj);
    cudaGetSymbolAddress((void**)&wf_fc1,  g_wf_fc1);    cudaGetSymbolAddress((void**)&wf_fc2,  g_wf_fc2);

    cudaFuncSetAttribute(gemm_bf16x3<0>, cudaFuncAttributeMaxDynamicSharedMemorySize, SMEM_GEMM);
    cudaFuncSetAttribute(gemm_bf16x3<1>, cudaFuncAttributeMaxDynamicSharedMemorySize, SMEM_GEMM);
    cudaFuncSetAttribute(gemm_f16<1>, cudaFuncAttributeMaxDynamicSharedMemorySize, SMEM_F16);
    cudaFuncSetAttribute(gemm_f16<4>, cudaFuncAttributeMaxDynamicSharedMemorySize, SMEM_F16);

    const int MT = (M + BM - 1) / BM;    // 99
    dim3 tb(32, 8);

    // ---- weight transforms ----
    tsplit_kernel<<<dim3(D3/32, D/32), tb>>>(tqkvw, wth_tqkv, wtl_tqkv, D, D3);
    tsplit_kernel<<<dim3(D3/32, D/32), tb>>>(aqkvw, wth_aqkv, wtl_aqkv, D, D3);
    tsplit_kernel<<<dim3(D/32,  D/32), tb>>>(tprojw, wth_tproj, wtl_tproj, D, D);
    tsplit_kernel<<<dim3(D/32,  D/32), tb>>>(aprojw, wth_aproj, wtl_aproj, D, D);
    tf16_kernel<<<dim3(D4/32, D/32), tb>>>(fc1w, wf_fc1, D, D4);
    tf16_kernel<<<dim3(D/32, D4/32), tb>>>(fc2w, wf_fc2, D4, D);

    const int nTimeBlocks = (B*H*NS*F) / 256;   // 588

    // ---- time attention branch ----
    ln_split_kernel<<<M, 256>>>(x, n3g, n3b, lnh, lnl);
    gemm_bf16x3<0><<<dim3(D3/BN, MT), 256, SMEM_GEMM>>>(lnh, lnl, wth_tqkv, wtl_tqkv, tqkvb, nullptr, bqkv, M, D, D3);
    attn_cls_kernel <<<B*H, 256>>>(bqkv, atth, attl);
    attn_time_kernel<<<nTimeBlocks, 256>>>(bqkv, atth, attl);
    gemm_bf16x3<1><<<dim3(D/BN, MT), 256, SMEM_GEMM>>>(atth, attl, wth_tproj, wtl_tproj, tprojb, x, btres, M, D, D);

    // ---- space attention branch ----
    ln_split_kernel<<<M, 256>>>(btres, n1g, n1b, lnh, lnl);
    gemm_bf16x3<0><<<dim3(D3/BN, MT), 256, SMEM_GEMM>>>(lnh, lnl, wth_aqkv, wtl_aqkv, aqkvb, nullptr, bqkv, M, D, D3);
    attn_cls_kernel  <<<B*H, 256>>>(bqkv, atth, attl);
    attn_space_kernel<<<B*H*F, 256>>>(bqkv, atth, attl);
    gemm_bf16x3<1><<<dim3(D/BN, MT), 256, SMEM_GEMM>>>(atth, attl, wth_aproj, wtl_aproj, aprojb, x, bsres, M, D, D);

    // ---- MLP (fp16 single-pass) ----
    ln_f16_kernel<<<M, 256>>>(bsres, n2g, n2b, (__half*)lnh);
    gemm_f16<4><<<dim3(D4/BN, MT), 256, SMEM_F16>>>((const __half*)lnh, wf_fc1, fc1b, nullptr, nullptr, hidf, M, D, D4);
    gemm_f16<1><<<dim3(D/BN, MT), 256, SMEM_F16>>>(hidf, wf_fc2, fc2b, bsres, out, nullptr, M, D4, D);
}

// round 9
// speedup vs baseline: 3.4774x; 1.3786x over previous
#include <cuda_runtime.h>
#include <cuda_fp16.h>
#include <math.h>
#include <cstdint>

// ---------------- problem constants ----------------------------------------
constexpr int B   = 8;
constexpr int F   = 8;
constexpr int NS  = 196;
constexpr int NT  = 1 + F*NS;   // 1569
constexpr int D   = 768;
constexpr int H   = 12;
constexpr int HD  = 64;
constexpr int D3  = 3*D;        // 2304
constexpr int D4  = 4*D;        // 3072
constexpr int M   = B*NT;       // 12552
constexpr float LN_EPS = 1e-5f;
constexpr float QSCALE = 0.125f;

// ---------------- scratch (device globals; no allocation) ------------------
__device__ __half g_lnf [(size_t)M * D];
__device__ float  g_qkv [(size_t)M * D3];
__device__ __half g_attf[(size_t)M * D];
__device__ float  g_tres[(size_t)M * D];
__device__ float  g_sres[(size_t)M * D];
__device__ __half g_hidf[(size_t)M * D4];
// transposed fp16 weights: Wt[n][k] = W[k][n]
__device__ __half g_wf_tqkv [(size_t)D3*D];
__device__ __half g_wf_aqkv [(size_t)D3*D];
__device__ __half g_wf_tproj[(size_t)D*D];
__device__ __half g_wf_aproj[(size_t)D*D];
__device__ __half g_wf_fc1  [(size_t)D4*D];
__device__ __half g_wf_fc2  [(size_t)D*D4];

// ---------------- helpers ----------------------------------------------------
__device__ __forceinline__ uint32_t smem_to_u32(const void* p) {
    uint32_t a;
    asm("{ .reg .u64 t; cvta.to.shared.u64 t, %1; cvt.u32.u64 %0, t; }"
        : "=r"(a) : "l"(p));
    return a;
}
__device__ __forceinline__ void cp_async16(uint32_t dst, const void* src, bool valid) {
    int sz = valid ? 16 : 0;
    asm volatile("cp.async.cg.shared.global [%0], [%1], 16, %2;"
                 :: "r"(dst), "l"(src), "r"(sz) : "memory");
}
#define CP_COMMIT()  asm volatile("cp.async.commit_group;" ::: "memory")
#define CP_WAIT(n)   asm volatile("cp.async.wait_group %0;" :: "n"(n) : "memory")

__device__ __forceinline__ void ldsm_x4(uint32_t& r0, uint32_t& r1, uint32_t& r2, uint32_t& r3, uint32_t addr) {
    asm volatile("ldmatrix.sync.aligned.m8n8.x4.shared.b16 {%0,%1,%2,%3}, [%4];"
                 : "=r"(r0), "=r"(r1), "=r"(r2), "=r"(r3) : "r"(addr));
}
__device__ __forceinline__ void mma_f16(float* c, const uint32_t* a, const uint32_t* b) {
    asm volatile(
        "mma.sync.aligned.m16n8k16.row.col.f32.f16.f16.f32 "
        "{%0,%1,%2,%3}, {%4,%5,%6,%7}, {%8,%9}, {%0,%1,%2,%3};"
        : "+f"(c[0]), "+f"(c[1]), "+f"(c[2]), "+f"(c[3])
        : "r"(a[0]), "r"(a[1]), "r"(a[2]), "r"(a[3]), "r"(b[0]), "r"(b[1]));
}
__device__ __forceinline__ float gelu_exact(float v) {
    return 0.5f * v * (1.f + erff(v * 0.70710678118654752f));
}

// ================= fp16 single-pass GEMM ======================================
// C[M][N] = A[M][K] @ Wt[N][K]^T
// CTA 128x128, BK=64, 4-stage cp.async pipeline, 8 warps in 2x4 of 64x32.
constexpr int BM = 128, BN = 128, FBK = 64;
constexpr int FRSB = 144;               // 128B data + 16B pad
constexpr int FMAT = 128 * FRSB;        // 18432
constexpr int FSTAGE = 2 * FMAT;        // 36864
constexpr int SMEM_F16 = 4 * FSTAGE;    // 147456

// EPI: 0 = bias -> fp32 C ; 1 = bias+residual -> fp32 C ; 4 = bias+GELU -> fp16 Ch
template<int EPI>
__global__ void __launch_bounds__(256, 1)
gemm_f16(const __half* __restrict__ A, const __half* __restrict__ Bw,
         const float* __restrict__ bias, const float* __restrict__ R,
         float* __restrict__ C, __half* __restrict__ Ch,
         int Mr, int K, int Nc)
{
    extern __shared__ char smem[];
    const uint32_t sb = smem_to_u32(smem);
    const int tid = threadIdx.x;
    const int wid = tid >> 5, lane = tid & 31;
    const int wm = wid & 1, wn = wid >> 1;
    const int bm = blockIdx.y * BM, bn = blockIdx.x * BN;

    float acc[4][4][4];
    #pragma unroll
    for (int i = 0; i < 4; i++)
        #pragma unroll
        for (int j = 0; j < 4; j++)
            #pragma unroll
            for (int q = 0; q < 4; q++) acc[i][j][q] = 0.f;

    auto load_stage = [&](int stage, int k0) {
        uint32_t base = sb + stage * FSTAGE;
        #pragma unroll
        for (int i = 0; i < 4; i++) {
            int idx = tid + i*256;
            int r = idx >> 3, cb = (idx & 7) << 4;
            int gr = bm + r;
            bool v = gr < Mr;
            cp_async16(base + r*FRSB + cb, (const char*)(A + (size_t)(v?gr:0)*K + k0) + cb, v);
        }
        #pragma unroll
        for (int i = 0; i < 4; i++) {
            int idx = tid + i*256;
            int r = idx >> 3, cb = (idx & 7) << 4;
            cp_async16(base + FMAT + r*FRSB + cb, (const char*)(Bw + (size_t)(bn + r)*K + k0) + cb, true);
        }
        CP_COMMIT();
    };

    const int NC = K / FBK;
    load_stage(0, 0);
    load_stage(1, FBK);
    load_stage(2, 2*FBK);

    const int aRow = (lane & 15);
    const int aColB = (lane >> 4) * 16;
    const int bMtx = lane >> 3, bRit = lane & 7;
    const int bNrow = (bMtx & 2) ? (8 + bRit) : bRit;
    const int bKoff = (bMtx & 1) * 16;

    for (int c = 0; c < NC; c++) {
        CP_WAIT(2);
        __syncthreads();
        if (c + 3 < NC) load_stage((c + 3) & 3, (c + 3) * FBK);

        uint32_t aB = sb + (c & 3) * FSTAGE;
        uint32_t bB = aB + FMAT;

        #pragma unroll
        for (int kk = 0; kk < 4; kk++) {
            uint32_t af[4][4], bf[4][2];
            #pragma unroll
            for (int mt = 0; mt < 4; mt++) {
                uint32_t off = (uint32_t)((wm*64 + mt*16 + aRow) * FRSB + kk*32 + aColB);
                ldsm_x4(af[mt][0], af[mt][1], af[mt][2], af[mt][3], aB + off);
            }
            #pragma unroll
            for (int np = 0; np < 2; np++) {
                uint32_t off = (uint32_t)((wn*32 + np*16 + bNrow) * FRSB + kk*32 + bKoff);
                ldsm_x4(bf[2*np][0], bf[2*np][1], bf[2*np+1][0], bf[2*np+1][1], bB + off);
            }
            #pragma unroll
            for (int mt = 0; mt < 4; mt++)
                #pragma unroll
                for (int nt = 0; nt < 4; nt++)
                    mma_f16(acc[mt][nt], af[mt], bf[nt]);
        }
    }

    const int er = lane >> 2, ec = (lane & 3) * 2;
    #pragma unroll
    for (int mt = 0; mt < 4; mt++) {
        int r0 = bm + wm*64 + mt*16 + er;
        int r1 = r0 + 8;
        #pragma unroll
        for (int nt = 0; nt < 4; nt++) {
            int cc = bn + wn*32 + nt*8 + ec;
            float b0 = bias[cc], b1 = bias[cc + 1];
            if (r0 < Mr) {
                float v0 = acc[mt][nt][0] + b0;
                float v1 = acc[mt][nt][1] + b1;
                size_t off = (size_t)r0 * Nc + cc;
                if (EPI == 0) {
                    C[off] = v0; C[off + 1] = v1;
                } else if (EPI == 1) {
                    C[off] = v0 + R[off]; C[off + 1] = v1 + R[off + 1];
                } else {
                    *(__half2*)&Ch[off] = __floats2half2_rn(gelu_exact(v0), gelu_exact(v1));
                }
            }
            if (r1 < Mr) {
                float v2 = acc[mt][nt][2] + b0;
                float v3 = acc[mt][nt][3] + b1;
                size_t off = (size_t)r1 * Nc + cc;
                if (EPI == 0) {
                    C[off] = v2; C[off + 1] = v3;
                } else if (EPI == 1) {
                    C[off] = v2 + R[off]; C[off + 1] = v3 + R[off + 1];
                } else {
                    *(__half2*)&Ch[off] = __floats2half2_rn(gelu_exact(v2), gelu_exact(v3));
                }
            }
        }
    }
}

// ---------------- LayerNorm -> fp16 -------------------------------------------
__global__ void ln_f16_kernel(const float* __restrict__ X,
                              const float* __restrict__ gam,
                              const float* __restrict__ bet,
                              __half* __restrict__ Y)
{
    int row = blockIdx.x;
    const float* x = X + (size_t)row * D;
    int tid = threadIdx.x;

    float s = 0.f, ss = 0.f;
    for (int i = tid; i < D; i += 256) { float v = x[i]; s += v; ss += v*v; }
    __shared__ float rs[32], rss[32];
    for (int o = 16; o > 0; o >>= 1) {
        s  += __shfl_xor_sync(0xffffffffu, s,  o);
        ss += __shfl_xor_sync(0xffffffffu, ss, o);
    }
    int wid = tid >> 5, lid = tid & 31;
    if (lid == 0) { rs[wid] = s; rss[wid] = ss; }
    __syncthreads();
    __shared__ float s_mean, s_inv;
    if (tid == 0) {
        float ts = 0.f, tss = 0.f;
        for (int w = 0; w < 8; w++) { ts += rs[w]; tss += rss[w]; }
        float mean = ts * (1.f/D);
        float var  = tss * (1.f/D) - mean*mean;
        s_mean = mean; s_inv = rsqrtf(var + LN_EPS);
    }
    __syncthreads();
    float mean = s_mean, inv = s_inv;
    for (int i = tid; i < D; i += 256)
        Y[(size_t)row*D + i] = __float2half((x[i] - mean) * inv * gam[i] + bet[i]);
}

// ---------------- weight transpose -> fp16 -------------------------------------
__global__ void tf16_kernel(const float* __restrict__ W,
                            __half* __restrict__ T, int K, int N)
{
    __shared__ float t[32][33];
    int n0 = blockIdx.x * 32, k0 = blockIdx.y * 32;
    int tx = threadIdx.x, ty = threadIdx.y;
    for (int i = ty; i < 32; i += 8)
        t[i][tx] = W[(size_t)(k0 + i) * N + n0 + tx];
    __syncthreads();
    for (int r = ty; r < 32; r += 8)
        T[(size_t)(n0 + r) * K + k0 + tx] = __float2half(t[tx][r]);
}

// ---------------- attention kernels (fp32 math, fp16 out) ----------------------
__global__ void attn_cls_kernel(const float* __restrict__ qkv,
                                __half* __restrict__ O)
{
    int bh = blockIdx.x;
    int b = bh / H, hh = bh % H;
    int tid = threadIdx.x;

    __shared__ float qs[HD];
    __shared__ float sim[NT];
    __shared__ float red[256];
    __shared__ float red2[4][HD];

    if (tid < HD)
        qs[tid] = qkv[(size_t)(b*NT) * D3 + hh*HD + tid] * QSCALE;
    __syncthreads();

    float lmx = -1e30f;
    for (int j = tid; j < NT; j += 256) {
        const float* kp = qkv + (size_t)(b*NT + j) * D3 + D + hh*HD;
        float s = 0.f;
        #pragma unroll
        for (int d = 0; d < HD; d++) s += qs[d] * kp[d];
        sim[j] = s;
        lmx = fmaxf(lmx, s);
    }
    red[tid] = lmx; __syncthreads();
    for (int st = 128; st > 0; st >>= 1) {
        if (tid < st) red[tid] = fmaxf(red[tid], red[tid+st]);
        __syncthreads();
    }
    float mx = red[0];
    __syncthreads();

    float ls = 0.f;
    for (int j = tid; j < NT; j += 256) {
        float e = __expf(sim[j] - mx);
        sim[j] = e;
        ls += e;
    }
    red[tid] = ls; __syncthreads();
    for (int st = 128; st > 0; st >>= 1) {
        if (tid < st) red[tid] += red[tid+st];
        __syncthreads();
    }
    float linv = 1.f / red[0];
    __syncthreads();

    int d = tid & 63, p = tid >> 6;
    float acc = 0.f;
    for (int j = p; j < NT; j += 4)
        acc += sim[j] * qkv[(size_t)(b*NT + j) * D3 + 2*D + hh*HD + d];
    red2[p][d] = acc;
    __syncthreads();
    if (p == 0) {
        float o = (red2[0][d] + red2[1][d] + red2[2][d] + red2[3][d]) * linv;
        O[(size_t)(b*NT) * D + hh*HD + d] = __float2half(o);
    }
}

__global__ void attn_time_kernel(const float* __restrict__ qkv,
                                 __half* __restrict__ O)
{
    int qid = blockIdx.x * blockDim.x + threadIdx.x;
    int fr = qid % F;
    int sp = (qid / F) % NS;
    int bh = qid / (F * NS);
    int b = bh / H, hh = bh % H;
    int t = 1 + fr*NS + sp;

    const float4* qp = (const float4*)(qkv + (size_t)(b*NT + t) * D3 + hh*HD);
    float4 q4[16];
    #pragma unroll
    for (int i = 0; i < 16; i++) {
        float4 v = qp[i];
        v.x *= QSCALE; v.y *= QSCALE; v.z *= QSCALE; v.w *= QSCALE;
        q4[i] = v;
    }

    float sim[F+1];
    #pragma unroll
    for (int j = 0; j < F+1; j++) {
        int tk = (j == 0) ? 0 : (1 + (j-1)*NS + sp);
        const float4* kp = (const float4*)(qkv + (size_t)(b*NT + tk) * D3 + D + hh*HD);
        float s = 0.f;
        #pragma unroll
        for (int i = 0; i < 16; i++) {
            float4 kk = kp[i];
            s += q4[i].x*kk.x + q4[i].y*kk.y + q4[i].z*kk.z + q4[i].w*kk.w;
        }
        sim[j] = s;
    }
    float mx = sim[0];
    #pragma unroll
    for (int j = 1; j < F+1; j++) mx = fmaxf(mx, sim[j]);
    float l = 0.f;
    #pragma unroll
    for (int j = 0; j < F+1; j++) { sim[j] = __expf(sim[j] - mx); l += sim[j]; }
    float inv = 1.f / l;

    float4 o4[16];
    #pragma unroll
    for (int i = 0; i < 16; i++) o4[i] = make_float4(0.f,0.f,0.f,0.f);
    #pragma unroll
    for (int j = 0; j < F+1; j++) {
        int tk = (j == 0) ? 0 : (1 + (j-1)*NS + sp);
        const float4* vp = (const float4*)(qkv + (size_t)(b*NT + tk) * D3 + 2*D + hh*HD);
        float p = sim[j] * inv;
        #pragma unroll
        for (int i = 0; i < 16; i++) {
            float4 vv = vp[i];
            o4[i].x += p*vv.x; o4[i].y += p*vv.y; o4[i].z += p*vv.z; o4[i].w += p*vv.w;
        }
    }
    __half2* op = (__half2*)(O + (size_t)(b*NT + t) * D + hh*HD);
    #pragma unroll
    for (int i = 0; i < 16; i++) {
        op[2*i]   = __floats2half2_rn(o4[i].x, o4[i].y);
        op[2*i+1] = __floats2half2_rn(o4[i].z, o4[i].w);
    }
}

__global__ void attn_space_kernel(const float* __restrict__ qkv,
                                  __half* __restrict__ O)
{
    int bx = blockIdx.x;
    int bh = bx / F, fr = bx % F;
    int b = bh / H, hh = bh % H;
    int tid = threadIdx.x;
    int sp = tid;
    const int NK = NS + 1;

    __shared__ float Ks[64 * HD];
    __shared__ float Vs[64 * HD];

    float4 q4[16], o4[16];
    float m = -1e30f, l = 0.f;
    if (sp < NS) {
        const float4* qp = (const float4*)(qkv + (size_t)(b*NT + 1 + fr*NS + sp) * D3 + hh*HD);
        #pragma unroll
        for (int i = 0; i < 16; i++) {
            float4 v = qp[i];
            v.x *= QSCALE; v.y *= QSCALE; v.z *= QSCALE; v.w *= QSCALE;
            q4[i] = v;
            o4[i] = make_float4(0.f,0.f,0.f,0.f);
        }
    }

    for (int t0 = 0; t0 < NK; t0 += 64) {
        __syncthreads();
        for (int e = tid; e < 64*HD; e += 256) {
            int jj = e >> 6, d = e & 63;
            int j = t0 + jj;
            float kv = 0.f, vv = 0.f;
            if (j < NK) {
                int tk = (j == 0) ? 0 : (1 + fr*NS + (j-1));
                size_t base = (size_t)(b*NT + tk) * D3 + hh*HD + d;
                kv = qkv[base + D];
                vv = qkv[base + 2*D];
            }
            Ks[e] = kv; Vs[e] = vv;
        }
        __syncthreads();

        if (sp < NS) {
            int lim = min(64, NK - t0);
            for (int jj = 0; jj < lim; jj++) {
                const float4* kr = (const float4*)&Ks[jj * HD];
                float s = 0.f;
                #pragma unroll
                for (int i = 0; i < 16; i++) {
                    float4 kk = kr[i];
                    s += q4[i].x*kk.x + q4[i].y*kk.y + q4[i].z*kk.z + q4[i].w*kk.w;
                }
                float mn  = fmaxf(m, s);
                float fac = __expf(m - mn);
                float p   = __expf(s - mn);
                l = l * fac + p;
                const float4* vr = (const float4*)&Vs[jj * HD];
                #pragma unroll
                for (int i = 0; i < 16; i++) {
                    float4 vv = vr[i];
                    o4[i].x = o4[i].x*fac + p*vv.x;
                    o4[i].y = o4[i].y*fac + p*vv.y;
                    o4[i].z = o4[i].z*fac + p*vv.z;
                    o4[i].w = o4[i].w*fac + p*vv.w;
                }
                m = mn;
            }
        }
    }

    if (sp < NS) {
        float inv = 1.f / l;
        __half2* op = (__half2*)(O + (size_t)(b*NT + 1 + fr*NS + sp) * D + hh*HD);
        #pragma unroll
        for (int i = 0; i < 16; i++) {
            op[2*i]   = __floats2half2_rn(o4[i].x*inv, o4[i].y*inv);
            op[2*i+1] = __floats2half2_rn(o4[i].z*inv, o4[i].w*inv);
        }
    }
}

// ---------------- host launch ------------------------------------------------
extern "C" void kernel_launch(void* const* d_in, const int* in_sizes, int n_in,
                              void* d_out, int out_size)
{
    const float* x      = (const float*)d_in[0];
    const float* n1g    = (const float*)d_in[1];
    const float* n1b    = (const float*)d_in[2];
    const float* n2g    = (const float*)d_in[3];
    const float* n2b    = (const float*)d_in[4];
    const float* n3g    = (const float*)d_in[5];
    const float* n3b    = (const float*)d_in[6];
    const float* aqkvw  = (const float*)d_in[7];
    const float* aqkvb  = (const float*)d_in[8];
    const float* aprojw = (const float*)d_in[9];
    const float* aprojb = (const float*)d_in[10];
    const float* tqkvw  = (const float*)d_in[11];
    const float* tqkvb  = (const float*)d_in[12];
    const float* tprojw = (const float*)d_in[13];
    const float* tprojb = (const float*)d_in[14];
    const float* fc1w   = (const float*)d_in[15];
    const float* fc1b   = (const float*)d_in[16];
    const float* fc2w   = (const float*)d_in[17];
    const float* fc2b   = (const float*)d_in[18];
    float* out = (float*)d_out;

    __half *lnf, *attf, *hidf;
    __half *wf_tqkv, *wf_aqkv, *wf_tproj, *wf_aproj, *wf_fc1, *wf_fc2;
    float *bqkv, *btres, *bsres;
    cudaGetSymbolAddress((void**)&lnf,  g_lnf);
    cudaGetSymbolAddress((void**)&attf, g_attf);
    cudaGetSymbolAddress((void**)&hidf, g_hidf);
    cudaGetSymbolAddress((void**)&bqkv, g_qkv);
    cudaGetSymbolAddress((void**)&btres,g_tres);
    cudaGetSymbolAddress((void**)&bsres,g_sres);
    cudaGetSymbolAddress((void**)&wf_tqkv, g_wf_tqkv);
    cudaGetSymbolAddress((void**)&wf_aqkv, g_wf_aqkv);
    cudaGetSymbolAddress((void**)&wf_tproj,g_wf_tproj);
    cudaGetSymbolAddress((void**)&wf_aproj,g_wf_aproj);
    cudaGetSymbolAddress((void**)&wf_fc1,  g_wf_fc1);
    cudaGetSymbolAddress((void**)&wf_fc2,  g_wf_fc2);

    cudaFuncSetAttribute(gemm_f16<0>, cudaFuncAttributeMaxDynamicSharedMemorySize, SMEM_F16);
    cudaFuncSetAttribute(gemm_f16<1>, cudaFuncAttributeMaxDynamicSharedMemorySize, SMEM_F16);
    cudaFuncSetAttribute(gemm_f16<4>, cudaFuncAttributeMaxDynamicSharedMemorySize, SMEM_F16);

    const int MT = (M + BM - 1) / BM;    // 99
    dim3 tb(32, 8);

    // ---- weight transforms (fp16 transpose) ----
    tf16_kernel<<<dim3(D3/32, D/32), tb>>>(tqkvw, wf_tqkv, D, D3);
    tf16_kernel<<<dim3(D3/32, D/32), tb>>>(aqkvw, wf_aqkv, D, D3);
    tf16_kernel<<<dim3(D/32,  D/32), tb>>>(tprojw, wf_tproj, D, D);
    tf16_kernel<<<dim3(D/32,  D/32), tb>>>(aprojw, wf_aproj, D, D);
    tf16_kernel<<<dim3(D4/32, D/32), tb>>>(fc1w, wf_fc1, D, D4);
    tf16_kernel<<<dim3(D/32, D4/32), tb>>>(fc2w, wf_fc2, D4, D);

    const int nTimeBlocks = (B*H*NS*F) / 256;   // 588

    // ---- time attention branch ----
    ln_f16_kernel<<<M, 256>>>(x, n3g, n3b, lnf);
    gemm_f16<0><<<dim3(D3/BN, MT), 256, SMEM_F16>>>(lnf, wf_tqkv, tqkvb, nullptr, bqkv, nullptr, M, D, D3);
    attn_cls_kernel <<<B*H, 256>>>(bqkv, attf);
    attn_time_kernel<<<nTimeBlocks, 256>>>(bqkv, attf);
    gemm_f16<1><<<dim3(D/BN, MT), 256, SMEM_F16>>>(attf, wf_tproj, tprojb, x, btres, nullptr, M, D, D);

    // ---- space attention branch ----
    ln_f16_kernel<<<M, 256>>>(btres, n1g, n1b, lnf);
    gemm_f16<0><<<dim3(D3/BN, MT), 256, SMEM_F16>>>(lnf, wf_aqkv, aqkvb, nullptr, bqkv, nullptr, M, D, D3);
    attn_cls_kernel  <<<B*H, 256>>>(bqkv, attf);
    attn_space_kernel<<<B*H*F, 256>>>(bqkv, attf);
    gemm_f16<1><<<dim3(D/BN, MT), 256, SMEM_F16>>>(attf, wf_aproj, aprojb, x, bsres, nullptr, M, D, D);

    // ---- MLP ----
    ln_f16_kernel<<<M, 256>>>(bsres, n2g, n2b, lnf);
    gemm_f16<4><<<dim3(D4/BN, MT), 256, SMEM_F16>>>(lnf, wf_fc1, fc1b, nullptr, nullptr, hidf, M, D, D4);
    gemm_f16<1><<<dim3(D/BN, MT), 256, SMEM_F16>>>(hidf, wf_fc2, fc2b, bsres, out, nullptr, M, D4, D);
}

// round 10
// speedup vs baseline: 3.5066x; 1.0084x over previous
#include <cuda_runtime.h>
#include <cuda_fp16.h>
#include <math.h>
#include <cstdint>

// ---------------- problem constants ----------------------------------------
constexpr int B   = 8;
constexpr int F   = 8;
constexpr int NS  = 196;
constexpr int NT  = 1 + F*NS;   // 1569
constexpr int D   = 768;
constexpr int H   = 12;
constexpr int HD  = 64;
constexpr int D3  = 3*D;        // 2304
constexpr int D4  = 4*D;        // 3072
constexpr int M   = B*NT;       // 12552
constexpr float LN_EPS = 1e-5f;
constexpr float QSCALE = 0.125f;

// ---------------- scratch (device globals; no allocation) ------------------
__device__ __half g_lnf [(size_t)M * D];
__device__ __half g_qkvh[(size_t)M * D3];
__device__ __half g_attf[(size_t)M * D];
__device__ float  g_tres[(size_t)M * D];
__device__ float  g_sres[(size_t)M * D];
__device__ __half g_hidf[(size_t)M * D4];
// transposed fp16 weights: Wt[n][k] = W[k][n]
__device__ __half g_wf_tqkv [(size_t)D3*D];
__device__ __half g_wf_aqkv [(size_t)D3*D];
__device__ __half g_wf_tproj[(size_t)D*D];
__device__ __half g_wf_aproj[(size_t)D*D];
__device__ __half g_wf_fc1  [(size_t)D4*D];
__device__ __half g_wf_fc2  [(size_t)D*D4];

// ---------------- helpers ----------------------------------------------------
__device__ __forceinline__ uint32_t smem_to_u32(const void* p) {
    uint32_t a;
    asm("{ .reg .u64 t; cvta.to.shared.u64 t, %1; cvt.u32.u64 %0, t; }"
        : "=r"(a) : "l"(p));
    return a;
}
__device__ __forceinline__ void cp_async16(uint32_t dst, const void* src, bool valid) {
    int sz = valid ? 16 : 0;
    asm volatile("cp.async.cg.shared.global [%0], [%1], 16, %2;"
                 :: "r"(dst), "l"(src), "r"(sz) : "memory");
}
#define CP_COMMIT()  asm volatile("cp.async.commit_group;" ::: "memory")
#define CP_WAIT(n)   asm volatile("cp.async.wait_group %0;" :: "n"(n) : "memory")

__device__ __forceinline__ void ldsm_x4(uint32_t& r0, uint32_t& r1, uint32_t& r2, uint32_t& r3, uint32_t addr) {
    asm volatile("ldmatrix.sync.aligned.m8n8.x4.shared.b16 {%0,%1,%2,%3}, [%4];"
                 : "=r"(r0), "=r"(r1), "=r"(r2), "=r"(r3) : "r"(addr));
}
__device__ __forceinline__ void mma_f16(float* c, const uint32_t* a, const uint32_t* b) {
    asm volatile(
        "mma.sync.aligned.m16n8k16.row.col.f32.f16.f16.f32 "
        "{%0,%1,%2,%3}, {%4,%5,%6,%7}, {%8,%9}, {%0,%1,%2,%3};"
        : "+f"(c[0]), "+f"(c[1]), "+f"(c[2]), "+f"(c[3])
        : "r"(a[0]), "r"(a[1]), "r"(a[2]), "r"(a[3]), "r"(b[0]), "r"(b[1]));
}
__device__ __forceinline__ float gelu_exact(float v) {
    return 0.5f * v * (1.f + erff(v * 0.70710678118654752f));
}
// unpack a uint4 holding 8 fp16 into 8 floats at dst
__device__ __forceinline__ void unpack8(const uint4& u, float* dst) {
    const __half2* h = (const __half2*)&u;
    #pragma unroll
    for (int j = 0; j < 4; j++) {
        float2 f = __half22float2(h[j]);
        dst[2*j]   = f.x;
        dst[2*j+1] = f.y;
    }
}
// load 64 fp16 from 128B-aligned gmem into float[64]
__device__ __forceinline__ void load64h(const __half* p, float* dst) {
    const uint4* u = (const uint4*)p;
    #pragma unroll
    for (int i = 0; i < 8; i++) {
        uint4 v = u[i];
        unpack8(v, dst + 8*i);
    }
}

// ================= fp16 single-pass GEMM ======================================
constexpr int BM = 128, BN = 128, FBK = 64;
constexpr int FRSB = 144;               // 128B data + 16B pad
constexpr int FMAT = 128 * FRSB;        // 18432
constexpr int FSTAGE = 2 * FMAT;        // 36864
constexpr int SMEM_F16 = 4 * FSTAGE;    // 147456

// EPI: 1 = bias+residual -> fp32 C ; 4 = bias+GELU -> fp16 Ch ; 5 = bias -> fp16 Ch
template<int EPI>
__global__ void __launch_bounds__(256, 1)
gemm_f16(const __half* __restrict__ A, const __half* __restrict__ Bw,
         const float* __restrict__ bias, const float* __restrict__ R,
         float* __restrict__ C, __half* __restrict__ Ch,
         int Mr, int K, int Nc)
{
    extern __shared__ char smem[];
    const uint32_t sb = smem_to_u32(smem);
    const int tid = threadIdx.x;
    const int wid = tid >> 5, lane = tid & 31;
    const int wm = wid & 1, wn = wid >> 1;
    const int bm = blockIdx.y * BM, bn = blockIdx.x * BN;

    float acc[4][4][4];
    #pragma unroll
    for (int i = 0; i < 4; i++)
        #pragma unroll
        for (int j = 0; j < 4; j++)
            #pragma unroll
            for (int q = 0; q < 4; q++) acc[i][j][q] = 0.f;

    auto load_stage = [&](int stage, int k0) {
        uint32_t base = sb + stage * FSTAGE;
        #pragma unroll
        for (int i = 0; i < 4; i++) {
            int idx = tid + i*256;
            int r = idx >> 3, cb = (idx & 7) << 4;
            int gr = bm + r;
            bool v = gr < Mr;
            cp_async16(base + r*FRSB + cb, (const char*)(A + (size_t)(v?gr:0)*K + k0) + cb, v);
        }
        #pragma unroll
        for (int i = 0; i < 4; i++) {
            int idx = tid + i*256;
            int r = idx >> 3, cb = (idx & 7) << 4;
            cp_async16(base + FMAT + r*FRSB + cb, (const char*)(Bw + (size_t)(bn + r)*K + k0) + cb, true);
        }
        CP_COMMIT();
    };

    const int NC = K / FBK;
    load_stage(0, 0);
    load_stage(1, FBK);
    load_stage(2, 2*FBK);

    const int aRow = (lane & 15);
    const int aColB = (lane >> 4) * 16;
    const int bMtx = lane >> 3, bRit = lane & 7;
    const int bNrow = (bMtx & 2) ? (8 + bRit) : bRit;
    const int bKoff = (bMtx & 1) * 16;

    for (int c = 0; c < NC; c++) {
        CP_WAIT(2);
        __syncthreads();
        if (c + 3 < NC) load_stage((c + 3) & 3, (c + 3) * FBK);

        uint32_t aB = sb + (c & 3) * FSTAGE;
        uint32_t bB = aB + FMAT;

        #pragma unroll
        for (int kk = 0; kk < 4; kk++) {
            uint32_t af[4][4], bf[4][2];
            #pragma unroll
            for (int mt = 0; mt < 4; mt++) {
                uint32_t off = (uint32_t)((wm*64 + mt*16 + aRow) * FRSB + kk*32 + aColB);
                ldsm_x4(af[mt][0], af[mt][1], af[mt][2], af[mt][3], aB + off);
            }
            #pragma unroll
            for (int np = 0; np < 2; np++) {
                uint32_t off = (uint32_t)((wn*32 + np*16 + bNrow) * FRSB + kk*32 + bKoff);
                ldsm_x4(bf[2*np][0], bf[2*np][1], bf[2*np+1][0], bf[2*np+1][1], bB + off);
            }
            #pragma unroll
            for (int mt = 0; mt < 4; mt++)
                #pragma unroll
                for (int nt = 0; nt < 4; nt++)
                    mma_f16(acc[mt][nt], af[mt], bf[nt]);
        }
    }

    const int er = lane >> 2, ec = (lane & 3) * 2;
    #pragma unroll
    for (int mt = 0; mt < 4; mt++) {
        int r0 = bm + wm*64 + mt*16 + er;
        int r1 = r0 + 8;
        #pragma unroll
        for (int nt = 0; nt < 4; nt++) {
            int cc = bn + wn*32 + nt*8 + ec;
            float b0 = bias[cc], b1 = bias[cc + 1];
            if (r0 < Mr) {
                float v0 = acc[mt][nt][0] + b0;
                float v1 = acc[mt][nt][1] + b1;
                size_t off = (size_t)r0 * Nc + cc;
                if (EPI == 1) {
                    C[off] = v0 + R[off]; C[off + 1] = v1 + R[off + 1];
                } else if (EPI == 4) {
                    *(__half2*)&Ch[off] = __floats2half2_rn(gelu_exact(v0), gelu_exact(v1));
                } else {
                    *(__half2*)&Ch[off] = __floats2half2_rn(v0, v1);
                }
            }
            if (r1 < Mr) {
                float v2 = acc[mt][nt][2] + b0;
                float v3 = acc[mt][nt][3] + b1;
                size_t off = (size_t)r1 * Nc + cc;
                if (EPI == 1) {
                    C[off] = v2 + R[off]; C[off + 1] = v3 + R[off + 1];
                } else if (EPI == 4) {
                    *(__half2*)&Ch[off] = __floats2half2_rn(gelu_exact(v2), gelu_exact(v3));
                } else {
                    *(__half2*)&Ch[off] = __floats2half2_rn(v2, v3);
                }
            }
        }
    }
}

// ---------------- LayerNorm -> fp16 -------------------------------------------
__global__ void ln_f16_kernel(const float* __restrict__ X,
                              const float* __restrict__ gam,
                              const float* __restrict__ bet,
                              __half* __restrict__ Y)
{
    int row = blockIdx.x;
    const float* x = X + (size_t)row * D;
    int tid = threadIdx.x;

    float s = 0.f, ss = 0.f;
    for (int i = tid; i < D; i += 256) { float v = x[i]; s += v; ss += v*v; }
    __shared__ float rs[32], rss[32];
    for (int o = 16; o > 0; o >>= 1) {
        s  += __shfl_xor_sync(0xffffffffu, s,  o);
        ss += __shfl_xor_sync(0xffffffffu, ss, o);
    }
    int wid = tid >> 5, lid = tid & 31;
    if (lid == 0) { rs[wid] = s; rss[wid] = ss; }
    __syncthreads();
    __shared__ float s_mean, s_inv;
    if (tid == 0) {
        float ts = 0.f, tss = 0.f;
        for (int w = 0; w < 8; w++) { ts += rs[w]; tss += rss[w]; }
        float mean = ts * (1.f/D);
        float var  = tss * (1.f/D) - mean*mean;
        s_mean = mean; s_inv = rsqrtf(var + LN_EPS);
    }
    __syncthreads();
    float mean = s_mean, inv = s_inv;
    for (int i = tid; i < D; i += 256)
        Y[(size_t)row*D + i] = __float2half((x[i] - mean) * inv * gam[i] + bet[i]);
}

// ---------------- weight transpose -> fp16 -------------------------------------
__global__ void tf16_kernel(const float* __restrict__ W,
                            __half* __restrict__ T, int K, int N)
{
    __shared__ float t[32][33];
    int n0 = blockIdx.x * 32, k0 = blockIdx.y * 32;
    int tx = threadIdx.x, ty = threadIdx.y;
    for (int i = ty; i < 32; i += 8)
        t[i][tx] = W[(size_t)(k0 + i) * N + n0 + tx];
    __syncthreads();
    for (int r = ty; r < 32; r += 8)
        T[(size_t)(n0 + r) * K + k0 + tx] = __float2half(t[tx][r]);
}

// ---------------- attention kernels (fp16 in, fp32 math, fp16 out) -------------
__global__ void attn_cls_kernel(const __half* __restrict__ qkv,
                                __half* __restrict__ O)
{
    int bh = blockIdx.x;
    int b = bh / H, hh = bh % H;
    int tid = threadIdx.x;

    __shared__ float qs[HD];
    __shared__ float sim[NT];
    __shared__ float red[256];
    __shared__ float red2[4][HD];

    if (tid < HD)
        qs[tid] = __half2float(qkv[(size_t)(b*NT) * D3 + hh*HD + tid]) * QSCALE;
    __syncthreads();

    float lmx = -1e30f;
    for (int j = tid; j < NT; j += 256) {
        const __half* kp = qkv + (size_t)(b*NT + j) * D3 + D + hh*HD;
        float kv[64];
        load64h(kp, kv);
        float s = 0.f;
        #pragma unroll
        for (int d = 0; d < HD; d++) s += qs[d] * kv[d];
        sim[j] = s;
        lmx = fmaxf(lmx, s);
    }
    red[tid] = lmx; __syncthreads();
    for (int st = 128; st > 0; st >>= 1) {
        if (tid < st) red[tid] = fmaxf(red[tid], red[tid+st]);
        __syncthreads();
    }
    float mx = red[0];
    __syncthreads();

    float ls = 0.f;
    for (int j = tid; j < NT; j += 256) {
        float e = __expf(sim[j] - mx);
        sim[j] = e;
        ls += e;
    }
    red[tid] = ls; __syncthreads();
    for (int st = 128; st > 0; st >>= 1) {
        if (tid < st) red[tid] += red[tid+st];
        __syncthreads();
    }
    float linv = 1.f / red[0];
    __syncthreads();

    int d = tid & 63, p = tid >> 6;
    float acc = 0.f;
    for (int j = p; j < NT; j += 4)
        acc += sim[j] * __half2float(qkv[(size_t)(b*NT + j) * D3 + 2*D + hh*HD + d]);
    red2[p][d] = acc;
    __syncthreads();
    if (p == 0) {
        float o = (red2[0][d] + red2[1][d] + red2[2][d] + red2[3][d]) * linv;
        O[(size_t)(b*NT) * D + hh*HD + d] = __float2half(o);
    }
}

__global__ void attn_time_kernel(const __half* __restrict__ qkv,
                                 __half* __restrict__ O)
{
    int qid = blockIdx.x * blockDim.x + threadIdx.x;
    int fr = qid % F;
    int sp = (qid / F) % NS;
    int bh = qid / (F * NS);
    int b = bh / H, hh = bh % H;
    int t = 1 + fr*NS + sp;

    float q[64];
    load64h(qkv + (size_t)(b*NT + t) * D3 + hh*HD, q);
    #pragma unroll
    for (int i = 0; i < 64; i++) q[i] *= QSCALE;

    float sim[F+1];
    #pragma unroll
    for (int j = 0; j < F+1; j++) {
        int tk = (j == 0) ? 0 : (1 + (j-1)*NS + sp);
        float kv[64];
        load64h(qkv + (size_t)(b*NT + tk) * D3 + D + hh*HD, kv);
        float s = 0.f;
        #pragma unroll
        for (int i = 0; i < 64; i++) s += q[i] * kv[i];
        sim[j] = s;
    }
    float mx = sim[0];
    #pragma unroll
    for (int j = 1; j < F+1; j++) mx = fmaxf(mx, sim[j]);
    float l = 0.f;
    #pragma unroll
    for (int j = 0; j < F+1; j++) { sim[j] = __expf(sim[j] - mx); l += sim[j]; }
    float inv = 1.f / l;

    float o[64];
    #pragma unroll
    for (int i = 0; i < 64; i++) o[i] = 0.f;
    #pragma unroll
    for (int j = 0; j < F+1; j++) {
        int tk = (j == 0) ? 0 : (1 + (j-1)*NS + sp);
        float vv[64];
        load64h(qkv + (size_t)(b*NT + tk) * D3 + 2*D + hh*HD, vv);
        float p = sim[j] * inv;
        #pragma unroll
        for (int i = 0; i < 64; i++) o[i] += p * vv[i];
    }
    __half2* op = (__half2*)(O + (size_t)(b*NT + t) * D + hh*HD);
    #pragma unroll
    for (int i = 0; i < 32; i++)
        op[i] = __floats2half2_rn(o[2*i], o[2*i+1]);
}

__global__ void attn_space_kernel(const __half* __restrict__ qkv,
                                  __half* __restrict__ O)
{
    int bx = blockIdx.x;
    int bh = bx / F, fr = bx % F;
    int b = bh / H, hh = bh % H;
    int tid = threadIdx.x;
    int sp = tid;
    const int NK = NS + 1;

    __shared__ __half2 Ks[64 * 32];
    __shared__ __half2 Vs[64 * 32];

    float q[64], o[64];
    float m = -1e30f, l = 0.f;
    if (sp < NS) {
        load64h(qkv + (size_t)(b*NT + 1 + fr*NS + sp) * D3 + hh*HD, q);
        #pragma unroll
        for (int i = 0; i < 64; i++) { q[i] *= QSCALE; o[i] = 0.f; }
    }

    for (int t0 = 0; t0 < NK; t0 += 64) {
        __syncthreads();
        for (int e = tid; e < 64*32; e += 256) {
            int jj = e >> 5, d2 = e & 31;
            int j = t0 + jj;
            __half2 kv = __floats2half2_rn(0.f, 0.f), vv = kv;
            if (j < NK) {
                int tk = (j == 0) ? 0 : (1 + fr*NS + (j-1));
                const __half2* base = (const __half2*)(qkv + (size_t)(b*NT + tk) * D3 + hh*HD);
                kv = base[(D   >> 1) + d2];
                vv = base[(2*D >> 1) + d2];
            }
            Ks[e] = kv; Vs[e] = vv;
        }
        __syncthreads();

        if (sp < NS) {
            int lim = min(64, NK - t0);
            for (int jj = 0; jj < lim; jj++) {
                const uint4* kr = (const uint4*)&Ks[jj * 32];
                float s = 0.f;
                #pragma unroll
                for (int i = 0; i < 8; i++) {
                    float kf[8];
                    unpack8(kr[i], kf);
                    #pragma unroll
                    for (int d = 0; d < 8; d++) s += q[8*i + d] * kf[d];
                }
                float mn  = fmaxf(m, s);
                float fac = __expf(m - mn);
                float p   = __expf(s - mn);
                l = l * fac + p;
                const uint4* vr = (const uint4*)&Vs[jj * 32];
                #pragma unroll
                for (int i = 0; i < 8; i++) {
                    float vf[8];
                    unpack8(vr[i], vf);
                    #pragma unroll
                    for (int d = 0; d < 8; d++)
                        o[8*i + d] = o[8*i + d] * fac + p * vf[d];
                }
                m = mn;
            }
        }
    }

    if (sp < NS) {
        float inv = 1.f / l;
        __half2* op = (__half2*)(O + (size_t)(b*NT + 1 + fr*NS + sp) * D + hh*HD);
        #pragma unroll
        for (int i = 0; i < 32; i++)
            op[i] = __floats2half2_rn(o[2*i]*inv, o[2*i+1]*inv);
    }
}

// ---------------- host launch ------------------------------------------------
extern "C" void kernel_launch(void* const* d_in, const int* in_sizes, int n_in,
                              void* d_out, int out_size)
{
    const float* x      = (const float*)d_in[0];
    const float* n1g    = (const float*)d_in[1];
    const float* n1b    = (const float*)d_in[2];
    const float* n2g    = (const float*)d_in[3];
    const float* n2b    = (const float*)d_in[4];
    const float* n3g    = (const float*)d_in[5];
    const float* n3b    = (const float*)d_in[6];
    const float* aqkvw  = (const float*)d_in[7];
    const float* aqkvb  = (const float*)d_in[8];
    const float* aprojw = (const float*)d_in[9];
    const float* aprojb = (const float*)d_in[10];
    const float* tqkvw  = (const float*)d_in[11];
    const float* tqkvb  = (const float*)d_in[12];
    const float* tprojw = (const float*)d_in[13];
    const float* tprojb = (const float*)d_in[14];
    const float* fc1w   = (const float*)d_in[15];
    const float* fc1b   = (const float*)d_in[16];
    const float* fc2w   = (const float*)d_in[17];
    const float* fc2b   = (const float*)d_in[18];
    float* out = (float*)d_out;

    __half *lnf, *attf, *hidf, *qkvh;
    __half *wf_tqkv, *wf_aqkv, *wf_tproj, *wf_aproj, *wf_fc1, *wf_fc2;
    float *btres, *bsres;
    cudaGetSymbolAddress((void**)&lnf,  g_lnf);
    cudaGetSymbolAddress((void**)&attf, g_attf);
    cudaGetSymbolAddress((void**)&hidf, g_hidf);
    cudaGetSymbolAddress((void**)&qkvh, g_qkvh);
    cudaGetSymbolAddress((void**)&btres,g_tres);
    cudaGetSymbolAddress((void**)&bsres,g_sres);
    cudaGetSymbolAddress((void**)&wf_tqkv, g_wf_tqkv);
    cudaGetSymbolAddress((void**)&wf_aqkv, g_wf_aqkv);
    cudaGetSymbolAddress((void**)&wf_tproj,g_wf_tproj);
    cudaGetSymbolAddress((void**)&wf_aproj,g_wf_aproj);
    cudaGetSymbolAddress((void**)&wf_fc1,  g_wf_fc1);
    cudaGetSymbolAddress((void**)&wf_fc2,  g_wf_fc2);

    cudaFuncSetAttribute(gemm_f16<1>, cudaFuncAttributeMaxDynamicSharedMemorySize, SMEM_F16);
    cudaFuncSetAttribute(gemm_f16<4>, cudaFuncAttributeMaxDynamicSharedMemorySize, SMEM_F16);
    cudaFuncSetAttribute(gemm_f16<5>, cudaFuncAttributeMaxDynamicSharedMemorySize, SMEM_F16);

    const int MT = (M + BM - 1) / BM;    // 99
    dim3 tb(32, 8);

    // ---- weight transforms (fp16 transpose) ----
    tf16_kernel<<<dim3(D3/32, D/32), tb>>>(tqkvw, wf_tqkv, D, D3);
    tf16_kernel<<<dim3(D3/32, D/32), tb>>>(aqkvw, wf_aqkv, D, D3);
    tf16_kernel<<<dim3(D/32,  D/32), tb>>>(tprojw, wf_tproj, D, D);
    tf16_kernel<<<dim3(D/32,  D/32), tb>>>(aprojw, wf_aproj, D, D);
    tf16_kernel<<<dim3(D4/32, D/32), tb>>>(fc1w, wf_fc1, D, D4);
    tf16_kernel<<<dim3(D/32, D4/32), tb>>>(fc2w, wf_fc2, D4, D);

    const int nTimeBlocks = (B*H*NS*F) / 256;   // 588

    // ---- time attention branch ----
    ln_f16_kernel<<<M, 256>>>(x, n3g, n3b, lnf);
    gemm_f16<5><<<dim3(D3/BN, MT), 256, SMEM_F16>>>(lnf, wf_tqkv, tqkvb, nullptr, nullptr, qkvh, M, D, D3);
    attn_cls_kernel <<<B*H, 256>>>(qkvh, attf);
    attn_time_kernel<<<nTimeBlocks, 256>>>(qkvh, attf);
    gemm_f16<1><<<dim3(D/BN, MT), 256, SMEM_F16>>>(attf, wf_tproj, tprojb, x, btres, nullptr, M, D, D);

    // ---- space attention branch ----
    ln_f16_kernel<<<M, 256>>>(btres, n1g, n1b, lnf);
    gemm_f16<5><<<dim3(D3/BN, MT), 256, SMEM_F16>>>(lnf, wf_aqkv, aqkvb, nullptr, nullptr, qkvh, M, D, D3);
    attn_cls_kernel  <<<B*H, 256>>>(qkvh, attf);
    attn_space_kernel<<<B*H*F, 256>>>(qkvh, attf);
    gemm_f16<1><<<dim3(D/BN, MT), 256, SMEM_F16>>>(attf, wf_aproj, aprojb, x, bsres, nullptr, M, D, D);

    // ---- MLP ----
    ln_f16_kernel<<<M, 256>>>(bsres, n2g, n2b, lnf);
    gemm_f16<4><<<dim3(D4/BN, MT), 256, SMEM_F16>>>(lnf, wf_fc1, fc1b, nullptr, nullptr, hidf, M, D, D4);
    gemm_f16<1><<<dim3(D/BN, MT), 256, SMEM_F16>>>(hidf, wf_fc2, fc2b, bsres, out, nullptr, M, D4, D);
}

// round 11
// speedup vs baseline: 4.0191x; 1.1462x over previous
#include <cuda_runtime.h>
#include <cuda_fp16.h>
#include <math.h>
#include <cstdint>

// ---------------- problem constants ----------------------------------------
constexpr int B   = 8;
constexpr int F   = 8;
constexpr int NS  = 196;
constexpr int NT  = 1 + F*NS;   // 1569
constexpr int D   = 768;
constexpr int H   = 12;
constexpr int HD  = 64;
constexpr int D3  = 3*D;        // 2304
constexpr int D4  = 4*D;        // 3072
constexpr int M   = B*NT;       // 12552
constexpr float LN_EPS = 1e-5f;
constexpr float QSCALE = 0.125f;

// ---------------- scratch (device globals; no allocation) ------------------
__device__ __half g_lnf [(size_t)M * D];
__device__ __half g_qkvh[(size_t)M * D3];
__device__ __half g_attf[(size_t)M * D];
__device__ float  g_tres[(size_t)M * D];
__device__ float  g_sres[(size_t)M * D];
__device__ __half g_hidf[(size_t)M * D4];
// transposed fp16 weights: Wt[n][k] = W[k][n]
__device__ __half g_wf_tqkv [(size_t)D3*D];
__device__ __half g_wf_aqkv [(size_t)D3*D];
__device__ __half g_wf_tproj[(size_t)D*D];
__device__ __half g_wf_aproj[(size_t)D*D];
__device__ __half g_wf_fc1  [(size_t)D4*D];
__device__ __half g_wf_fc2  [(size_t)D*D4];

// ---------------- helpers ----------------------------------------------------
__device__ __forceinline__ uint32_t smem_to_u32(const void* p) {
    uint32_t a;
    asm("{ .reg .u64 t; cvta.to.shared.u64 t, %1; cvt.u32.u64 %0, t; }"
        : "=r"(a) : "l"(p));
    return a;
}
__device__ __forceinline__ void cp_async16(uint32_t dst, const void* src, bool valid) {
    int sz = valid ? 16 : 0;
    asm volatile("cp.async.cg.shared.global [%0], [%1], 16, %2;"
                 :: "r"(dst), "l"(src), "r"(sz) : "memory");
}
#define CP_COMMIT()  asm volatile("cp.async.commit_group;" ::: "memory")
#define CP_WAIT(n)   asm volatile("cp.async.wait_group %0;" :: "n"(n) : "memory")

__device__ __forceinline__ void ldsm_x4(uint32_t& r0, uint32_t& r1, uint32_t& r2, uint32_t& r3, uint32_t addr) {
    asm volatile("ldmatrix.sync.aligned.m8n8.x4.shared.b16 {%0,%1,%2,%3}, [%4];"
                 : "=r"(r0), "=r"(r1), "=r"(r2), "=r"(r3) : "r"(addr));
}
__device__ __forceinline__ void mma_f16(float* c, const uint32_t* a, const uint32_t* b) {
    asm volatile(
        "mma.sync.aligned.m16n8k16.row.col.f32.f16.f16.f32 "
        "{%0,%1,%2,%3}, {%4,%5,%6,%7}, {%8,%9}, {%0,%1,%2,%3};"
        : "+f"(c[0]), "+f"(c[1]), "+f"(c[2]), "+f"(c[3])
        : "r"(a[0]), "r"(a[1]), "r"(a[2]), "r"(a[3]), "r"(b[0]), "r"(b[1]));
}
__device__ __forceinline__ float gelu_exact(float v) {
    return 0.5f * v * (1.f + erff(v * 0.70710678118654752f));
}
__device__ __forceinline__ void unpack8(const uint4& u, float* dst) {
    const __half2* h = (const __half2*)&u;
    #pragma unroll
    for (int j = 0; j < 4; j++) {
        float2 f = __half22float2(h[j]);
        dst[2*j]   = f.x;
        dst[2*j+1] = f.y;
    }
}
__device__ __forceinline__ void load64h(const __half* p, float* dst) {
    const uint4* u = (const uint4*)p;
    #pragma unroll
    for (int i = 0; i < 8; i++) {
        uint4 v = u[i];
        unpack8(v, dst + 8*i);
    }
}

// ================= fp16 single-pass GEMM (3-stage, 2 CTAs/SM) =================
constexpr int BM = 128, BN = 128, FBK = 64;
constexpr int FRSB = 144;               // 128B data + 16B pad
constexpr int FMAT = 128 * FRSB;        // 18432
constexpr int FSTAGE = 2 * FMAT;        // 36864
constexpr int SMEM_F16 = 3 * FSTAGE;    // 110592 -> 2 CTAs/SM

// EPI: 1 = bias+residual -> fp32 C ; 4 = bias+GELU -> fp16 Ch ; 5 = bias -> fp16 Ch
template<int EPI>
__global__ void __launch_bounds__(256, 2)
gemm_f16(const __half* __restrict__ A, const __half* __restrict__ Bw,
         const float* __restrict__ bias, const float* __restrict__ R,
         float* __restrict__ C, __half* __restrict__ Ch,
         int Mr, int K, int Nc)
{
    extern __shared__ char smem[];
    const uint32_t sb = smem_to_u32(smem);
    const int tid = threadIdx.x;
    const int wid = tid >> 5, lane = tid & 31;
    const int wm = wid & 1, wn = wid >> 1;
    const int bm = blockIdx.y * BM, bn = blockIdx.x * BN;

    float acc[4][4][4];
    #pragma unroll
    for (int i = 0; i < 4; i++)
        #pragma unroll
        for (int j = 0; j < 4; j++)
            #pragma unroll
            for (int q = 0; q < 4; q++) acc[i][j][q] = 0.f;

    auto load_stage = [&](int stage, int k0) {
        uint32_t base = sb + stage * FSTAGE;
        #pragma unroll
        for (int i = 0; i < 4; i++) {
            int idx = tid + i*256;
            int r = idx >> 3, cb = (idx & 7) << 4;
            int gr = bm + r;
            bool v = gr < Mr;
            cp_async16(base + r*FRSB + cb, (const char*)(A + (size_t)(v?gr:0)*K + k0) + cb, v);
        }
        #pragma unroll
        for (int i = 0; i < 4; i++) {
            int idx = tid + i*256;
            int r = idx >> 3, cb = (idx & 7) << 4;
            cp_async16(base + FMAT + r*FRSB + cb, (const char*)(Bw + (size_t)(bn + r)*K + k0) + cb, true);
        }
        CP_COMMIT();
    };

    const int NC = K / FBK;
    load_stage(0, 0);
    load_stage(1, FBK);

    const int aRow = (lane & 15);
    const int aColB = (lane >> 4) * 16;
    const int bMtx = lane >> 3, bRit = lane & 7;
    const int bNrow = (bMtx & 2) ? (8 + bRit) : bRit;
    const int bKoff = (bMtx & 1) * 16;

    int s = 0;   // stage index of chunk c (mod 3)
    for (int c = 0; c < NC; c++) {
        CP_WAIT(1);
        __syncthreads();
        if (c + 2 < NC) {
            int s2 = s + 2; if (s2 >= 3) s2 -= 3;
            load_stage(s2, (c + 2) * FBK);
        }

        uint32_t aB = sb + s * FSTAGE;
        uint32_t bB = aB + FMAT;

        #pragma unroll
        for (int kk = 0; kk < 4; kk++) {
            uint32_t af[4][4], bf[4][2];
            #pragma unroll
            for (int mt = 0; mt < 4; mt++) {
                uint32_t off = (uint32_t)((wm*64 + mt*16 + aRow) * FRSB + kk*32 + aColB);
                ldsm_x4(af[mt][0], af[mt][1], af[mt][2], af[mt][3], aB + off);
            }
            #pragma unroll
            for (int np = 0; np < 2; np++) {
                uint32_t off = (uint32_t)((wn*32 + np*16 + bNrow) * FRSB + kk*32 + bKoff);
                ldsm_x4(bf[2*np][0], bf[2*np][1], bf[2*np+1][0], bf[2*np+1][1], bB + off);
            }
            #pragma unroll
            for (int mt = 0; mt < 4; mt++)
                #pragma unroll
                for (int nt = 0; nt < 4; nt++)
                    mma_f16(acc[mt][nt], af[mt], bf[nt]);
        }
        __syncthreads();
        if (++s == 3) s = 0;
    }

    const int er = lane >> 2, ec = (lane & 3) * 2;
    #pragma unroll
    for (int mt = 0; mt < 4; mt++) {
        int r0 = bm + wm*64 + mt*16 + er;
        int r1 = r0 + 8;
        #pragma unroll
        for (int nt = 0; nt < 4; nt++) {
            int cc = bn + wn*32 + nt*8 + ec;
            float b0 = bias[cc], b1 = bias[cc + 1];
            if (r0 < Mr) {
                float v0 = acc[mt][nt][0] + b0;
                float v1 = acc[mt][nt][1] + b1;
                size_t off = (size_t)r0 * Nc + cc;
                if (EPI == 1) {
                    C[off] = v0 + R[off]; C[off + 1] = v1 + R[off + 1];
                } else if (EPI == 4) {
                    *(__half2*)&Ch[off] = __floats2half2_rn(gelu_exact(v0), gelu_exact(v1));
                } else {
                    *(__half2*)&Ch[off] = __floats2half2_rn(v0, v1);
                }
            }
            if (r1 < Mr) {
                float v2 = acc[mt][nt][2] + b0;
                float v3 = acc[mt][nt][3] + b1;
                size_t off = (size_t)r1 * Nc + cc;
                if (EPI == 1) {
                    C[off] = v2 + R[off]; C[off + 1] = v3 + R[off + 1];
                } else if (EPI == 4) {
                    *(__half2*)&Ch[off] = __floats2half2_rn(gelu_exact(v2), gelu_exact(v3));
                } else {
                    *(__half2*)&Ch[off] = __floats2half2_rn(v2, v3);
                }
            }
        }
    }
}

// ---------------- LayerNorm -> fp16 -------------------------------------------
__global__ void ln_f16_kernel(const float* __restrict__ X,
                              const float* __restrict__ gam,
                              const float* __restrict__ bet,
                              __half* __restrict__ Y)
{
    int row = blockIdx.x;
    const float* x = X + (size_t)row * D;
    int tid = threadIdx.x;

    float s = 0.f, ss = 0.f;
    for (int i = tid; i < D; i += 256) { float v = x[i]; s += v; ss += v*v; }
    __shared__ float rs[32], rss[32];
    for (int o = 16; o > 0; o >>= 1) {
        s  += __shfl_xor_sync(0xffffffffu, s,  o);
        ss += __shfl_xor_sync(0xffffffffu, ss, o);
    }
    int wid = tid >> 5, lid = tid & 31;
    if (lid == 0) { rs[wid] = s; rss[wid] = ss; }
    __syncthreads();
    __shared__ float s_mean, s_inv;
    if (tid == 0) {
        float ts = 0.f, tss = 0.f;
        for (int w = 0; w < 8; w++) { ts += rs[w]; tss += rss[w]; }
        float mean = ts * (1.f/D);
        float var  = tss * (1.f/D) - mean*mean;
        s_mean = mean; s_inv = rsqrtf(var + LN_EPS);
    }
    __syncthreads();
    float mean = s_mean, inv = s_inv;
    for (int i = tid; i < D; i += 256)
        Y[(size_t)row*D + i] = __float2half((x[i] - mean) * inv * gam[i] + bet[i]);
}

// ---------------- weight transpose -> fp16 -------------------------------------
__global__ void tf16_kernel(const float* __restrict__ W,
                            __half* __restrict__ T, int K, int N)
{
    __shared__ float t[32][33];
    int n0 = blockIdx.x * 32, k0 = blockIdx.y * 32;
    int tx = threadIdx.x, ty = threadIdx.y;
    for (int i = ty; i < 32; i += 8)
        t[i][tx] = W[(size_t)(k0 + i) * N + n0 + tx];
    __syncthreads();
    for (int r = ty; r < 32; r += 8)
        T[(size_t)(n0 + r) * K + k0 + tx] = __float2half(t[tx][r]);
}

// ---------------- attention kernels (fp16 in, fp32 math, fp16 out) -------------
__global__ void attn_cls_kernel(const __half* __restrict__ qkv,
                                __half* __restrict__ O)
{
    int bh = blockIdx.x;
    int b = bh / H, hh = bh % H;
    int tid = threadIdx.x;

    __shared__ float qs[HD];
    __shared__ float sim[NT];
    __shared__ float red[256];
    __shared__ float red2[4][HD];

    if (tid < HD)
        qs[tid] = __half2float(qkv[(size_t)(b*NT) * D3 + hh*HD + tid]) * QSCALE;
    __syncthreads();

    float lmx = -1e30f;
    for (int j = tid; j < NT; j += 256) {
        const __half* kp = qkv + (size_t)(b*NT + j) * D3 + D + hh*HD;
        float kv[64];
        load64h(kp, kv);
        float s = 0.f;
        #pragma unroll
        for (int d = 0; d < HD; d++) s += qs[d] * kv[d];
        sim[j] = s;
        lmx = fmaxf(lmx, s);
    }
    red[tid] = lmx; __syncthreads();
    for (int st = 128; st > 0; st >>= 1) {
        if (tid < st) red[tid] = fmaxf(red[tid], red[tid+st]);
        __syncthreads();
    }
    float mx = red[0];
    __syncthreads();

    float ls = 0.f;
    for (int j = tid; j < NT; j += 256) {
        float e = __expf(sim[j] - mx);
        sim[j] = e;
        ls += e;
    }
    red[tid] = ls; __syncthreads();
    for (int st = 128; st > 0; st >>= 1) {
        if (tid < st) red[tid] += red[tid+st];
        __syncthreads();
    }
    float linv = 1.f / red[0];
    __syncthreads();

    int d = tid & 63, p = tid >> 6;
    float acc = 0.f;
    for (int j = p; j < NT; j += 4)
        acc += sim[j] * __half2float(qkv[(size_t)(b*NT + j) * D3 + 2*D + hh*HD + d]);
    red2[p][d] = acc;
    __syncthreads();
    if (p == 0) {
        float o = (red2[0][d] + red2[1][d] + red2[2][d] + red2[3][d]) * linv;
        O[(size_t)(b*NT) * D + hh*HD + d] = __float2half(o);
    }
}

__global__ void attn_time_kernel(const __half* __restrict__ qkv,
                                 __half* __restrict__ O)
{
    int qid = blockIdx.x * blockDim.x + threadIdx.x;
    int fr = qid % F;
    int sp = (qid / F) % NS;
    int bh = qid / (F * NS);
    int b = bh / H, hh = bh % H;
    int t = 1 + fr*NS + sp;

    float q[64];
    load64h(qkv + (size_t)(b*NT + t) * D3 + hh*HD, q);
    #pragma unroll
    for (int i = 0; i < 64; i++) q[i] *= QSCALE;

    float sim[F+1];
    #pragma unroll
    for (int j = 0; j < F+1; j++) {
        int tk = (j == 0) ? 0 : (1 + (j-1)*NS + sp);
        float kv[64];
        load64h(qkv + (size_t)(b*NT + tk) * D3 + D + hh*HD, kv);
        float s = 0.f;
        #pragma unroll
        for (int i = 0; i < 64; i++) s += q[i] * kv[i];
        sim[j] = s;
    }
    float mx = sim[0];
    #pragma unroll
    for (int j = 1; j < F+1; j++) mx = fmaxf(mx, sim[j]);
    float l = 0.f;
    #pragma unroll
    for (int j = 0; j < F+1; j++) { sim[j] = __expf(sim[j] - mx); l += sim[j]; }
    float inv = 1.f / l;

    float o[64];
    #pragma unroll
    for (int i = 0; i < 64; i++) o[i] = 0.f;
    #pragma unroll
    for (int j = 0; j < F+1; j++) {
        int tk = (j == 0) ? 0 : (1 + (j-1)*NS + sp);
        float vv[64];
        load64h(qkv + (size_t)(b*NT + tk) * D3 + 2*D + hh*HD, vv);
        float p = sim[j] * inv;
        #pragma unroll
        for (int i = 0; i < 64; i++) o[i] += p * vv[i];
    }
    __half2* op = (__half2*)(O + (size_t)(b*NT + t) * D + hh*HD);
    #pragma unroll
    for (int i = 0; i < 32; i++)
        op[i] = __floats2half2_rn(o[2*i], o[2*i+1]);
}

__global__ void attn_space_kernel(const __half* __restrict__ qkv,
                                  __half* __restrict__ O)
{
    int bx = blockIdx.x;
    int bh = bx / F, fr = bx % F;
    int b = bh / H, hh = bh % H;
    int tid = threadIdx.x;
    int sp = tid;
    const int NK = NS + 1;

    __shared__ __half2 Ks[64 * 32];
    __shared__ __half2 Vs[64 * 32];

    float q[64], o[64];
    float m = -1e30f, l = 0.f;
    if (sp < NS) {
        load64h(qkv + (size_t)(b*NT + 1 + fr*NS + sp) * D3 + hh*HD, q);
        #pragma unroll
        for (int i = 0; i < 64; i++) { q[i] *= QSCALE; o[i] = 0.f; }
    }

    for (int t0 = 0; t0 < NK; t0 += 64) {
        __syncthreads();
        for (int e = tid; e < 64*32; e += 256) {
            int jj = e >> 5, d2 = e & 31;
            int j = t0 + jj;
            __half2 kv = __floats2half2_rn(0.f, 0.f), vv = kv;
            if (j < NK) {
                int tk = (j == 0) ? 0 : (1 + fr*NS + (j-1));
                const __half2* base = (const __half2*)(qkv + (size_t)(b*NT + tk) * D3 + hh*HD);
                kv = base[(D   >> 1) + d2];
                vv = base[(2*D >> 1) + d2];
            }
            Ks[e] = kv; Vs[e] = vv;
        }
        __syncthreads();

        if (sp < NS) {
            int lim = min(64, NK - t0);
            for (int jj = 0; jj < lim; jj++) {
                const uint4* kr = (const uint4*)&Ks[jj * 32];
                float s = 0.f;
                #pragma unroll
                for (int i = 0; i < 8; i++) {
                    float kf[8];
                    unpack8(kr[i], kf);
                    #pragma unroll
                    for (int d = 0; d < 8; d++) s += q[8*i + d] * kf[d];
                }
                float mn  = fmaxf(m, s);
                float fac = __expf(m - mn);
                float p   = __expf(s - mn);
                l = l * fac + p;
                const uint4* vr = (const uint4*)&Vs[jj * 32];
                #pragma unroll
                for (int i = 0; i < 8; i++) {
                    float vf[8];
                    unpack8(vr[i], vf);
                    #pragma unroll
                    for (int d = 0; d < 8; d++)
                        o[8*i + d] = o[8*i + d] * fac + p * vf[d];
                }
                m = mn;
            }
        }
    }

    if (sp < NS) {
        float inv = 1.f / l;
        __half2* op = (__half2*)(O + (size_t)(b*NT + 1 + fr*NS + sp) * D + hh*HD);
        #pragma unroll
        for (int i = 0; i < 32; i++)
            op[i] = __floats2half2_rn(o[2*i]*inv, o[2*i+1]*inv);
    }
}

// ---------------- host launch ------------------------------------------------
extern "C" void kernel_launch(void* const* d_in, const int* in_sizes, int n_in,
                              void* d_out, int out_size)
{
    const float* x      = (const float*)d_in[0];
    const float* n1g    = (const float*)d_in[1];
    const float* n1b    = (const float*)d_in[2];
    const float* n2g    = (const float*)d_in[3];
    const float* n2b    = (const float*)d_in[4];
    const float* n3g    = (const float*)d_in[5];
    const float* n3b    = (const float*)d_in[6];
    const float* aqkvw  = (const float*)d_in[7];
    const float* aqkvb  = (const float*)d_in[8];
    const float* aprojw = (const float*)d_in[9];
    const float* aprojb = (const float*)d_in[10];
    const float* tqkvw  = (const float*)d_in[11];
    const float* tqkvb  = (const float*)d_in[12];
    const float* tprojw = (const float*)d_in[13];
    const float* tprojb = (const float*)d_in[14];
    const float* fc1w   = (const float*)d_in[15];
    const float* fc1b   = (const float*)d_in[16];
    const float* fc2w   = (const float*)d_in[17];
    const float* fc2b   = (const float*)d_in[18];
    float* out = (float*)d_out;

    __half *lnf, *attf, *hidf, *qkvh;
    __half *wf_tqkv, *wf_aqkv, *wf_tproj, *wf_aproj, *wf_fc1, *wf_fc2;
    float *btres, *bsres;
    cudaGetSymbolAddress((void**)&lnf,  g_lnf);
    cudaGetSymbolAddress((void**)&attf, g_attf);
    cudaGetSymbolAddress((void**)&hidf, g_hidf);
    cudaGetSymbolAddress((void**)&qkvh, g_qkvh);
    cudaGetSymbolAddress((void**)&btres,g_tres);
    cudaGetSymbolAddress((void**)&bsres,g_sres);
    cudaGetSymbolAddress((void**)&wf_tqkv, g_wf_tqkv);
    cudaGetSymbolAddress((void**)&wf_aqkv, g_wf_aqkv);
    cudaGetSymbolAddress((void**)&wf_tproj,g_wf_tproj);
    cudaGetSymbolAddress((void**)&wf_aproj,g_wf_aproj);
    cudaGetSymbolAddress((void**)&wf_fc1,  g_wf_fc1);
    cudaGetSymbolAddress((void**)&wf_fc2,  g_wf_fc2);

    cudaFuncSetAttribute(gemm_f16<1>, cudaFuncAttributeMaxDynamicSharedMemorySize, SMEM_F16);
    cudaFuncSetAttribute(gemm_f16<4>, cudaFuncAttributeMaxDynamicSharedMemorySize, SMEM_F16);
    cudaFuncSetAttribute(gemm_f16<5>, cudaFuncAttributeMaxDynamicSharedMemorySize, SMEM_F16);

    const int MT = (M + BM - 1) / BM;    // 99
    dim3 tb(32, 8);
    const int nTimeBlocks = (B*H*NS*F) / 256;   // 588

    // Launch order puts the QKV GEMM at index 5 so ncu (-s 5 -c 1) captures it.
    tf16_kernel<<<dim3(D3/32, D/32), tb>>>(tqkvw, wf_tqkv, D, D3);   // 0
    tf16_kernel<<<dim3(D3/32, D/32), tb>>>(aqkvw, wf_aqkv, D, D3);   // 1
    tf16_kernel<<<dim3(D/32,  D/32), tb>>>(tprojw, wf_tproj, D, D);  // 2
    tf16_kernel<<<dim3(D/32,  D/32), tb>>>(aprojw, wf_aproj, D, D);  // 3
    ln_f16_kernel<<<M, 256>>>(x, n3g, n3b, lnf);                     // 4
    gemm_f16<5><<<dim3(D3/BN, MT), 256, SMEM_F16>>>(lnf, wf_tqkv, tqkvb, nullptr, nullptr, qkvh, M, D, D3);  // 5 <- profiled
    attn_cls_kernel <<<B*H, 256>>>(qkvh, attf);
    attn_time_kernel<<<nTimeBlocks, 256>>>(qkvh, attf);
    gemm_f16<1><<<dim3(D/BN, MT), 256, SMEM_F16>>>(attf, wf_tproj, tprojb, x, btres, nullptr, M, D, D);

    // ---- space attention branch ----
    ln_f16_kernel<<<M, 256>>>(btres, n1g, n1b, lnf);
    gemm_f16<5><<<dim3(D3/BN, MT), 256, SMEM_F16>>>(lnf, wf_aqkv, aqkvb, nullptr, nullptr, qkvh, M, D, D3);
    attn_cls_kernel  <<<B*H, 256>>>(qkvh, attf);
    attn_space_kernel<<<B*H*F, 256>>>(qkvh, attf);
    gemm_f16<1><<<dim3(D/BN, MT), 256, SMEM_F16>>>(attf, wf_aproj, aprojb, x, bsres, nullptr, M, D, D);

    // ---- MLP ----
    tf16_kernel<<<dim3(D4/32, D/32), tb>>>(fc1w, wf_fc1, D, D4);
    tf16_kernel<<<dim3(D/32, D4/32), tb>>>(fc2w, wf_fc2, D4, D);
    ln_f16_kernel<<<M, 256>>>(bsres, n2g, n2b, lnf);
    gemm_f16<4><<<dim3(D4/BN, MT), 256, SMEM_F16>>>(lnf, wf_fc1, fc1b, nullptr, nullptr, hidf, M, D, D4);
    gemm_f16<1><<<dim3(D/BN, MT), 256, SMEM_F16>>>(hidf, wf_fc2, fc2b, bsres, out, nullptr, M, D4, D);
}

// round 12
// speedup vs baseline: 4.4692x; 1.1120x over previous
#include <cuda_runtime.h>
#include <cuda_fp16.h>
#include <math.h>
#include <cstdint>

// ---------------- problem constants ----------------------------------------
constexpr int B   = 8;
constexpr int F   = 8;
constexpr int NS  = 196;
constexpr int NT  = 1 + F*NS;   // 1569
constexpr int D   = 768;
constexpr int H   = 12;
constexpr int HD  = 64;
constexpr int D3  = 3*D;        // 2304
constexpr int D4  = 4*D;        // 3072
constexpr int M   = B*NT;       // 12552
constexpr float LN_EPS = 1e-5f;
constexpr float QSCALE = 0.125f;

// ---------------- scratch (device globals; no allocation) ------------------
__device__ __half g_lnf [(size_t)M * D];
__device__ __half g_qkvh[(size_t)M * D3];
__device__ __half g_attf[(size_t)M * D];
__device__ float  g_tres[(size_t)M * D];
__device__ float  g_sres[(size_t)M * D];
__device__ __half g_hidf[(size_t)M * D4];
// transposed fp16 weights: Wt[n][k] = W[k][n]
__device__ __half g_wf_tqkv [(size_t)D3*D];
__device__ __half g_wf_aqkv [(size_t)D3*D];
__device__ __half g_wf_tproj[(size_t)D*D];
__device__ __half g_wf_aproj[(size_t)D*D];
__device__ __half g_wf_fc1  [(size_t)D4*D];
__device__ __half g_wf_fc2  [(size_t)D*D4];

// ---------------- helpers ----------------------------------------------------
__device__ __forceinline__ uint32_t smem_to_u32(const void* p) {
    uint32_t a;
    asm("{ .reg .u64 t; cvta.to.shared.u64 t, %1; cvt.u32.u64 %0, t; }"
        : "=r"(a) : "l"(p));
    return a;
}
__device__ __forceinline__ void cp_async16(uint32_t dst, const void* src, bool valid) {
    int sz = valid ? 16 : 0;
    asm volatile("cp.async.cg.shared.global [%0], [%1], 16, %2;"
                 :: "r"(dst), "l"(src), "r"(sz) : "memory");
}
#define CP_COMMIT()  asm volatile("cp.async.commit_group;" ::: "memory")
#define CP_WAIT(n)   asm volatile("cp.async.wait_group %0;" :: "n"(n) : "memory")

__device__ __forceinline__ void ldsm_x4(uint32_t& r0, uint32_t& r1, uint32_t& r2, uint32_t& r3, uint32_t addr) {
    asm volatile("ldmatrix.sync.aligned.m8n8.x4.shared.b16 {%0,%1,%2,%3}, [%4];"
                 : "=r"(r0), "=r"(r1), "=r"(r2), "=r"(r3) : "r"(addr));
}
__device__ __forceinline__ void mma_f16(float* c, const uint32_t* a, const uint32_t* b) {
    asm volatile(
        "mma.sync.aligned.m16n8k16.row.col.f32.f16.f16.f32 "
        "{%0,%1,%2,%3}, {%4,%5,%6,%7}, {%8,%9}, {%0,%1,%2,%3};"
        : "+f"(c[0]), "+f"(c[1]), "+f"(c[2]), "+f"(c[3])
        : "r"(a[0]), "r"(a[1]), "r"(a[2]), "r"(a[3]), "r"(b[0]), "r"(b[1]));
}
__device__ __forceinline__ float gelu_exact(float v) {
    return 0.5f * v * (1.f + erff(v * 0.70710678118654752f));
}
__device__ __forceinline__ void unpack8(const uint4& u, float* dst) {
    const __half2* h = (const __half2*)&u;
    #pragma unroll
    for (int j = 0; j < 4; j++) {
        float2 f = __half22float2(h[j]);
        dst[2*j]   = f.x;
        dst[2*j+1] = f.y;
    }
}
__device__ __forceinline__ void load64h(const __half* p, float* dst) {
    const uint4* u = (const uint4*)p;
    #pragma unroll
    for (int i = 0; i < 8; i++) {
        uint4 v = u[i];
        unpack8(v, dst + 8*i);
    }
}

// ================= fp16 single-pass GEMM (3-stage, 2 CTAs/SM) =================
constexpr int BM = 128, BN = 128, FBK = 64;
constexpr int FRSB = 144;               // 128B data + 16B pad
constexpr int FMAT = 128 * FRSB;        // 18432
constexpr int FSTAGE = 2 * FMAT;        // 36864
constexpr int SMEM_F16 = 3 * FSTAGE;    // 110592 -> 2 CTAs/SM

// EPI: 1 = bias+residual -> fp32 C ; 4 = bias+GELU -> fp16 Ch ; 5 = bias -> fp16 Ch
template<int EPI>
__global__ void __launch_bounds__(256, 2)
gemm_f16(const __half* __restrict__ A, const __half* __restrict__ Bw,
         const float* __restrict__ bias, const float* __restrict__ R,
         float* __restrict__ C, __half* __restrict__ Ch,
         int Mr, int K, int Nc)
{
    extern __shared__ char smem[];
    const uint32_t sb = smem_to_u32(smem);
    const int tid = threadIdx.x;
    const int wid = tid >> 5, lane = tid & 31;
    const int wm = wid & 1, wn = wid >> 1;
    const int bm = blockIdx.y * BM, bn = blockIdx.x * BN;

    float acc[4][4][4];
    #pragma unroll
    for (int i = 0; i < 4; i++)
        #pragma unroll
        for (int j = 0; j < 4; j++)
            #pragma unroll
            for (int q = 0; q < 4; q++) acc[i][j][q] = 0.f;

    auto load_stage = [&](int stage, int k0) {
        uint32_t base = sb + stage * FSTAGE;
        #pragma unroll
        for (int i = 0; i < 4; i++) {
            int idx = tid + i*256;
            int r = idx >> 3, cb = (idx & 7) << 4;
            int gr = bm + r;
            bool v = gr < Mr;
            cp_async16(base + r*FRSB + cb, (const char*)(A + (size_t)(v?gr:0)*K + k0) + cb, v);
        }
        #pragma unroll
        for (int i = 0; i < 4; i++) {
            int idx = tid + i*256;
            int r = idx >> 3, cb = (idx & 7) << 4;
            cp_async16(base + FMAT + r*FRSB + cb, (const char*)(Bw + (size_t)(bn + r)*K + k0) + cb, true);
        }
        CP_COMMIT();
    };

    const int NC = K / FBK;
    load_stage(0, 0);
    load_stage(1, FBK);

    const int aRow = (lane & 15);
    const int aColB = (lane >> 4) * 16;
    const int bMtx = lane >> 3, bRit = lane & 7;
    const int bNrow = (bMtx & 2) ? (8 + bRit) : bRit;
    const int bKoff = (bMtx & 1) * 16;

    int s = 0;   // stage of chunk c (mod 3)
    for (int c = 0; c < NC; c++) {
        CP_WAIT(1);
        __syncthreads();
        if (c + 2 < NC) {
            int s2 = s + 2; if (s2 >= 3) s2 -= 3;
            load_stage(s2, (c + 2) * FBK);
        }

        uint32_t aB = sb + s * FSTAGE;
        uint32_t bB = aB + FMAT;

        #pragma unroll
        for (int kk = 0; kk < 4; kk++) {
            uint32_t af[4][4], bf[4][2];
            #pragma unroll
            for (int mt = 0; mt < 4; mt++) {
                uint32_t off = (uint32_t)((wm*64 + mt*16 + aRow) * FRSB + kk*32 + aColB);
                ldsm_x4(af[mt][0], af[mt][1], af[mt][2], af[mt][3], aB + off);
            }
            #pragma unroll
            for (int np = 0; np < 2; np++) {
                uint32_t off = (uint32_t)((wn*32 + np*16 + bNrow) * FRSB + kk*32 + bKoff);
                ldsm_x4(bf[2*np][0], bf[2*np][1], bf[2*np+1][0], bf[2*np+1][1], bB + off);
            }
            #pragma unroll
            for (int mt = 0; mt < 4; mt++)
                #pragma unroll
                for (int nt = 0; nt < 4; nt++)
                    mma_f16(acc[mt][nt], af[mt], bf[nt]);
        }
        if (++s == 3) s = 0;
    }

    const int er = lane >> 2, ec = (lane & 3) * 2;
    #pragma unroll
    for (int mt = 0; mt < 4; mt++) {
        int r0 = bm + wm*64 + mt*16 + er;
        int r1 = r0 + 8;
        #pragma unroll
        for (int nt = 0; nt < 4; nt++) {
            int cc = bn + wn*32 + nt*8 + ec;
            float b0 = bias[cc], b1 = bias[cc + 1];
            if (r0 < Mr) {
                float v0 = acc[mt][nt][0] + b0;
                float v1 = acc[mt][nt][1] + b1;
                size_t off = (size_t)r0 * Nc + cc;
                if (EPI == 1) {
                    C[off] = v0 + R[off]; C[off + 1] = v1 + R[off + 1];
                } else if (EPI == 4) {
                    *(__half2*)&Ch[off] = __floats2half2_rn(gelu_exact(v0), gelu_exact(v1));
                } else {
                    *(__half2*)&Ch[off] = __floats2half2_rn(v0, v1);
                }
            }
            if (r1 < Mr) {
                float v2 = acc[mt][nt][2] + b0;
                float v3 = acc[mt][nt][3] + b1;
                size_t off = (size_t)r1 * Nc + cc;
                if (EPI == 1) {
                    C[off] = v2 + R[off]; C[off + 1] = v3 + R[off + 1];
                } else if (EPI == 4) {
                    *(__half2*)&Ch[off] = __floats2half2_rn(gelu_exact(v2), gelu_exact(v3));
                } else {
                    *(__half2*)&Ch[off] = __floats2half2_rn(v2, v3);
                }
            }
        }
    }
}

// ---------------- LayerNorm -> fp16 -------------------------------------------
__global__ void ln_f16_kernel(const float* __restrict__ X,
                              const float* __restrict__ gam,
                              const float* __restrict__ bet,
                              __half* __restrict__ Y)
{
    int row = blockIdx.x;
    const float* x = X + (size_t)row * D;
    int tid = threadIdx.x;

    float s = 0.f, ss = 0.f;
    for (int i = tid; i < D; i += 256) { float v = x[i]; s += v; ss += v*v; }
    __shared__ float rs[32], rss[32];
    for (int o = 16; o > 0; o >>= 1) {
        s  += __shfl_xor_sync(0xffffffffu, s,  o);
        ss += __shfl_xor_sync(0xffffffffu, ss, o);
    }
    int wid = tid >> 5, lid = tid & 31;
    if (lid == 0) { rs[wid] = s; rss[wid] = ss; }
    __syncthreads();
    __shared__ float s_mean, s_inv;
    if (tid == 0) {
        float ts = 0.f, tss = 0.f;
        for (int w = 0; w < 8; w++) { ts += rs[w]; tss += rss[w]; }
        float mean = ts * (1.f/D);
        float var  = tss * (1.f/D) - mean*mean;
        s_mean = mean; s_inv = rsqrtf(var + LN_EPS);
    }
    __syncthreads();
    float mean = s_mean, inv = s_inv;
    for (int i = tid; i < D; i += 256)
        Y[(size_t)row*D + i] = __float2half((x[i] - mean) * inv * gam[i] + bet[i]);
}

// ---------------- weight transpose -> fp16 -------------------------------------
__global__ void tf16_kernel(const float* __restrict__ W,
                            __half* __restrict__ T, int K, int N)
{
    __shared__ float t[32][33];
    int n0 = blockIdx.x * 32, k0 = blockIdx.y * 32;
    int tx = threadIdx.x, ty = threadIdx.y;
    for (int i = ty; i < 32; i += 8)
        t[i][tx] = W[(size_t)(k0 + i) * N + n0 + tx];
    __syncthreads();
    for (int r = ty; r < 32; r += 8)
        T[(size_t)(n0 + r) * K + k0 + tx] = __float2half(t[tx][r]);
}

// ---------------- attention kernels ------------------------------------------
__global__ void attn_cls_kernel(const __half* __restrict__ qkv,
                                __half* __restrict__ O)
{
    int bh = blockIdx.x;
    int b = bh / H, hh = bh % H;
    int tid = threadIdx.x;

    __shared__ float qs[HD];
    __shared__ float sim[NT];
    __shared__ float red[256];
    __shared__ float red2[4][HD];

    if (tid < HD)
        qs[tid] = __half2float(qkv[(size_t)(b*NT) * D3 + hh*HD + tid]) * QSCALE;
    __syncthreads();

    float lmx = -1e30f;
    for (int j = tid; j < NT; j += 256) {
        const __half* kp = qkv + (size_t)(b*NT + j) * D3 + D + hh*HD;
        float kv[64];
        load64h(kp, kv);
        float s = 0.f;
        #pragma unroll
        for (int d = 0; d < HD; d++) s += qs[d] * kv[d];
        sim[j] = s;
        lmx = fmaxf(lmx, s);
    }
    red[tid] = lmx; __syncthreads();
    for (int st = 128; st > 0; st >>= 1) {
        if (tid < st) red[tid] = fmaxf(red[tid], red[tid+st]);
        __syncthreads();
    }
    float mx = red[0];
    __syncthreads();

    float ls = 0.f;
    for (int j = tid; j < NT; j += 256) {
        float e = __expf(sim[j] - mx);
        sim[j] = e;
        ls += e;
    }
    red[tid] = ls; __syncthreads();
    for (int st = 128; st > 0; st >>= 1) {
        if (tid < st) red[tid] += red[tid+st];
        __syncthreads();
    }
    float linv = 1.f / red[0];
    __syncthreads();

    int d = tid & 63, p = tid >> 6;
    float acc = 0.f;
    for (int j = p; j < NT; j += 4)
        acc += sim[j] * __half2float(qkv[(size_t)(b*NT + j) * D3 + 2*D + hh*HD + d]);
    red2[p][d] = acc;
    __syncthreads();
    if (p == 0) {
        float o = (red2[0][d] + red2[1][d] + red2[2][d] + red2[3][d]) * linv;
        O[(size_t)(b*NT) * D + hh*HD + d] = __float2half(o);
    }
}

__global__ void attn_time_kernel(const __half* __restrict__ qkv,
                                 __half* __restrict__ O)
{
    int qid = blockIdx.x * blockDim.x + threadIdx.x;
    int fr = qid % F;
    int sp = (qid / F) % NS;
    int bh = qid / (F * NS);
    int b = bh / H, hh = bh % H;
    int t = 1 + fr*NS + sp;

    float q[64];
    load64h(qkv + (size_t)(b*NT + t) * D3 + hh*HD, q);
    #pragma unroll
    for (int i = 0; i < 64; i++) q[i] *= QSCALE;

    float sim[F+1];
    #pragma unroll
    for (int j = 0; j < F+1; j++) {
        int tk = (j == 0) ? 0 : (1 + (j-1)*NS + sp);
        float kv[64];
        load64h(qkv + (size_t)(b*NT + tk) * D3 + D + hh*HD, kv);
        float s = 0.f;
        #pragma unroll
        for (int i = 0; i < 64; i++) s += q[i] * kv[i];
        sim[j] = s;
    }
    float mx = sim[0];
    #pragma unroll
    for (int j = 1; j < F+1; j++) mx = fmaxf(mx, sim[j]);
    float l = 0.f;
    #pragma unroll
    for (int j = 0; j < F+1; j++) { sim[j] = __expf(sim[j] - mx); l += sim[j]; }
    float inv = 1.f / l;

    float o[64];
    #pragma unroll
    for (int i = 0; i < 64; i++) o[i] = 0.f;
    #pragma unroll
    for (int j = 0; j < F+1; j++) {
        int tk = (j == 0) ? 0 : (1 + (j-1)*NS + sp);
        float vv[64];
        load64h(qkv + (size_t)(b*NT + tk) * D3 + 2*D + hh*HD, vv);
        float p = sim[j] * inv;
        #pragma unroll
        for (int i = 0; i < 64; i++) o[i] += p * vv[i];
    }
    __half2* op = (__half2*)(O + (size_t)(b*NT + t) * D + hh*HD);
    #pragma unroll
    for (int i = 0; i < 32; i++)
        op[i] = __floats2half2_rn(o[2*i], o[2*i+1]);
}

// space attention: fp32 K/V smem tiles, grouped online softmax (8 keys/group)
__global__ void attn_space_kernel(const __half* __restrict__ qkv,
                                  __half* __restrict__ O)
{
    int bx = blockIdx.x;
    int bh = bx / F, fr = bx % F;
    int b = bh / H, hh = bh % H;
    int tid = threadIdx.x;
    int sp = tid;
    const int NK = NS + 1;

    __shared__ float Ks[64 * HD];
    __shared__ float Vs[64 * HD];

    float q[64], o[64];
    float m = -1e30f, l = 0.f;
    if (sp < NS) {
        load64h(qkv + (size_t)(b*NT + 1 + fr*NS + sp) * D3 + hh*HD, q);
        #pragma unroll
        for (int i = 0; i < 64; i++) { q[i] *= QSCALE; o[i] = 0.f; }
    }

    for (int t0 = 0; t0 < NK; t0 += 64) {
        __syncthreads();
        for (int e = tid; e < 64*32; e += 256) {
            int jj = e >> 5, d2 = e & 31;
            int j = t0 + jj;
            float2 kf = make_float2(0.f, 0.f), vf = kf;
            if (j < NK) {
                int tk = (j == 0) ? 0 : (1 + fr*NS + (j-1));
                const __half2* base = (const __half2*)(qkv + (size_t)(b*NT + tk) * D3 + hh*HD);
                kf = __half22float2(base[(D   >> 1) + d2]);
                vf = __half22float2(base[(2*D >> 1) + d2]);
            }
            Ks[jj*HD + 2*d2] = kf.x; Ks[jj*HD + 2*d2 + 1] = kf.y;
            Vs[jj*HD + 2*d2] = vf.x; Vs[jj*HD + 2*d2 + 1] = vf.y;
        }
        __syncthreads();

        if (sp < NS) {
            int lim = min(64, NK - t0);
            for (int g = 0; g < lim; g += 8) {
                int gl = min(8, lim - g);
                float sg[8];
                float gm = -1e30f;
                for (int j = 0; j < gl; j++) {
                    const float4* kr = (const float4*)&Ks[(g + j) * HD];
                    float s = 0.f;
                    #pragma unroll
                    for (int i = 0; i < 16; i++) {
                        float4 kk = kr[i];
                        s += q[4*i]*kk.x + q[4*i+1]*kk.y + q[4*i+2]*kk.z + q[4*i+3]*kk.w;
                    }
                    sg[j] = s;
                    gm = fmaxf(gm, s);
                }
                float mn = fmaxf(m, gm);
                float fac = __expf(m - mn);       // == 1.0 when m unchanged
                l *= fac;
                #pragma unroll
                for (int i = 0; i < 64; i++) o[i] *= fac;
                m = mn;
                for (int j = 0; j < gl; j++) {
                    float p = __expf(sg[j] - m);
                    l += p;
                    const float4* vr = (const float4*)&Vs[(g + j) * HD];
                    #pragma unroll
                    for (int i = 0; i < 16; i++) {
                        float4 vv = vr[i];
                        o[4*i]   = fmaf(p, vv.x, o[4*i]);
                        o[4*i+1] = fmaf(p, vv.y, o[4*i+1]);
                        o[4*i+2] = fmaf(p, vv.z, o[4*i+2]);
                        o[4*i+3] = fmaf(p, vv.w, o[4*i+3]);
                    }
                }
            }
        }
    }

    if (sp < NS) {
        float inv = 1.f / l;
        __half2* op = (__half2*)(O + (size_t)(b*NT + 1 + fr*NS + sp) * D + hh*HD);
        #pragma unroll
        for (int i = 0; i < 32; i++)
            op[i] = __floats2half2_rn(o[2*i]*inv, o[2*i+1]*inv);
    }
}

// ---------------- host launch ------------------------------------------------
extern "C" void kernel_launch(void* const* d_in, const int* in_sizes, int n_in,
                              void* d_out, int out_size)
{
    const float* x      = (const float*)d_in[0];
    const float* n1g    = (const float*)d_in[1];
    const float* n1b    = (const float*)d_in[2];
    const float* n2g    = (const float*)d_in[3];
    const float* n2b    = (const float*)d_in[4];
    const float* n3g    = (const float*)d_in[5];
    const float* n3b    = (const float*)d_in[6];
    const float* aqkvw  = (const float*)d_in[7];
    const float* aqkvb  = (const float*)d_in[8];
    const float* aprojw = (const float*)d_in[9];
    const float* aprojb = (const float*)d_in[10];
    const float* tqkvw  = (const float*)d_in[11];
    const float* tqkvb  = (const float*)d_in[12];
    const float* tprojw = (const float*)d_in[13];
    const float* tprojb = (const float*)d_in[14];
    const float* fc1w   = (const float*)d_in[15];
    const float* fc1b   = (const float*)d_in[16];
    const float* fc2w   = (const float*)d_in[17];
    const float* fc2b   = (const float*)d_in[18];
    float* out = (float*)d_out;

    __half *lnf, *attf, *hidf, *qkvh;
    __half *wf_tqkv, *wf_aqkv, *wf_tproj, *wf_aproj, *wf_fc1, *wf_fc2;
    float *btres, *bsres;
    cudaGetSymbolAddress((void**)&lnf,  g_lnf);
    cudaGetSymbolAddress((void**)&attf, g_attf);
    cudaGetSymbolAddress((void**)&hidf, g_hidf);
    cudaGetSymbolAddress((void**)&qkvh, g_qkvh);
    cudaGetSymbolAddress((void**)&btres,g_tres);
    cudaGetSymbolAddress((void**)&bsres,g_sres);
    cudaGetSymbolAddress((void**)&wf_tqkv, g_wf_tqkv);
    cudaGetSymbolAddress((void**)&wf_aqkv, g_wf_aqkv);
    cudaGetSymbolAddress((void**)&wf_tproj,g_wf_tproj);
    cudaGetSymbolAddress((void**)&wf_aproj,g_wf_aproj);
    cudaGetSymbolAddress((void**)&wf_fc1,  g_wf_fc1);
    cudaGetSymbolAddress((void**)&wf_fc2,  g_wf_fc2);

    cudaFuncSetAttribute(gemm_f16<1>, cudaFuncAttributeMaxDynamicSharedMemorySize, SMEM_F16);
    cudaFuncSetAttribute(gemm_f16<4>, cudaFuncAttributeMaxDynamicSharedMemorySize, SMEM_F16);
    cudaFuncSetAttribute(gemm_f16<5>, cudaFuncAttributeMaxDynamicSharedMemorySize, SMEM_F16);

    const int MT = (M + BM - 1) / BM;    // 99
    dim3 tb(32, 8);
    const int nTimeBlocks = (B*H*NS*F) / 256;   // 588

    tf16_kernel<<<dim3(D3/32, D/32), tb>>>(tqkvw, wf_tqkv, D, D3);   // 0
    tf16_kernel<<<dim3(D3/32, D/32), tb>>>(aqkvw, wf_aqkv, D, D3);   // 1
    tf16_kernel<<<dim3(D/32,  D/32), tb>>>(tprojw, wf_tproj, D, D);  // 2
    tf16_kernel<<<dim3(D/32,  D/32), tb>>>(aprojw, wf_aproj, D, D);  // 3
    ln_f16_kernel<<<M, 256>>>(x, n3g, n3b, lnf);                     // 4
    gemm_f16<5><<<dim3(D3/BN, MT), 256, SMEM_F16>>>(lnf, wf_tqkv, tqkvb, nullptr, nullptr, qkvh, M, D, D3);  // 5 <- profiled
    attn_cls_kernel <<<B*H, 256>>>(qkvh, attf);
    attn_time_kernel<<<nTimeBlocks, 256>>>(qkvh, attf);
    gemm_f16<1><<<dim3(D/BN, MT), 256, SMEM_F16>>>(attf, wf_tproj, tprojb, x, btres, nullptr, M, D, D);

    // ---- space attention branch ----
    ln_f16_kernel<<<M, 256>>>(btres, n1g, n1b, lnf);
    gemm_f16<5><<<dim3(D3/BN, MT), 256, SMEM_F16>>>(lnf, wf_aqkv, aqkvb, nullptr, nullptr, qkvh, M, D, D3);
    attn_cls_kernel  <<<B*H, 256>>>(qkvh, attf);
    attn_space_kernel<<<B*H*F, 256>>>(qkvh, attf);
    gemm_f16<1><<<dim3(D/BN, MT), 256, SMEM_F16>>>(attf, wf_aproj, aprojb, x, bsres, nullptr, M, D, D);

    // ---- MLP ----
    tf16_kernel<<<dim3(D4/32, D/32), tb>>>(fc1w, wf_fc1, D, D4);
    tf16_kernel<<<dim3(D/32, D4/32), tb>>>(fc2w, wf_fc2, D4, D);
    ln_f16_kernel<<<M, 256>>>(bsres, n2g, n2b, lnf);
    gemm_f16<4><<<dim3(D4/BN, MT), 256, SMEM_F16>>>(lnf, wf_fc1, fc1b, nullptr, nullptr, hidf, M, D, D4);
    gemm_f16<1><<<dim3(D/BN, MT), 256, SMEM_F16>>>(hidf, wf_fc2, fc2b, bsres, out, nullptr, M, D4, D);
}

// round 14
// speedup vs baseline: 4.6159x; 1.0328x over previous
#include <cuda_runtime.h>
#include <cuda_fp16.h>
#include <math.h>
#include <cstdint>

// ---------------- problem constants ----------------------------------------
constexpr int B   = 8;
constexpr int F   = 8;
constexpr int NS  = 196;
constexpr int NT  = 1 + F*NS;   // 1569
constexpr int D   = 768;
constexpr int H   = 12;
constexpr int HD  = 64;
constexpr int D3  = 3*D;        // 2304
constexpr int D4  = 4*D;        // 3072
constexpr int M   = B*NT;       // 12552
constexpr float LN_EPS = 1e-5f;
constexpr float QSCALE = 0.125f;
constexpr int NSPL = 8;
constexpr int SPAN = (NT + NSPL - 1) / NSPL;  // 197

// ---------------- scratch (device globals; no allocation) ------------------
__device__ __half g_lnf [(size_t)M * D];
__device__ __half g_qkvh[(size_t)M * D3];
__device__ __half g_attf[(size_t)M * D];
__device__ float  g_tres[(size_t)M * D];
__device__ float  g_sres[(size_t)M * D];
__device__ __half g_hidf[(size_t)M * D4];
__device__ float  g_clsp[B*H*NSPL*66];
// transposed fp16 weights: Wt[n][k] = W[k][n]
__device__ __half g_wf_tqkv [(size_t)D3*D];
__device__ __half g_wf_aqkv [(size_t)D3*D];
__device__ __half g_wf_tproj[(size_t)D*D];
__device__ __half g_wf_aproj[(size_t)D*D];
__device__ __half g_wf_fc1  [(size_t)D4*D];
__device__ __half g_wf_fc2  [(size_t)D*D4];

// ---------------- helpers ----------------------------------------------------
__device__ __forceinline__ uint32_t smem_to_u32(const void* p) {
    uint32_t a;
    asm("{ .reg .u64 t; cvta.to.shared.u64 t, %1; cvt.u32.u64 %0, t; }"
        : "=r"(a) : "l"(p));
    return a;
}
__device__ __forceinline__ void cp_async16(uint32_t dst, const void* src, bool valid) {
    int sz = valid ? 16 : 0;
    asm volatile("cp.async.cg.shared.global [%0], [%1], 16, %2;"
                 :: "r"(dst), "l"(src), "r"(sz) : "memory");
}
#define CP_COMMIT()  asm volatile("cp.async.commit_group;" ::: "memory")
#define CP_WAIT(n)   asm volatile("cp.async.wait_group %0;" :: "n"(n) : "memory")

__device__ __forceinline__ void ldsm_x4(uint32_t& r0, uint32_t& r1, uint32_t& r2, uint32_t& r3, uint32_t addr) {
    asm volatile("ldmatrix.sync.aligned.m8n8.x4.shared.b16 {%0,%1,%2,%3}, [%4];"
                 : "=r"(r0), "=r"(r1), "=r"(r2), "=r"(r3) : "r"(addr));
}
__device__ __forceinline__ void mma_f16(float* c, const uint32_t* a, const uint32_t* b) {
    asm volatile(
        "mma.sync.aligned.m16n8k16.row.col.f32.f16.f16.f32 "
        "{%0,%1,%2,%3}, {%4,%5,%6,%7}, {%8,%9}, {%0,%1,%2,%3};"
        : "+f"(c[0]), "+f"(c[1]), "+f"(c[2]), "+f"(c[3])
        : "r"(a[0]), "r"(a[1]), "r"(a[2]), "r"(a[3]), "r"(b[0]), "r"(b[1]));
}
__device__ __forceinline__ float gelu_exact(float v) {
    return 0.5f * v * (1.f + erff(v * 0.70710678118654752f));
}
__device__ __forceinline__ void unpack8(const uint4& u, float* dst) {
    const __half2* h = (const __half2*)&u;
    #pragma unroll
    for (int j = 0; j < 4; j++) {
        float2 f = __half22float2(h[j]);
        dst[2*j]   = f.x;
        dst[2*j+1] = f.y;
    }
}
__device__ __forceinline__ void load64h(const __half* p, float* dst) {
    const uint4* u = (const uint4*)p;
    #pragma unroll
    for (int i = 0; i < 8; i++) {
        uint4 v = u[i];
        unpack8(v, dst + 8*i);
    }
}

// ================= fp16 single-pass GEMM (3-stage, 2 CTAs/SM) =================
constexpr int BM = 128, BN = 128, FBK = 64;
constexpr int FRSB = 144;
constexpr int FMAT = 128 * FRSB;        // 18432
constexpr int FSTAGE = 2 * FMAT;        // 36864
constexpr int SMEM_F16 = 3 * FSTAGE;    // 110592 -> 2 CTAs/SM

// EPI: 1 = bias+residual -> fp32 C ; 4 = bias+GELU -> fp16 Ch ; 5 = bias -> fp16 Ch
template<int EPI>
__global__ void __launch_bounds__(256, 2)
gemm_f16(const __half* __restrict__ A, const __half* __restrict__ Bw,
         const float* __restrict__ bias, const float* __restrict__ R,
         float* __restrict__ C, __half* __restrict__ Ch,
         int Mr, int K, int Nc)
{
    extern __shared__ char smem[];
    const uint32_t sb = smem_to_u32(smem);
    const int tid = threadIdx.x;
    const int wid = tid >> 5, lane = tid & 31;
    const int wm = wid & 1, wn = wid >> 1;
    const int bm = blockIdx.y * BM, bn = blockIdx.x * BN;

    float acc[4][4][4];
    #pragma unroll
    for (int i = 0; i < 4; i++)
        #pragma unroll
        for (int j = 0; j < 4; j++)
            #pragma unroll
            for (int q = 0; q < 4; q++) acc[i][j][q] = 0.f;

    auto load_stage = [&](int stage, int k0) {
        uint32_t base = sb + stage * FSTAGE;
        #pragma unroll
        for (int i = 0; i < 4; i++) {
            int idx = tid + i*256;
            int r = idx >> 3, cb = (idx & 7) << 4;
            int gr = bm + r;
            bool v = gr < Mr;
            cp_async16(base + r*FRSB + cb, (const char*)(A + (size_t)(v?gr:0)*K + k0) + cb, v);
        }
        #pragma unroll
        for (int i = 0; i < 4; i++) {
            int idx = tid + i*256;
            int r = idx >> 3, cb = (idx & 7) << 4;
            cp_async16(base + FMAT + r*FRSB + cb, (const char*)(Bw + (size_t)(bn + r)*K + k0) + cb, true);
        }
        CP_COMMIT();
    };

    const int NC = K / FBK;
    load_stage(0, 0);
    load_stage(1, FBK);

    const int aRow = (lane & 15);
    const int aColB = (lane >> 4) * 16;
    const int bMtx = lane >> 3, bRit = lane & 7;
    const int bNrow = (bMtx & 2) ? (8 + bRit) : bRit;
    const int bKoff = (bMtx & 1) * 16;

    int s = 0;
    for (int c = 0; c < NC; c++) {
        // chunk c's group complete: (wait -> barrier) gives cross-warp visibility
        if (c + 1 < NC) { CP_WAIT(1); } else { CP_WAIT(0); }
        __syncthreads();
        // stage s+2 was last read for chunk c-1 (finished before the barrier)
        if (c + 2 < NC) {
            int s2 = s + 2; if (s2 >= 3) s2 -= 3;
            load_stage(s2, (c + 2) * FBK);
        }

        uint32_t aB = sb + s * FSTAGE;
        uint32_t bB = aB + FMAT;

        #pragma unroll
        for (int kk = 0; kk < 4; kk++) {
            uint32_t af[4][4], bf[4][2];
            #pragma unroll
            for (int mt = 0; mt < 4; mt++) {
                uint32_t off = (uint32_t)((wm*64 + mt*16 + aRow) * FRSB + kk*32 + aColB);
                ldsm_x4(af[mt][0], af[mt][1], af[mt][2], af[mt][3], aB + off);
            }
            #pragma unroll
            for (int np = 0; np < 2; np++) {
                uint32_t off = (uint32_t)((wn*32 + np*16 + bNrow) * FRSB + kk*32 + bKoff);
                ldsm_x4(bf[2*np][0], bf[2*np][1], bf[2*np+1][0], bf[2*np+1][1], bB + off);
            }
            #pragma unroll
            for (int mt = 0; mt < 4; mt++)
                #pragma unroll
                for (int nt = 0; nt < 4; nt++)
                    mma_f16(acc[mt][nt], af[mt], bf[nt]);
        }
        if (++s == 3) s = 0;
    }

    const int er = lane >> 2, ec = (lane & 3) * 2;
    #pragma unroll
    for (int mt = 0; mt < 4; mt++) {
        int r0 = bm + wm*64 + mt*16 + er;
        int r1 = r0 + 8;
        #pragma unroll
        for (int nt = 0; nt < 4; nt++) {
            int cc = bn + wn*32 + nt*8 + ec;
            float b0 = bias[cc], b1 = bias[cc + 1];
            if (r0 < Mr) {
                float v0 = acc[mt][nt][0] + b0;
                float v1 = acc[mt][nt][1] + b1;
                size_t off = (size_t)r0 * Nc + cc;
                if (EPI == 1) {
                    C[off] = v0 + R[off]; C[off + 1] = v1 + R[off + 1];
                } else if (EPI == 4) {
                    *(__half2*)&Ch[off] = __floats2half2_rn(gelu_exact(v0), gelu_exact(v1));
                } else {
                    *(__half2*)&Ch[off] = __floats2half2_rn(v0, v1);
                }
            }
            if (r1 < Mr) {
                float v2 = acc[mt][nt][2] + b0;
                float v3 = acc[mt][nt][3] + b1;
                size_t off = (size_t)r1 * Nc + cc;
                if (EPI == 1) {
                    C[off] = v2 + R[off]; C[off + 1] = v3 + R[off + 1];
                } else if (EPI == 4) {
                    *(__half2*)&Ch[off] = __floats2half2_rn(gelu_exact(v2), gelu_exact(v3));
                } else {
                    *(__half2*)&Ch[off] = __floats2half2_rn(v2, v3);
                }
            }
        }
    }
}

// ---------------- LayerNorm -> fp16 -------------------------------------------
__global__ void ln_f16_kernel(const float* __restrict__ X,
                              const float* __restrict__ gam,
                              const float* __restrict__ bet,
                              __half* __restrict__ Y)
{
    int row = blockIdx.x;
    const float* x = X + (size_t)row * D;
    int tid = threadIdx.x;

    float s = 0.f, ss = 0.f;
    for (int i = tid; i < D; i += 256) { float v = x[i]; s += v; ss += v*v; }
    __shared__ float rs[32], rss[32];
    for (int o = 16; o > 0; o >>= 1) {
        s  += __shfl_xor_sync(0xffffffffu, s,  o);
        ss += __shfl_xor_sync(0xffffffffu, ss, o);
    }
    int wid = tid >> 5, lid = tid & 31;
    if (lid == 0) { rs[wid] = s; rss[wid] = ss; }
    __syncthreads();
    __shared__ float s_mean, s_inv;
    if (tid == 0) {
        float ts = 0.f, tss = 0.f;
        for (int w = 0; w < 8; w++) { ts += rs[w]; tss += rss[w]; }
        float mean = ts * (1.f/D);
        float var  = tss * (1.f/D) - mean*mean;
        s_mean = mean; s_inv = rsqrtf(var + LN_EPS);
    }
    __syncthreads();
    float mean = s_mean, inv = s_inv;
    for (int i = tid; i < D; i += 256)
        Y[(size_t)row*D + i] = __float2half((x[i] - mean) * inv * gam[i] + bet[i]);
}

// ---------------- weight transpose -> fp16 -------------------------------------
__global__ void tf16_kernel(const float* __restrict__ W,
                            __half* __restrict__ T, int K, int N)
{
    __shared__ float t[32][33];
    int n0 = blockIdx.x * 32, k0 = blockIdx.y * 32;
    int tx = threadIdx.x, ty = threadIdx.y;
    for (int i = ty; i < 32; i += 8)
        t[i][tx] = W[(size_t)(k0 + i) * N + n0 + tx];
    __syncthreads();
    for (int r = ty; r < 32; r += 8)
        T[(size_t)(n0 + r) * K + k0 + tx] = __float2half(t[tx][r]);
}

// ---------------- cls attention: split-K phase 1 -------------------------------
__global__ void attn_cls_p1(const __half* __restrict__ qkv,
                            float* __restrict__ P)
{
    int bx = blockIdx.x;
    int bh = bx / NSPL, sl = bx % NSPL;
    int b = bh / H, hh = bh % H;
    int tid = threadIdx.x;
    int j0 = sl * SPAN;
    int j1 = min(NT, j0 + SPAN);

    __shared__ float qs[HD];
    __shared__ float sim[SPAN];
    __shared__ float red[256];
    __shared__ float red2[4][HD];

    if (tid < HD)
        qs[tid] = __half2float(qkv[(size_t)(b*NT) * D3 + hh*HD + tid]) * QSCALE;
    __syncthreads();

    float lmx = -1e30f;
    for (int j = j0 + tid; j < j1; j += 256) {
        const __half* kp = qkv + (size_t)(b*NT + j) * D3 + D + hh*HD;
        float kv[64];
        load64h(kp, kv);
        float s = 0.f;
        #pragma unroll
        for (int d = 0; d < HD; d++) s += qs[d] * kv[d];
        sim[j - j0] = s;
        lmx = fmaxf(lmx, s);
    }
    red[tid] = lmx; __syncthreads();
    for (int st = 128; st > 0; st >>= 1) {
        if (tid < st) red[tid] = fmaxf(red[tid], red[tid+st]);
        __syncthreads();
    }
    float mx = red[0];
    __syncthreads();

    float ls = 0.f;
    for (int j = j0 + tid; j < j1; j += 256) {
        float e = __expf(sim[j - j0] - mx);
        sim[j - j0] = e;
        ls += e;
    }
    red[tid] = ls; __syncthreads();
    for (int st = 128; st > 0; st >>= 1) {
        if (tid < st) red[tid] += red[tid+st];
        __syncthreads();
    }
    float lsum = red[0];
    __syncthreads();

    int d = tid & 63, p = tid >> 6;
    float acc = 0.f;
    for (int j = j0 + p; j < j1; j += 4)
        acc += sim[j - j0] * __half2float(qkv[(size_t)(b*NT + j) * D3 + 2*D + hh*HD + d]);
    red2[p][d] = acc;
    __syncthreads();
    if (p == 0) {
        float o = red2[0][d] + red2[1][d] + red2[2][d] + red2[3][d];
        float* dst = P + (size_t)(bh*NSPL + sl) * 66;
        dst[d] = o;
        if (d == 0) { dst[64] = mx; dst[65] = lsum; }
    }
}

// ---------------- cls attention: merge phase ----------------------------------
__global__ void attn_cls_p2(const float* __restrict__ P,
                            __half* __restrict__ O)
{
    int bh = blockIdx.x;
    int b = bh / H, hh = bh % H;
    int d = threadIdx.x;   // 64 threads

    const float* base = P + (size_t)bh * NSPL * 66;
    float mg = -1e30f;
    #pragma unroll
    for (int sl = 0; sl < NSPL; sl++) mg = fmaxf(mg, base[sl*66 + 64]);
    float lg = 0.f, og = 0.f;
    #pragma unroll
    for (int sl = 0; sl < NSPL; sl++) {
        float w = __expf(base[sl*66 + 64] - mg);
        lg += base[sl*66 + 65] * w;
        og += base[sl*66 + d] * w;
    }
    O[(size_t)(b*NT) * D + hh*HD + d] = __float2half(og / lg);
}

// ---------------- time attention -----------------------------------------------
__global__ void attn_time_kernel(const __half* __restrict__ qkv,
                                 __half* __restrict__ O)
{
    int qid = blockIdx.x * blockDim.x + threadIdx.x;
    int fr = qid % F;
    int sp = (qid / F) % NS;
    int bh = qid / (F * NS);
    int b = bh / H, hh = bh % H;
    int t = 1 + fr*NS + sp;

    float q[64];
    load64h(qkv + (size_t)(b*NT + t) * D3 + hh*HD, q);
    #pragma unroll
    for (int i = 0; i < 64; i++) q[i] *= QSCALE;

    float sim[F+1];
    #pragma unroll
    for (int j = 0; j < F+1; j++) {
        int tk = (j == 0) ? 0 : (1 + (j-1)*NS + sp);
        float kv[64];
        load64h(qkv + (size_t)(b*NT + tk) * D3 + D + hh*HD, kv);
        float s = 0.f;
        #pragma unroll
        for (int i = 0; i < 64; i++) s += q[i] * kv[i];
        sim[j] = s;
    }
    float mx = sim[0];
    #pragma unroll
    for (int j = 1; j < F+1; j++) mx = fmaxf(mx, sim[j]);
    float l = 0.f;
    #pragma unroll
    for (int j = 0; j < F+1; j++) { sim[j] = __expf(sim[j] - mx); l += sim[j]; }
    float inv = 1.f / l;

    float o[64];
    #pragma unroll
    for (int i = 0; i < 64; i++) o[i] = 0.f;
    #pragma unroll
    for (int j = 0; j < F+1; j++) {
        int tk = (j == 0) ? 0 : (1 + (j-1)*NS + sp);
        float vv[64];
        load64h(qkv + (size_t)(b*NT + tk) * D3 + 2*D + hh*HD, vv);
        float p = sim[j] * inv;
        #pragma unroll
        for (int i = 0; i < 64; i++) o[i] += p * vv[i];
    }
    __half2* op = (__half2*)(O + (size_t)(b*NT + t) * D + hh*HD);
    #pragma unroll
    for (int i = 0; i < 32; i++)
        op[i] = __floats2half2_rn(o[2*i], o[2*i+1]);
}

// ---------------- space attention -----------------------------------------------
__global__ void attn_space_kernel(const __half* __restrict__ qkv,
                                  __half* __restrict__ O)
{
    int bx = blockIdx.x;
    int bh = bx / F, fr = bx % F;
    int b = bh / H, hh = bh % H;
    int tid = threadIdx.x;
    int sp = tid;
    const int NK = NS + 1;

    __shared__ float Ks[64 * HD];
    __shared__ float Vs[64 * HD];

    float q[64], o[64];
    float m = -1e30f, l = 0.f;
    if (sp < NS) {
        load64h(qkv + (size_t)(b*NT + 1 + fr*NS + sp) * D3 + hh*HD, q);
        #pragma unroll
        for (int i = 0; i < 64; i++) { q[i] *= QSCALE; o[i] = 0.f; }
    }

    for (int t0 = 0; t0 < NK; t0 += 64) {
        __syncthreads();
        for (int e = tid; e < 64*32; e += 256) {
            int jj = e >> 5, d2 = e & 31;
            int j = t0 + jj;
            float2 kf = make_float2(0.f, 0.f), vf = kf;
            if (j < NK) {
                int tk = (j == 0) ? 0 : (1 + fr*NS + (j-1));
                const __half2* base = (const __half2*)(qkv + (size_t)(b*NT + tk) * D3 + hh*HD);
                kf = __half22float2(base[(D   >> 1) + d2]);
                vf = __half22float2(base[(2*D >> 1) + d2]);
            }
            Ks[jj*HD + 2*d2] = kf.x; Ks[jj*HD + 2*d2 + 1] = kf.y;
            Vs[jj*HD + 2*d2] = vf.x; Vs[jj*HD + 2*d2 + 1] = vf.y;
        }
        __syncthreads();

        if (sp < NS) {
            int lim = min(64, NK - t0);
            for (int g = 0; g < lim; g += 8) {
                int gl = min(8, lim - g);
                float sg[8];
                float gm = -1e30f;
                for (int j = 0; j < gl; j++) {
                    const float4* kr = (const float4*)&Ks[(g + j) * HD];
                    float s = 0.f;
                    #pragma unroll
                    for (int i = 0; i < 16; i++) {
                        float4 kk = kr[i];
                        s += q[4*i]*kk.x + q[4*i+1]*kk.y + q[4*i+2]*kk.z + q[4*i+3]*kk.w;
                    }
                    sg[j] = s;
                    gm = fmaxf(gm, s);
                }
                float mn = fmaxf(m, gm);
                float fac = __expf(m - mn);
                l *= fac;
                #pragma unroll
                for (int i = 0; i < 64; i++) o[i] *= fac;
                m = mn;
                for (int j = 0; j < gl; j++) {
                    float p = __expf(sg[j] - m);
                    l += p;
                    const float4* vr = (const float4*)&Vs[(g + j) * HD];
                    #pragma unroll
                    for (int i = 0; i < 16; i++) {
                        float4 vv = vr[i];
                        o[4*i]   = fmaf(p, vv.x, o[4*i]);
                        o[4*i+1] = fmaf(p, vv.y, o[4*i+1]);
                        o[4*i+2] = fmaf(p, vv.z, o[4*i+2]);
                        o[4*i+3] = fmaf(p, vv.w, o[4*i+3]);
                    }
                }
            }
        }
    }

    if (sp < NS) {
        float inv = 1.f / l;
        __half2* op = (__half2*)(O + (size_t)(b*NT + 1 + fr*NS + sp) * D + hh*HD);
        #pragma unroll
        for (int i = 0; i < 32; i++)
            op[i] = __floats2half2_rn(o[2*i]*inv, o[2*i+1]*inv);
    }
}

// ---------------- host launch ------------------------------------------------
extern "C" void kernel_launch(void* const* d_in, const int* in_sizes, int n_in,
                              void* d_out, int out_size)
{
    const float* x      = (const float*)d_in[0];
    const float* n1g    = (const float*)d_in[1];
    const float* n1b    = (const float*)d_in[2];
    const float* n2g    = (const float*)d_in[3];
    const float* n2b    = (const float*)d_in[4];
    const float* n3g    = (const float*)d_in[5];
    const float* n3b    = (const float*)d_in[6];
    const float* aqkvw  = (const float*)d_in[7];
    const float* aqkvb  = (const float*)d_in[8];
    const float* aprojw = (const float*)d_in[9];
    const float* aprojb = (const float*)d_in[10];
    const float* tqkvw  = (const float*)d_in[11];
    const float* tqkvb  = (const float*)d_in[12];
    const float* tprojw = (const float*)d_in[13];
    const float* tprojb = (const float*)d_in[14];
    const float* fc1w   = (const float*)d_in[15];
    const float* fc1b   = (const float*)d_in[16];
    const float* fc2w   = (const float*)d_in[17];
    const float* fc2b   = (const float*)d_in[18];
    float* out = (float*)d_out;

    __half *lnf, *attf, *hidf, *qkvh;
    __half *wf_tqkv, *wf_aqkv, *wf_tproj, *wf_aproj, *wf_fc1, *wf_fc2;
    float *btres, *bsres, *clsp;
    cudaGetSymbolAddress((void**)&lnf,  g_lnf);
    cudaGetSymbolAddress((void**)&attf, g_attf);
    cudaGetSymbolAddress((void**)&hidf, g_hidf);
    cudaGetSymbolAddress((void**)&qkvh, g_qkvh);
    cudaGetSymbolAddress((void**)&btres,g_tres);
    cudaGetSymbolAddress((void**)&bsres,g_sres);
    cudaGetSymbolAddress((void**)&clsp, g_clsp);
    cudaGetSymbolAddress((void**)&wf_tqkv, g_wf_tqkv);
    cudaGetSymbolAddress((void**)&wf_aqkv, g_wf_aqkv);
    cudaGetSymbolAddress((void**)&wf_tproj,g_wf_tproj);
    cudaGetSymbolAddress((void**)&wf_aproj,g_wf_aproj);
    cudaGetSymbolAddress((void**)&wf_fc1,  g_wf_fc1);
    cudaGetSymbolAddress((void**)&wf_fc2,  g_wf_fc2);

    cudaFuncSetAttribute(gemm_f16<1>, cudaFuncAttributeMaxDynamicSharedMemorySize, SMEM_F16);
    cudaFuncSetAttribute(gemm_f16<4>, cudaFuncAttributeMaxDynamicSharedMemorySize, SMEM_F16);
    cudaFuncSetAttribute(gemm_f16<5>, cudaFuncAttributeMaxDynamicSharedMemorySize, SMEM_F16);

    const int MT = (M + BM - 1) / BM;    // 99
    dim3 tb(32, 8);
    const int nTimeBlocks = (B*H*NS*F) / 256;   // 588

    tf16_kernel<<<dim3(D3/32, D/32), tb>>>(tqkvw, wf_tqkv, D, D3);
    tf16_kernel<<<dim3(D3/32, D/32), tb>>>(aqkvw, wf_aqkv, D, D3);
    tf16_kernel<<<dim3(D/32,  D/32), tb>>>(tprojw, wf_tproj, D, D);
    tf16_kernel<<<dim3(D/32,  D/32), tb>>>(aprojw, wf_aproj, D, D);
    ln_f16_kernel<<<M, 256>>>(x, n3g, n3b, lnf);
    gemm_f16<5><<<dim3(D3/BN, MT), 256, SMEM_F16>>>(lnf, wf_tqkv, tqkvb, nullptr, nullptr, qkvh, M, D, D3);
    attn_cls_p1<<<B*H*NSPL, 256>>>(qkvh, clsp);
    attn_cls_p2<<<B*H, 64>>>(clsp, attf);
    attn_time_kernel<<<nTimeBlocks, 256>>>(qkvh, attf);
    gemm_f16<1><<<dim3(D/BN, MT), 256, SMEM_F16>>>(attf, wf_tproj, tprojb, x, btres, nullptr, M, D, D);

    // ---- space attention branch ----
    ln_f16_kernel<<<M, 256>>>(btres, n1g, n1b, lnf);
    gemm_f16<5><<<dim3(D3/BN, MT), 256, SMEM_F16>>>(lnf, wf_aqkv, aqkvb, nullptr, nullptr, qkvh, M, D, D3);
    attn_cls_p1<<<B*H*NSPL, 256>>>(qkvh, clsp);
    attn_cls_p2<<<B*H, 64>>>(clsp, attf);
    attn_space_kernel<<<B*H*F, 256>>>(qkvh, attf);
    gemm_f16<1><<<dim3(D/BN, MT), 256, SMEM_F16>>>(attf, wf_aproj, aprojb, x, bsres, nullptr, M, D, D);

    // ---- MLP ----
    tf16_kernel<<<dim3(D4/32, D/32), tb>>>(fc1w, wf_fc1, D, D4);
    tf16_kernel<<<dim3(D/32, D4/32), tb>>>(fc2w, wf_fc2, D4, D);
    ln_f16_kernel<<<M, 256>>>(bsres, n2g, n2b, lnf);
    gemm_f16<4><<<dim3(D4/BN, MT), 256, SMEM_F16>>>(lnf, wf_fc1, fc1b, nullptr, nullptr, hidf, M, D, D4);
    gemm_f16<1><<<dim3(D/BN, MT), 256, SMEM_F16>>>(hidf, wf_fc2, fc2b, bsres, out, nullptr, M, D4, D);
}

// round 15
// speedup vs baseline: 4.6802x; 1.0139x over previous
#include <cuda_runtime.h>
#include <cuda_fp16.h>
#include <math.h>
#include <cstdint>

// ---------------- problem constants ----------------------------------------
constexpr int B   = 8;
constexpr int F   = 8;
constexpr int NS  = 196;
constexpr int NT  = 1 + F*NS;   // 1569
constexpr int D   = 768;
constexpr int H   = 12;
constexpr int HD  = 64;
constexpr int D3  = 3*D;        // 2304
constexpr int D4  = 4*D;        // 3072
constexpr int M   = B*NT;       // 12552
constexpr float LN_EPS = 1e-5f;
constexpr float QSCALE = 0.125f;
constexpr int NSPL = 8;
constexpr int SPAN = (NT + NSPL - 1) / NSPL;  // 197

// ---------------- scratch (device globals; no allocation) ------------------
__device__ __half g_lnf [(size_t)M * D];
__device__ __half g_qkvh[(size_t)M * D3];
__device__ __half g_attf[(size_t)M * D];
__device__ float  g_tres[(size_t)M * D];
__device__ float  g_sres[(size_t)M * D];
__device__ __half g_hidf[(size_t)M * D4];
__device__ float  g_clsp[B*H*NSPL*66];
// transposed fp16 weights: Wt[n][k] = W[k][n]
__device__ __half g_wf_tqkv [(size_t)D3*D];
__device__ __half g_wf_aqkv [(size_t)D3*D];
__device__ __half g_wf_tproj[(size_t)D*D];
__device__ __half g_wf_aproj[(size_t)D*D];
__device__ __half g_wf_fc1  [(size_t)D4*D];
__device__ __half g_wf_fc2  [(size_t)D*D4];

// ---------------- helpers ----------------------------------------------------
__device__ __forceinline__ uint32_t smem_to_u32(const void* p) {
    uint32_t a;
    asm("{ .reg .u64 t; cvta.to.shared.u64 t, %1; cvt.u32.u64 %0, t; }"
        : "=r"(a) : "l"(p));
    return a;
}
__device__ __forceinline__ void cp_async16(uint32_t dst, const void* src, bool valid) {
    int sz = valid ? 16 : 0;
    asm volatile("cp.async.cg.shared.global [%0], [%1], 16, %2;"
                 :: "r"(dst), "l"(src), "r"(sz) : "memory");
}
#define CP_COMMIT()  asm volatile("cp.async.commit_group;" ::: "memory")
#define CP_WAIT(n)   asm volatile("cp.async.wait_group %0;" :: "n"(n) : "memory")

__device__ __forceinline__ void ldsm_x4(uint32_t& r0, uint32_t& r1, uint32_t& r2, uint32_t& r3, uint32_t addr) {
    asm volatile("ldmatrix.sync.aligned.m8n8.x4.shared.b16 {%0,%1,%2,%3}, [%4];"
                 : "=r"(r0), "=r"(r1), "=r"(r2), "=r"(r3) : "r"(addr));
}
__device__ __forceinline__ void mma_f16(float* c, const uint32_t* a, const uint32_t* b) {
    asm volatile(
        "mma.sync.aligned.m16n8k16.row.col.f32.f16.f16.f32 "
        "{%0,%1,%2,%3}, {%4,%5,%6,%7}, {%8,%9}, {%0,%1,%2,%3};"
        : "+f"(c[0]), "+f"(c[1]), "+f"(c[2]), "+f"(c[3])
        : "r"(a[0]), "r"(a[1]), "r"(a[2]), "r"(a[3]), "r"(b[0]), "r"(b[1]));
}
__device__ __forceinline__ float gelu_exact(float v) {
    return 0.5f * v * (1.f + erff(v * 0.70710678118654752f));
}
__device__ __forceinline__ void unpack8(const uint4& u, float* dst) {
    const __half2* h = (const __half2*)&u;
    #pragma unroll
    for (int j = 0; j < 4; j++) {
        float2 f = __half22float2(h[j]);
        dst[2*j]   = f.x;
        dst[2*j+1] = f.y;
    }
}
__device__ __forceinline__ void load64h(const __half* p, float* dst) {
    const uint4* u = (const uint4*)p;
    #pragma unroll
    for (int i = 0; i < 8; i++) {
        uint4 v = u[i];
        unpack8(v, dst + 8*i);
    }
}

// ================= fp16 single-pass GEMM (3-stage, 2 CTAs/SM) =================
constexpr int BM = 128, BN = 128, FBK = 64;
constexpr int FRSB = 144;
constexpr int FMAT = 128 * FRSB;        // 18432
constexpr int FSTAGE = 2 * FMAT;        // 36864
constexpr int SMEM_F16 = 3 * FSTAGE;    // 110592 -> 2 CTAs/SM
constexpr int SROWH = 272;              // fp16 staging row stride (bytes)
constexpr int SROWF = 528;              // fp32 staging row stride (bytes)

// EPI: 1 = bias+residual -> fp32 C ; 4 = bias+GELU -> fp16 Ch ; 5 = bias -> fp16 Ch
template<int EPI>
__global__ void __launch_bounds__(256, 2)
gemm_f16(const __half* __restrict__ A, const __half* __restrict__ Bw,
         const float* __restrict__ bias, const float* __restrict__ R,
         float* __restrict__ C, __half* __restrict__ Ch,
         int Mr, int K, int Nc)
{
    extern __shared__ char smem[];
    const uint32_t sb = smem_to_u32(smem);
    const int tid = threadIdx.x;
    const int wid = tid >> 5, lane = tid & 31;
    const int wm = wid & 1, wn = wid >> 1;
    const int bm = blockIdx.y * BM, bn = blockIdx.x * BN;

    float acc[4][4][4];
    #pragma unroll
    for (int i = 0; i < 4; i++)
        #pragma unroll
        for (int j = 0; j < 4; j++)
            #pragma unroll
            for (int q = 0; q < 4; q++) acc[i][j][q] = 0.f;

    auto load_stage = [&](int stage, int k0) {
        uint32_t base = sb + stage * FSTAGE;
        #pragma unroll
        for (int i = 0; i < 4; i++) {
            int idx = tid + i*256;
            int r = idx >> 3, cb = (idx & 7) << 4;
            int gr = bm + r;
            bool v = gr < Mr;
            cp_async16(base + r*FRSB + cb, (const char*)(A + (size_t)(v?gr:0)*K + k0) + cb, v);
        }
        #pragma unroll
        for (int i = 0; i < 4; i++) {
            int idx = tid + i*256;
            int r = idx >> 3, cb = (idx & 7) << 4;
            cp_async16(base + FMAT + r*FRSB + cb, (const char*)(Bw + (size_t)(bn + r)*K + k0) + cb, true);
        }
        CP_COMMIT();
    };

    const int NC = K / FBK;
    load_stage(0, 0);
    load_stage(1, FBK);

    const int aRow = (lane & 15);
    const int aColB = (lane >> 4) * 16;
    const int bMtx = lane >> 3, bRit = lane & 7;
    const int bNrow = (bMtx & 2) ? (8 + bRit) : bRit;
    const int bKoff = (bMtx & 1) * 16;

    int s = 0;
    for (int c = 0; c < NC; c++) {
        if (c + 1 < NC) { CP_WAIT(1); } else { CP_WAIT(0); }
        __syncthreads();
        if (c + 2 < NC) {
            int s2 = s + 2; if (s2 >= 3) s2 -= 3;
            load_stage(s2, (c + 2) * FBK);
        }

        uint32_t aB = sb + s * FSTAGE;
        uint32_t bB = aB + FMAT;

        #pragma unroll
        for (int kk = 0; kk < 4; kk++) {
            uint32_t af[4][4], bf[4][2];
            #pragma unroll
            for (int mt = 0; mt < 4; mt++) {
                uint32_t off = (uint32_t)((wm*64 + mt*16 + aRow) * FRSB + kk*32 + aColB);
                ldsm_x4(af[mt][0], af[mt][1], af[mt][2], af[mt][3], aB + off);
            }
            #pragma unroll
            for (int np = 0; np < 2; np++) {
                uint32_t off = (uint32_t)((wn*32 + np*16 + bNrow) * FRSB + kk*32 + bKoff);
                ldsm_x4(bf[2*np][0], bf[2*np][1], bf[2*np+1][0], bf[2*np+1][1], bB + off);
            }
            #pragma unroll
            for (int mt = 0; mt < 4; mt++)
                #pragma unroll
                for (int nt = 0; nt < 4; nt++)
                    mma_f16(acc[mt][nt], af[mt], bf[nt]);
        }
        if (++s == 3) s = 0;
    }

    // ---------- smem-staged epilogue ----------
    __syncthreads();   // all warps done reading stage smem before reuse
    const int er = lane >> 2, ec = (lane & 3) * 2;

    if (EPI == 1) {
        // stage fp32 128x128 (row stride 528B)
        #pragma unroll
        for (int mt = 0; mt < 4; mt++) {
            int r = wm*64 + mt*16 + er;
            #pragma unroll
            for (int nt = 0; nt < 4; nt++) {
                int cc = wn*32 + nt*8 + ec;
                float b0 = bias[bn + cc], b1 = bias[bn + cc + 1];
                *(float2*)(smem + (size_t)r*SROWF + cc*4) =
                    make_float2(acc[mt][nt][0] + b0, acc[mt][nt][1] + b1);
                *(float2*)(smem + (size_t)(r+8)*SROWF + cc*4) =
                    make_float2(acc[mt][nt][2] + b0, acc[mt][nt][3] + b1);
            }
        }
        __syncthreads();
        #pragma unroll
        for (int i = 0; i < 16; i++) {
            int idx = tid + i*256;
            int row = idx >> 5, cb = (idx & 31) << 4;   // 32 x 16B chunks per 512B row
            int gr = bm + row;
            if (gr < Mr) {
                float4 v = *(const float4*)(smem + (size_t)row*SROWF + cb);
                size_t off = (size_t)gr * Nc + bn + (cb >> 2);
                float4 rr = *(const float4*)&R[off];
                v.x += rr.x; v.y += rr.y; v.z += rr.z; v.w += rr.w;
                *(float4*)&C[off] = v;
            }
        }
    } else {
        // stage fp16 128x128 (row stride 272B)
        #pragma unroll
        for (int mt = 0; mt < 4; mt++) {
            int r = wm*64 + mt*16 + er;
            #pragma unroll
            for (int nt = 0; nt < 4; nt++) {
                int cc = wn*32 + nt*8 + ec;
                float b0 = bias[bn + cc], b1 = bias[bn + cc + 1];
                float v0 = acc[mt][nt][0] + b0, v1 = acc[mt][nt][1] + b1;
                float v2 = acc[mt][nt][2] + b0, v3 = acc[mt][nt][3] + b1;
                if (EPI == 4) {
                    v0 = gelu_exact(v0); v1 = gelu_exact(v1);
                    v2 = gelu_exact(v2); v3 = gelu_exact(v3);
                }
                *(__half2*)(smem + (size_t)r*SROWH + cc*2)     = __floats2half2_rn(v0, v1);
                *(__half2*)(smem + (size_t)(r+8)*SROWH + cc*2) = __floats2half2_rn(v2, v3);
            }
        }
        __syncthreads();
        #pragma unroll
        for (int i = 0; i < 8; i++) {
            int idx = tid + i*256;
            int row = idx >> 4, cb = (idx & 15) << 4;   // 16 x 16B chunks per 256B row
            int gr = bm + row;
            if (gr < Mr)
                *(uint4*)&Ch[(size_t)gr * Nc + bn + (cb >> 1)] =
                    *(const uint4*)(smem + (size_t)row*SROWH + cb);
        }
    }
}

// ---------------- LayerNorm -> fp16 -------------------------------------------
__global__ void ln_f16_kernel(const float* __restrict__ X,
                              const float* __restrict__ gam,
                              const float* __restrict__ bet,
                              __half* __restrict__ Y)
{
    int row = blockIdx.x;
    const float* x = X + (size_t)row * D;
    int tid = threadIdx.x;

    float s = 0.f, ss = 0.f;
    for (int i = tid; i < D; i += 256) { float v = x[i]; s += v; ss += v*v; }
    __shared__ float rs[32], rss[32];
    for (int o = 16; o > 0; o >>= 1) {
        s  += __shfl_xor_sync(0xffffffffu, s,  o);
        ss += __shfl_xor_sync(0xffffffffu, ss, o);
    }
    int wid = tid >> 5, lid = tid & 31;
    if (lid == 0) { rs[wid] = s; rss[wid] = ss; }
    __syncthreads();
    __shared__ float s_mean, s_inv;
    if (tid == 0) {
        float ts = 0.f, tss = 0.f;
        for (int w = 0; w < 8; w++) { ts += rs[w]; tss += rss[w]; }
        float mean = ts * (1.f/D);
        float var  = tss * (1.f/D) - mean*mean;
        s_mean = mean; s_inv = rsqrtf(var + LN_EPS);
    }
    __syncthreads();
    float mean = s_mean, inv = s_inv;
    for (int i = tid; i < D; i += 256)
        Y[(size_t)row*D + i] = __float2half((x[i] - mean) * inv * gam[i] + bet[i]);
}

// ---------------- weight transpose -> fp16 -------------------------------------
__global__ void tf16_kernel(const float* __restrict__ W,
                            __half* __restrict__ T, int K, int N)
{
    __shared__ float t[32][33];
    int n0 = blockIdx.x * 32, k0 = blockIdx.y * 32;
    int tx = threadIdx.x, ty = threadIdx.y;
    for (int i = ty; i < 32; i += 8)
        t[i][tx] = W[(size_t)(k0 + i) * N + n0 + tx];
    __syncthreads();
    for (int r = ty; r < 32; r += 8)
        T[(size_t)(n0 + r) * K + k0 + tx] = __float2half(t[tx][r]);
}

// ---------------- cls attention: split-K phase 1 -------------------------------
__global__ void attn_cls_p1(const __half* __restrict__ qkv,
                            float* __restrict__ P)
{
    int bx = blockIdx.x;
    int bh = bx / NSPL, sl = bx % NSPL;
    int b = bh / H, hh = bh % H;
    int tid = threadIdx.x;
    int j0 = sl * SPAN;
    int j1 = min(NT, j0 + SPAN);

    __shared__ float qs[HD];
    __shared__ float sim[SPAN];
    __shared__ float red[256];
    __shared__ float red2[4][HD];

    if (tid < HD)
        qs[tid] = __half2float(qkv[(size_t)(b*NT) * D3 + hh*HD + tid]) * QSCALE;
    __syncthreads();

    float lmx = -1e30f;
    for (int j = j0 + tid; j < j1; j += 256) {
        const __half* kp = qkv + (size_t)(b*NT + j) * D3 + D + hh*HD;
        float kv[64];
        load64h(kp, kv);
        float s = 0.f;
        #pragma unroll
        for (int d = 0; d < HD; d++) s += qs[d] * kv[d];
        sim[j - j0] = s;
        lmx = fmaxf(lmx, s);
    }
    red[tid] = lmx; __syncthreads();
    for (int st = 128; st > 0; st >>= 1) {
        if (tid < st) red[tid] = fmaxf(red[tid], red[tid+st]);
        __syncthreads();
    }
    float mx = red[0];
    __syncthreads();

    float ls = 0.f;
    for (int j = j0 + tid; j < j1; j += 256) {
        float e = __expf(sim[j - j0] - mx);
        sim[j - j0] = e;
        ls += e;
    }
    red[tid] = ls; __syncthreads();
    for (int st = 128; st > 0; st >>= 1) {
        if (tid < st) red[tid] += red[tid+st];
        __syncthreads();
    }
    float lsum = red[0];
    __syncthreads();

    int d = tid & 63, p = tid >> 6;
    float acc = 0.f;
    for (int j = j0 + p; j < j1; j += 4)
        acc += sim[j - j0] * __half2float(qkv[(size_t)(b*NT + j) * D3 + 2*D + hh*HD + d]);
    red2[p][d] = acc;
    __syncthreads();
    if (p == 0) {
        float o = red2[0][d] + red2[1][d] + red2[2][d] + red2[3][d];
        float* dst = P + (size_t)(bh*NSPL + sl) * 66;
        dst[d] = o;
        if (d == 0) { dst[64] = mx; dst[65] = lsum; }
    }
}

// ---------------- cls attention: merge phase ----------------------------------
__global__ void attn_cls_p2(const float* __restrict__ P,
                            __half* __restrict__ O)
{
    int bh = blockIdx.x;
    int b = bh / H, hh = bh % H;
    int d = threadIdx.x;   // 64 threads

    const float* base = P + (size_t)bh * NSPL * 66;
    float mg = -1e30f;
    #pragma unroll
    for (int sl = 0; sl < NSPL; sl++) mg = fmaxf(mg, base[sl*66 + 64]);
    float lg = 0.f, og = 0.f;
    #pragma unroll
    for (int sl = 0; sl < NSPL; sl++) {
        float w = __expf(base[sl*66 + 64] - mg);
        lg += base[sl*66 + 65] * w;
        og += base[sl*66 + d] * w;
    }
    O[(size_t)(b*NT) * D + hh*HD + d] = __float2half(og / lg);
}

// ---------------- time attention -----------------------------------------------
__global__ void attn_time_kernel(const __half* __restrict__ qkv,
                                 __half* __restrict__ O)
{
    int qid = blockIdx.x * blockDim.x + threadIdx.x;
    int fr = qid % F;
    int sp = (qid / F) % NS;
    int bh = qid / (F * NS);
    int b = bh / H, hh = bh % H;
    int t = 1 + fr*NS + sp;

    float q[64];
    load64h(qkv + (size_t)(b*NT + t) * D3 + hh*HD, q);
    #pragma unroll
    for (int i = 0; i < 64; i++) q[i] *= QSCALE;

    float sim[F+1];
    #pragma unroll
    for (int j = 0; j < F+1; j++) {
        int tk = (j == 0) ? 0 : (1 + (j-1)*NS + sp);
        float kv[64];
        load64h(qkv + (size_t)(b*NT + tk) * D3 + D + hh*HD, kv);
        float s = 0.f;
        #pragma unroll
        for (int i = 0; i < 64; i++) s += q[i] * kv[i];
        sim[j] = s;
    }
    float mx = sim[0];
    #pragma unroll
    for (int j = 1; j < F+1; j++) mx = fmaxf(mx, sim[j]);
    float l = 0.f;
    #pragma unroll
    for (int j = 0; j < F+1; j++) { sim[j] = __expf(sim[j] - mx); l += sim[j]; }
    float inv = 1.f / l;

    float o[64];
    #pragma unroll
    for (int i = 0; i < 64; i++) o[i] = 0.f;
    #pragma unroll
    for (int j = 0; j < F+1; j++) {
        int tk = (j == 0) ? 0 : (1 + (j-1)*NS + sp);
        float vv[64];
        load64h(qkv + (size_t)(b*NT + tk) * D3 + 2*D + hh*HD, vv);
        float p = sim[j] * inv;
        #pragma unroll
        for (int i = 0; i < 64; i++) o[i] += p * vv[i];
    }
    __half2* op = (__half2*)(O + (size_t)(b*NT + t) * D + hh*HD);
    #pragma unroll
    for (int i = 0; i < 32; i++)
        op[i] = __floats2half2_rn(o[2*i], o[2*i+1]);
}

// ---------------- space attention -----------------------------------------------
__global__ void attn_space_kernel(const __half* __restrict__ qkv,
                                  __half* __restrict__ O)
{
    int bx = blockIdx.x;
    int bh = bx / F, fr = bx % F;
    int b = bh / H, hh = bh % H;
    int tid = threadIdx.x;
    int sp = tid;
    const int NK = NS + 1;

    __shared__ float Ks[64 * HD];
    __shared__ float Vs[64 * HD];

    float q[64], o[64];
    float m = -1e30f, l = 0.f;
    if (sp < NS) {
        load64h(qkv + (size_t)(b*NT + 1 + fr*NS + sp) * D3 + hh*HD, q);
        #pragma unroll
        for (int i = 0; i < 64; i++) { q[i] *= QSCALE; o[i] = 0.f; }
    }

    for (int t0 = 0; t0 < NK; t0 += 64) {
        __syncthreads();
        for (int e = tid; e < 64*32; e += 256) {
            int jj = e >> 5, d2 = e & 31;
            int j = t0 + jj;
            float2 kf = make_float2(0.f, 0.f), vf = kf;
            if (j < NK) {
                int tk = (j == 0) ? 0 : (1 + fr*NS + (j-1));
                const __half2* base = (const __half2*)(qkv + (size_t)(b*NT + tk) * D3 + hh*HD);
                kf = __half22float2(base[(D   >> 1) + d2]);
                vf = __half22float2(base[(2*D >> 1) + d2]);
            }
            Ks[jj*HD + 2*d2] = kf.x; Ks[jj*HD + 2*d2 + 1] = kf.y;
            Vs[jj*HD + 2*d2] = vf.x; Vs[jj*HD + 2*d2 + 1] = vf.y;
        }
        __syncthreads();

        if (sp < NS) {
            int lim = min(64, NK - t0);
            for (int g = 0; g < lim; g += 8) {
                int gl = min(8, lim - g);
                float sg[8];
                float gm = -1e30f;
                for (int j = 0; j < gl; j++) {
                    const float4* kr = (const float4*)&Ks[(g + j) * HD];
                    float s = 0.f;
                    #pragma unroll
                    for (int i = 0; i < 16; i++) {
                        float4 kk = kr[i];
                        s += q[4*i]*kk.x + q[4*i+1]*kk.y + q[4*i+2]*kk.z + q[4*i+3]*kk.w;
                    }
                    sg[j] = s;
                    gm = fmaxf(gm, s);
                }
                float mn = fmaxf(m, gm);
                float fac = __expf(m - mn);
                l *= fac;
                #pragma unroll
                for (int i = 0; i < 64; i++) o[i] *= fac;
                m = mn;
                for (int j = 0; j < gl; j++) {
                    float p = __expf(sg[j] - m);
                    l += p;
                    const float4* vr = (const float4*)&Vs[(g + j) * HD];
                    #pragma unroll
                    for (int i = 0; i < 16; i++) {
                        float4 vv = vr[i];
                        o[4*i]   = fmaf(p, vv.x, o[4*i]);
                        o[4*i+1] = fmaf(p, vv.y, o[4*i+1]);
                        o[4*i+2] = fmaf(p, vv.z, o[4*i+2]);
                        o[4*i+3] = fmaf(p, vv.w, o[4*i+3]);
                    }
                }
            }
        }
    }

    if (sp < NS) {
        float inv = 1.f / l;
        __half2* op = (__half2*)(O + (size_t)(b*NT + 1 + fr*NS + sp) * D + hh*HD);
        #pragma unroll
        for (int i = 0; i < 32; i++)
            op[i] = __floats2half2_rn(o[2*i]*inv, o[2*i+1]*inv);
    }
}

// ---------------- host launch ------------------------------------------------
extern "C" void kernel_launch(void* const* d_in, const int* in_sizes, int n_in,
                              void* d_out, int out_size)
{
    const float* x      = (const float*)d_in[0];
    const float* n1g    = (const float*)d_in[1];
    const float* n1b    = (const float*)d_in[2];
    const float* n2g    = (const float*)d_in[3];
    const float* n2b    = (const float*)d_in[4];
    const float* n3g    = (const float*)d_in[5];
    const float* n3b    = (const float*)d_in[6];
    const float* aqkvw  = (const float*)d_in[7];
    const float* aqkvb  = (const float*)d_in[8];
    const float* aprojw = (const float*)d_in[9];
    const float* aprojb = (const float*)d_in[10];
    const float* tqkvw  = (const float*)d_in[11];
    const float* tqkvb  = (const float*)d_in[12];
    const float* tprojw = (const float*)d_in[13];
    const float* tprojb = (const float*)d_in[14];
    const float* fc1w   = (const float*)d_in[15];
    const float* fc1b   = (const float*)d_in[16];
    const float* fc2w   = (const float*)d_in[17];
    const float* fc2b   = (const float*)d_in[18];
    float* out = (float*)d_out;

    __half *lnf, *attf, *hidf, *qkvh;
    __half *wf_tqkv, *wf_aqkv, *wf_tproj, *wf_aproj, *wf_fc1, *wf_fc2;
    float *btres, *bsres, *clsp;
    cudaGetSymbolAddress((void**)&lnf,  g_lnf);
    cudaGetSymbolAddress((void**)&attf, g_attf);
    cudaGetSymbolAddress((void**)&hidf, g_hidf);
    cudaGetSymbolAddress((void**)&qkvh, g_qkvh);
    cudaGetSymbolAddress((void**)&btres,g_tres);
    cudaGetSymbolAddress((void**)&bsres,g_sres);
    cudaGetSymbolAddress((void**)&clsp, g_clsp);
    cudaGetSymbolAddress((void**)&wf_tqkv, g_wf_tqkv);
    cudaGetSymbolAddress((void**)&wf_aqkv, g_wf_aqkv);
    cudaGetSymbolAddress((void**)&wf_tproj,g_wf_tproj);
    cudaGetSymbolAddress((void**)&wf_aproj,g_wf_aproj);
    cudaGetSymbolAddress((void**)&wf_fc1,  g_wf_fc1);
    cudaGetSymbolAddress((void**)&wf_fc2,  g_wf_fc2);

    cudaFuncSetAttribute(gemm_f16<1>, cudaFuncAttributeMaxDynamicSharedMemorySize, SMEM_F16);
    cudaFuncSetAttribute(gemm_f16<4>, cudaFuncAttributeMaxDynamicSharedMemorySize, SMEM_F16);
    cudaFuncSetAttribute(gemm_f16<5>, cudaFuncAttributeMaxDynamicSharedMemorySize, SMEM_F16);

    const int MT = (M + BM - 1) / BM;    // 99
    dim3 tb(32, 8);
    const int nTimeBlocks = (B*H*NS*F) / 256;   // 588

    tf16_kernel<<<dim3(D3/32, D/32), tb>>>(tqkvw, wf_tqkv, D, D3);
    tf16_kernel<<<dim3(D3/32, D/32), tb>>>(aqkvw, wf_aqkv, D, D3);
    tf16_kernel<<<dim3(D/32,  D/32), tb>>>(tprojw, wf_tproj, D, D);
    tf16_kernel<<<dim3(D/32,  D/32), tb>>>(aprojw, wf_aproj, D, D);
    ln_f16_kernel<<<M, 256>>>(x, n3g, n3b, lnf);
    gemm_f16<5><<<dim3(D3/BN, MT), 256, SMEM_F16>>>(lnf, wf_tqkv, tqkvb, nullptr, nullptr, qkvh, M, D, D3);
    attn_cls_p1<<<B*H*NSPL, 256>>>(qkvh, clsp);
    attn_cls_p2<<<B*H, 64>>>(clsp, attf);
    attn_time_kernel<<<nTimeBlocks, 256>>>(qkvh, attf);
    gemm_f16<1><<<dim3(D/BN, MT), 256, SMEM_F16>>>(attf, wf_tproj, tprojb, x, btres, nullptr, M, D, D);

    // ---- space attention branch ----
    ln_f16_kernel<<<M, 256>>>(btres, n1g, n1b, lnf);
    gemm_f16<5><<<dim3(D3/BN, MT), 256, SMEM_F16>>>(lnf, wf_aqkv, aqkvb, nullptr, nullptr, qkvh, M, D, D3);
    attn_cls_p1<<<B*H*NSPL, 256>>>(qkvh, clsp);
    attn_cls_p2<<<B*H, 64>>>(clsp, attf);
    attn_space_kernel<<<B*H*F, 256>>>(qkvh, attf);
    gemm_f16<1><<<dim3(D/BN, MT), 256, SMEM_F16>>>(attf, wf_aproj, aprojb, x, bsres, nullptr, M, D, D);

    // ---- MLP ----
    tf16_kernel<<<dim3(D4/32, D/32), tb>>>(fc1w, wf_fc1, D, D4);
    tf16_kernel<<<dim3(D/32, D4/32), tb>>>(fc2w, wf_fc2, D4, D);
    ln_f16_kernel<<<M, 256>>>(bsres, n2g, n2b, lnf);
    gemm_f16<4><<<dim3(D4/BN, MT), 256, SMEM_F16>>>(lnf, wf_fc1, fc1b, nullptr, nullptr, hidf, M, D, D4);
    gemm_f16<1><<<dim3(D/BN, MT), 256, SMEM_F16>>>(hidf, wf_fc2, fc2b, bsres, out, nullptr, M, D4, D);
}